// round 2
// baseline (speedup 1.0000x reference)
#include <cuda_runtime.h>
#include <cuda_bf16.h>
#include <math.h>
#include <stdint.h>

#define B_    4
#define SEQ_  1024
#define DIM_  1024
#define HEADS_ 16
#define HD_   64
#define VOCAB_ 32000
#define FF_   4096

#define ROWS_ (B_*SEQ_)           // 4096
#define ACT_ELEMS ((size_t)ROWS_*DIM_)   // 4M floats

// ------------------------- scratch (device globals) -------------------------
__device__ float g_X   [ACT_ELEMS];   // x_embed
__device__ float g_XENR[ACT_ELEMS];
__device__ float g_S0  [ACT_ELEMS];
__device__ float g_S1  [ACT_ELEMS];
__device__ float g_H0  [ACT_ELEMS];
__device__ float g_H1  [ACT_ELEMS];
__device__ float g_Q   [ACT_ELEMS];
__device__ float g_K   [ACT_ELEMS];
__device__ float g_V   [ACT_ELEMS];
__device__ float g_AT  [ACT_ELEMS];
__device__ float g_T   [ACT_ELEMS];
__device__ float g_G   [ACT_ELEMS];   // h1 inside hrm layer
__device__ float g_FF  [(size_t)ROWS_*FF_];
__device__ float g_MEAN[B_*DIM_];

// ------------------------------ GEMM (NT) ------------------------------
// C[M,N] = A[M,K] @ B[N,K]^T   (torch Linear: y = x @ W.T)
// BM=BN=128, BK=8, 256 threads, 8x8 micro-tile.
// FUSE: 0 = none, 1 = tanh-GELU
__device__ __forceinline__ float gelu_tanh(float x) {
    float x3 = x * x * x;
    return 0.5f * x * (1.0f + tanhf(0.79788456080286535588f * (x + 0.044715f * x3)));
}

template<int FUSE>
__global__ __launch_bounds__(256)
void gemm_nt(const float* __restrict__ A, const float* __restrict__ Bm,
             float* __restrict__ C, int M, int N, int K)
{
    __shared__ float As[8][128];
    __shared__ float Bs[8][128];

    const int bm = blockIdx.y * 128;
    const int bn = blockIdx.x * 128;
    const int tid = threadIdx.x;
    const int arow = tid >> 1;            // 0..127
    const int ac4  = (tid & 1) * 4;       // 0 or 4
    const int ty = tid >> 4;              // 0..15
    const int tx = tid & 15;              // 0..15

    const float* Aptr = A  + (size_t)(bm + arow) * K + ac4;
    const float* Bptr = Bm + (size_t)(bn + arow) * K + ac4;

    float acc[8][8];
#pragma unroll
    for (int i = 0; i < 8; i++)
#pragma unroll
        for (int j = 0; j < 8; j++) acc[i][j] = 0.0f;

    for (int k0 = 0; k0 < K; k0 += 8) {
        float4 av = *(const float4*)(Aptr + k0);
        float4 bv = *(const float4*)(Bptr + k0);
        __syncthreads();
        As[ac4 + 0][arow] = av.x; As[ac4 + 1][arow] = av.y;
        As[ac4 + 2][arow] = av.z; As[ac4 + 3][arow] = av.w;
        Bs[ac4 + 0][arow] = bv.x; Bs[ac4 + 1][arow] = bv.y;
        Bs[ac4 + 2][arow] = bv.z; Bs[ac4 + 3][arow] = bv.w;
        __syncthreads();
#pragma unroll
        for (int kk = 0; kk < 8; kk++) {
            float4 a0 = *(const float4*)&As[kk][ty * 8];
            float4 a1 = *(const float4*)&As[kk][ty * 8 + 4];
            float4 b0 = *(const float4*)&Bs[kk][tx * 8];
            float4 b1 = *(const float4*)&Bs[kk][tx * 8 + 4];
            float ar[8] = {a0.x, a0.y, a0.z, a0.w, a1.x, a1.y, a1.z, a1.w};
            float br[8] = {b0.x, b0.y, b0.z, b0.w, b1.x, b1.y, b1.z, b1.w};
#pragma unroll
            for (int i = 0; i < 8; i++)
#pragma unroll
                for (int j = 0; j < 8; j++) acc[i][j] = fmaf(ar[i], br[j], acc[i][j]);
        }
    }

#pragma unroll
    for (int i = 0; i < 8; i++) {
        float* crow = C + (size_t)(bm + ty * 8 + i) * N + bn + tx * 8;
        float v[8];
#pragma unroll
        for (int j = 0; j < 8; j++) {
            v[j] = acc[i][j];
            if (FUSE == 1) v[j] = gelu_tanh(v[j]);
        }
        *(float4*)(crow)     = make_float4(v[0], v[1], v[2], v[3]);
        *(float4*)(crow + 4) = make_float4(v[4], v[5], v[6], v[7]);
    }
}

// ------------------------------ attention ------------------------------
// Q,K,V layout: [B, S, H, HD]  (= [B,S,DIM] with heads interleaved)
// grid: (SEQ/64, B*HEADS), 256 threads, dynamic smem.
// causal: mask j > i. gate != nullptr: multiply output by (1 - sigmoid(gate[h])).
#define ATTN_SMEM_FLOATS (64*65*3 + 64*64 + 64*3)
__global__ __launch_bounds__(256)
void attn_kernel(const float* __restrict__ Q, const float* __restrict__ K,
                 const float* __restrict__ V, float* __restrict__ O,
                 const float* __restrict__ gate, int causal)
{
    extern __shared__ float sm[];
    float* Qs   = sm;                 // [64][65]
    float* Ks   = Qs + 64 * 65;       // [64][65]
    float* Ss   = Ks + 64 * 65;       // [64][65]
    float* Vs   = Ss + 64 * 65;       // [64][64]
    float* mrow = Vs + 64 * 64;       // [64]
    float* lrow = mrow + 64;          // [64]
    float* arow = lrow + 64;          // [64]

    const int bh = blockIdx.y;
    const int b  = bh / HEADS_;
    const int h  = bh % HEADS_;
    const int q0 = blockIdx.x * 64;
    const int tid = threadIdx.x;

    const float* Qbase = Q + ((size_t)(b * SEQ_ + q0) * HEADS_ + h) * HD_;

    for (int i = tid; i < 1024; i += 256) {       // 64x64 tile as float4s
        int r = i >> 4, c4 = (i & 15) << 2;
        float4 v = *(const float4*)(Qbase + (size_t)r * DIM_ + c4);
        Qs[r * 65 + c4 + 0] = v.x; Qs[r * 65 + c4 + 1] = v.y;
        Qs[r * 65 + c4 + 2] = v.z; Qs[r * 65 + c4 + 3] = v.w;
    }
    if (tid < 64) { mrow[tid] = -3.0e38f; lrow[tid] = 0.0f; }

    const int ty = tid >> 4, tx = tid & 15;
    float acc[4][4];
#pragma unroll
    for (int i = 0; i < 4; i++)
#pragma unroll
        for (int j = 0; j < 4; j++) acc[i][j] = 0.0f;

    const int nkb = causal ? (q0 / 64 + 1) : (SEQ_ / 64);

    for (int kb = 0; kb < nkb; kb++) {
        const int k0 = kb * 64;
        __syncthreads();
        const float* Kbase = K + ((size_t)(b * SEQ_ + k0) * HEADS_ + h) * HD_;
        const float* Vbase = V + ((size_t)(b * SEQ_ + k0) * HEADS_ + h) * HD_;
        for (int i = tid; i < 1024; i += 256) {
            int r = i >> 4, c4 = (i & 15) << 2;
            float4 kv = *(const float4*)(Kbase + (size_t)r * DIM_ + c4);
            Ks[r * 65 + c4 + 0] = kv.x; Ks[r * 65 + c4 + 1] = kv.y;
            Ks[r * 65 + c4 + 2] = kv.z; Ks[r * 65 + c4 + 3] = kv.w;
            float4 vv = *(const float4*)(Vbase + (size_t)r * DIM_ + c4);
            *(float4*)&Vs[r * 64 + c4] = vv;
        }
        __syncthreads();

        // scores: 4x4 per thread
        float s[4][4];
#pragma unroll
        for (int i = 0; i < 4; i++)
#pragma unroll
            for (int j = 0; j < 4; j++) s[i][j] = 0.0f;
#pragma unroll 8
        for (int d = 0; d < 64; d++) {
            float a0 = Qs[(ty * 4 + 0) * 65 + d];
            float a1 = Qs[(ty * 4 + 1) * 65 + d];
            float a2 = Qs[(ty * 4 + 2) * 65 + d];
            float a3 = Qs[(ty * 4 + 3) * 65 + d];
            float b0 = Ks[(tx * 4 + 0) * 65 + d];
            float b1 = Ks[(tx * 4 + 1) * 65 + d];
            float b2 = Ks[(tx * 4 + 2) * 65 + d];
            float b3 = Ks[(tx * 4 + 3) * 65 + d];
            s[0][0] = fmaf(a0, b0, s[0][0]); s[0][1] = fmaf(a0, b1, s[0][1]);
            s[0][2] = fmaf(a0, b2, s[0][2]); s[0][3] = fmaf(a0, b3, s[0][3]);
            s[1][0] = fmaf(a1, b0, s[1][0]); s[1][1] = fmaf(a1, b1, s[1][1]);
            s[1][2] = fmaf(a1, b2, s[1][2]); s[1][3] = fmaf(a1, b3, s[1][3]);
            s[2][0] = fmaf(a2, b0, s[2][0]); s[2][1] = fmaf(a2, b1, s[2][1]);
            s[2][2] = fmaf(a2, b2, s[2][2]); s[2][3] = fmaf(a2, b3, s[2][3]);
            s[3][0] = fmaf(a3, b0, s[3][0]); s[3][1] = fmaf(a3, b1, s[3][1]);
            s[3][2] = fmaf(a3, b2, s[3][2]); s[3][3] = fmaf(a3, b3, s[3][3]);
        }
#pragma unroll
        for (int i = 0; i < 4; i++)
#pragma unroll
            for (int j = 0; j < 4; j++) {
                float val = s[i][j] * 0.125f;   // 1/sqrt(64)
                if (causal && (k0 + tx * 4 + j > q0 + ty * 4 + i)) val = -3.0e38f;
                Ss[(ty * 4 + i) * 65 + tx * 4 + j] = val;
            }
        __syncthreads();

        // online softmax: 4 threads per row
        {
            int row = tid >> 2, q = tid & 3;
            float mx = -3.0e38f;
            for (int c = q; c < 64; c += 4) mx = fmaxf(mx, Ss[row * 65 + c]);
            mx = fmaxf(mx, __shfl_xor_sync(0xffffffffu, mx, 1));
            mx = fmaxf(mx, __shfl_xor_sync(0xffffffffu, mx, 2));
            float mold = mrow[row];
            float mnew = fmaxf(mold, mx);
            float al = __expf(mold - mnew);
            float ls = 0.0f;
            for (int c = q; c < 64; c += 4) {
                float p = __expf(Ss[row * 65 + c] - mnew);
                Ss[row * 65 + c] = p;
                ls += p;
            }
            ls += __shfl_xor_sync(0xffffffffu, ls, 1);
            ls += __shfl_xor_sync(0xffffffffu, ls, 2);
            if (q == 0) {
                mrow[row] = mnew;
                lrow[row] = lrow[row] * al + ls;
                arow[row] = al;
            }
        }
        __syncthreads();

        // O = O*alpha + P @ V   (rows ty*4+i, cols tx*4+j)
        float alv[4];
#pragma unroll
        for (int i = 0; i < 4; i++) alv[i] = arow[ty * 4 + i];
#pragma unroll
        for (int i = 0; i < 4; i++)
#pragma unroll
            for (int j = 0; j < 4; j++) acc[i][j] *= alv[i];
#pragma unroll 8
        for (int jj = 0; jj < 64; jj++) {
            float p0 = Ss[(ty * 4 + 0) * 65 + jj];
            float p1 = Ss[(ty * 4 + 1) * 65 + jj];
            float p2 = Ss[(ty * 4 + 2) * 65 + jj];
            float p3 = Ss[(ty * 4 + 3) * 65 + jj];
            float v0 = Vs[jj * 64 + tx * 4 + 0];
            float v1 = Vs[jj * 64 + tx * 4 + 1];
            float v2 = Vs[jj * 64 + tx * 4 + 2];
            float v3 = Vs[jj * 64 + tx * 4 + 3];
            acc[0][0] = fmaf(p0, v0, acc[0][0]); acc[0][1] = fmaf(p0, v1, acc[0][1]);
            acc[0][2] = fmaf(p0, v2, acc[0][2]); acc[0][3] = fmaf(p0, v3, acc[0][3]);
            acc[1][0] = fmaf(p1, v0, acc[1][0]); acc[1][1] = fmaf(p1, v1, acc[1][1]);
            acc[1][2] = fmaf(p1, v2, acc[1][2]); acc[1][3] = fmaf(p1, v3, acc[1][3]);
            acc[2][0] = fmaf(p2, v0, acc[2][0]); acc[2][1] = fmaf(p2, v1, acc[2][1]);
            acc[2][2] = fmaf(p2, v2, acc[2][2]); acc[2][3] = fmaf(p2, v3, acc[2][3]);
            acc[3][0] = fmaf(p3, v0, acc[3][0]); acc[3][1] = fmaf(p3, v1, acc[3][1]);
            acc[3][2] = fmaf(p3, v2, acc[3][2]); acc[3][3] = fmaf(p3, v3, acc[3][3]);
        }
    }
    __syncthreads();

    float gmul = 1.0f;
    if (gate != nullptr) gmul = 1.0f - 1.0f / (1.0f + __expf(-gate[h]));

#pragma unroll
    for (int i = 0; i < 4; i++) {
        int rg = q0 + ty * 4 + i;
        float inv = gmul / lrow[ty * 4 + i];
        float* op = O + ((size_t)(b * SEQ_ + rg) * HEADS_ + h) * HD_ + tx * 4;
        *(float4*)op = make_float4(acc[i][0] * inv, acc[i][1] * inv,
                                   acc[i][2] * inv, acc[i][3] * inv);
    }
}

// ------------------------------ elementwise ------------------------------
__global__ void embed_kernel(const int* __restrict__ x, const float* __restrict__ emb,
                             float* __restrict__ out)
{
    int i = blockIdx.x * blockDim.x + threadIdx.x;      // over 1M float4
    if (i >= (int)(ACT_ELEMS / 4)) return;
    int row = i >> 8;                                    // DIM/4 = 256
    int c4  = i & 255;
    int tok = x[row];
    ((float4*)out)[i] = ((const float4*)(emb + (size_t)tok * DIM_))[c4];
}

// broadcast init0 -> S0, init1 -> S1 over batch (per-batch copy of [SEQ,DIM])
__global__ void bcast_init_kernel(const float* __restrict__ i0, const float* __restrict__ i1,
                                  float* __restrict__ S0, float* __restrict__ S1)
{
    int i = blockIdx.x * blockDim.x + threadIdx.x;      // over ACT_ELEMS/4
    if (i >= (int)(ACT_ELEMS / 4)) return;
    int src = i & (int)(SEQ_ * DIM_ / 4 - 1);            // wrap within one batch
    ((float4*)S0)[i] = ((const float4*)i0)[src];
    ((float4*)S1)[i] = ((const float4*)i1)[src];
}

__global__ void add3_kernel(const float* __restrict__ a, const float* __restrict__ b,
                            const float* __restrict__ c, float* __restrict__ o)
{
    int i = blockIdx.x * blockDim.x + threadIdx.x;
    if (i >= (int)(ACT_ELEMS / 4)) return;
    float4 va = ((const float4*)a)[i];
    float4 vb = ((const float4*)b)[i];
    float4 vc = ((const float4*)c)[i];
    ((float4*)o)[i] = make_float4(va.x + vb.x + vc.x, va.y + vb.y + vc.y,
                                  va.z + vb.z + vc.z, va.w + vb.w + vc.w);
}

// out = rmsnorm(a + b), row-wise over DIM=1024. 1 block (256 thr) per row.
__global__ __launch_bounds__(256)
void rmsnorm_add_kernel(const float* __restrict__ a, const float* __restrict__ b,
                        float* __restrict__ o)
{
    int row = blockIdx.x;
    int tid = threadIdx.x;
    const float4* a4 = (const float4*)(a + (size_t)row * DIM_);
    const float4* b4 = (const float4*)(b + (size_t)row * DIM_);
    float4 va = a4[tid], vb = b4[tid];
    float4 s = make_float4(va.x + vb.x, va.y + vb.y, va.z + vb.z, va.w + vb.w);
    float ss = s.x * s.x + s.y * s.y + s.z * s.z + s.w * s.w;
#pragma unroll
    for (int off = 16; off > 0; off >>= 1) ss += __shfl_xor_sync(0xffffffffu, ss, off);
    __shared__ float red[8];
    __shared__ float scale_s;
    if ((tid & 31) == 0) red[tid >> 5] = ss;
    __syncthreads();
    if (tid == 0) {
        float t = 0.0f;
#pragma unroll
        for (int w = 0; w < 8; w++) t += red[w];
        scale_s = rsqrtf(t * (1.0f / DIM_) + 1e-6f);
    }
    __syncthreads();
    float sc = scale_s;
    ((float4*)(o + (size_t)row * DIM_))[tid] =
        make_float4(s.x * sc, s.y * sc, s.z * sc, s.w * sc);
}

__global__ void mean_kernel(const float* __restrict__ S, float* __restrict__ M)
{
    int idx = blockIdx.x * blockDim.x + threadIdx.x;     // 4096 = B*DIM
    if (idx >= B_ * DIM_) return;
    int b = idx >> 10, d = idx & (DIM_ - 1);
    const float* p = S + (size_t)b * SEQ_ * DIM_ + d;
    float s = 0.0f;
    for (int t = 0; t < SEQ_; t++) s += p[(size_t)t * DIM_];
    M[idx] = s * (1.0f / SEQ_);
}

__global__ void qhead_kernel(const float* __restrict__ M, const float* __restrict__ W,
                             float* __restrict__ out)
{
    int w = threadIdx.x >> 5, lane = threadIdx.x & 31;   // 8 warps = B*2 outputs
    int b = w >> 1, o = w & 1;
    const float* m  = M + (size_t)b * DIM_;
    const float* ww = W + (size_t)o * DIM_;
    float s = 0.0f;
    for (int k = lane; k < DIM_; k += 32) s += m[k] * ww[k];
#pragma unroll
    for (int off = 16; off > 0; off >>= 1) s += __shfl_xor_sync(0xffffffffu, s, off);
    if (lane == 0) out[b * 2 + o] = 1.0f / (1.0f + __expf(-s));
}

// ------------------------------ host orchestration ------------------------------
static void launch_gemm(const float* A, const float* B, float* C,
                        int M, int N, int K, int fuse_gelu)
{
    dim3 grid(N / 128, M / 128);
    if (fuse_gelu) gemm_nt<1><<<grid, 256>>>(A, B, C, M, N, K);
    else           gemm_nt<0><<<grid, 256>>>(A, B, C, M, N, K);
}

struct LayerP { const float *wq, *wk, *wv, *wo, *w1, *w2; };

static void run_hrm_layer(float* H, const LayerP& p, float* OUT,
                          float* Q, float* Kb, float* V, float* AT,
                          float* T, float* G, float* FF)
{
    launch_gemm(H, p.wq, Q,  ROWS_, DIM_, DIM_, 0);
    launch_gemm(H, p.wk, Kb, ROWS_, DIM_, DIM_, 0);
    launch_gemm(H, p.wv, V,  ROWS_, DIM_, DIM_, 0);
    attn_kernel<<<dim3(SEQ_ / 64, B_ * HEADS_), 256, ATTN_SMEM_FLOATS * 4>>>(
        Q, Kb, V, AT, nullptr, 0);
    launch_gemm(AT, p.wo, T, ROWS_, DIM_, DIM_, 0);
    rmsnorm_add_kernel<<<ROWS_, 256>>>(H, T, G);
    launch_gemm(G, p.w1, FF, ROWS_, FF_, DIM_, 1);     // fused GELU
    launch_gemm(FF, p.w2, T, ROWS_, DIM_, FF_, 0);
    rmsnorm_add_kernel<<<ROWS_, 256>>>(G, T, OUT);
}

extern "C" void kernel_launch(void* const* d_in, const int* in_sizes, int n_in,
                              void* d_out, int out_size)
{
    (void)in_sizes; (void)n_in; (void)out_size;
    // input order: x, emb, a_wq, a_wk, a_wv, a_wo, gate, init0, init1,
    // l0_wq,l0_wk,l0_wv,l0_wo,l0_w1,l0_w2, l1_wq,l1_wk,l1_wv,l1_wo,l1_w1,l1_w2,
    // w_out, w_qhead
    const int*   x     = (const int*)  d_in[0];
    const float* emb   = (const float*)d_in[1];
    const float* a_wq  = (const float*)d_in[2];
    const float* a_wk  = (const float*)d_in[3];
    const float* a_wv  = (const float*)d_in[4];
    const float* a_wo  = (const float*)d_in[5];
    const float* gate  = (const float*)d_in[6];
    const float* init0 = (const float*)d_in[7];
    const float* init1 = (const float*)d_in[8];
    LayerP lp[2];
    lp[0] = { (const float*)d_in[9],  (const float*)d_in[10], (const float*)d_in[11],
              (const float*)d_in[12], (const float*)d_in[13], (const float*)d_in[14] };
    lp[1] = { (const float*)d_in[15], (const float*)d_in[16], (const float*)d_in[17],
              (const float*)d_in[18], (const float*)d_in[19], (const float*)d_in[20] };
    const float* w_out   = (const float*)d_in[21];
    const float* w_qhead = (const float*)d_in[22];
    float* out = (float*)d_out;

    // device-symbol pointers (host-side lookups; safe during graph capture)
    float *X, *XENR, *S0, *S1, *H0, *H1, *Q, *Kb, *V, *AT, *T, *G, *FF, *MEAN;
    cudaGetSymbolAddress((void**)&X,    g_X);
    cudaGetSymbolAddress((void**)&XENR, g_XENR);
    cudaGetSymbolAddress((void**)&S0,   g_S0);
    cudaGetSymbolAddress((void**)&S1,   g_S1);
    cudaGetSymbolAddress((void**)&H0,   g_H0);
    cudaGetSymbolAddress((void**)&H1,   g_H1);
    cudaGetSymbolAddress((void**)&Q,    g_Q);
    cudaGetSymbolAddress((void**)&Kb,   g_K);
    cudaGetSymbolAddress((void**)&V,    g_V);
    cudaGetSymbolAddress((void**)&AT,   g_AT);
    cudaGetSymbolAddress((void**)&T,    g_T);
    cudaGetSymbolAddress((void**)&G,    g_G);
    cudaGetSymbolAddress((void**)&FF,   g_FF);
    cudaGetSymbolAddress((void**)&MEAN, g_MEAN);

    cudaFuncSetAttribute(attn_kernel, cudaFuncAttributeMaxDynamicSharedMemorySize,
                         ATTN_SMEM_FLOATS * 4);

    const int v4blocks = (int)(ACT_ELEMS / 4 + 255) / 256;

    // 1) embedding
    embed_kernel<<<v4blocks, 256>>>(x, emb, X);

    // 2) infini attention (memory==0 => combined = (1-sigmoid(gate))*local)
    launch_gemm(X, a_wq, Q,  ROWS_, DIM_, DIM_, 0);
    launch_gemm(X, a_wk, Kb, ROWS_, DIM_, DIM_, 0);
    launch_gemm(X, a_wv, V,  ROWS_, DIM_, DIM_, 0);
    attn_kernel<<<dim3(SEQ_ / 64, B_ * HEADS_), 256, ATTN_SMEM_FLOATS * 4>>>(
        Q, Kb, V, AT, gate, 1);
    launch_gemm(AT, a_wo, XENR, ROWS_, DIM_, DIM_, 0);

    // 3) init states: broadcast init over batch (single kernel, no memcpy nodes)
    bcast_init_kernel<<<v4blocks, 256>>>(init0, init1, S0, S1);

    // 4) HRM steps: layer0 every step; layer1 at steps 3 and 7.
    for (int step = 0; step < 8; step++) {
        bool u1 = ((step + 1) % 4 == 0);
        add3_kernel<<<v4blocks, 256>>>(S0, XENR, S1, H0);
        if (u1) add3_kernel<<<v4blocks, 256>>>(S1, XENR, S0, H1);
        run_hrm_layer(H0, lp[0], S0, Q, Kb, V, AT, T, G, FF);
        if (u1) run_hrm_layer(H1, lp[1], S1, Q, Kb, V, AT, T, G, FF);
    }

    // 5) outputs: y_hat = S1 @ w_out^T ; q = sigmoid(mean(S1) @ w_qhead^T)
    launch_gemm(S1, w_out, out, ROWS_, VOCAB_, DIM_, 0);
    mean_kernel<<<(B_ * DIM_ + 255) / 256, 256>>>(S1, MEAN);
    qhead_kernel<<<1, 256>>>(MEAN, w_qhead, out + (size_t)ROWS_ * VOCAB_);
}

// round 3
// speedup vs baseline: 1.0887x; 1.0887x over previous
#include <cuda_runtime.h>
#include <cuda_bf16.h>
#include <math.h>
#include <stdint.h>

#define B_    4
#define SEQ_  1024
#define DIM_  1024
#define HEADS_ 16
#define HD_   64
#define VOCAB_ 32000
#define FF_   4096

#define ROWS_ (B_*SEQ_)           // 4096
#define ACT_ELEMS ((size_t)ROWS_*DIM_)   // 4M floats

// ------------------------- scratch (device globals) -------------------------
__device__ float g_X   [ACT_ELEMS];
__device__ float g_XENR[ACT_ELEMS];
__device__ float g_S0  [ACT_ELEMS];
__device__ float g_S1  [ACT_ELEMS];
__device__ float g_H0  [ACT_ELEMS];
__device__ float g_H1  [ACT_ELEMS];
__device__ float g_Q   [ACT_ELEMS];
__device__ float g_K   [ACT_ELEMS];
__device__ float g_V   [ACT_ELEMS];
__device__ float g_AT  [ACT_ELEMS];
__device__ float g_T   [ACT_ELEMS];
__device__ float g_G   [ACT_ELEMS];
__device__ float g_FF  [(size_t)ROWS_*FF_];
__device__ float g_MEAN[B_*DIM_];

__device__ __forceinline__ float gelu_tanh(float x) {
    float x3 = x * x * x;
    return 0.5f * x * (1.0f + tanhf(0.79788456080286535588f * (x + 0.044715f * x3)));
}

__device__ __forceinline__ uint32_t f32_to_tf32(float x) {
    uint32_t r;
    asm("cvt.rna.tf32.f32 %0, %1;" : "=r"(r) : "f"(x));
    return r;
}

__device__ __forceinline__ void mma_tf32(float c[4], const uint32_t a[4], const uint32_t b[2]) {
    asm volatile(
        "mma.sync.aligned.m16n8k8.row.col.f32.tf32.tf32.f32 "
        "{%0,%1,%2,%3}, {%4,%5,%6,%7}, {%8,%9}, {%0,%1,%2,%3};"
        : "+f"(c[0]), "+f"(c[1]), "+f"(c[2]), "+f"(c[3])
        : "r"(a[0]), "r"(a[1]), "r"(a[2]), "r"(a[3]), "r"(b[0]), "r"(b[1]));
}

// ------------------------------ TF32 GEMM (NT) ------------------------------
// C[M,N] = A[M,K] @ B[N,K]^T, 3xTF32 for ~fp32 accuracy.
// Block tile 128x128, K-chunk 16, 256 threads (8 warps, 64x32 warp tiles).
// FUSE: 0 = none, 1 = tanh-GELU.
#define SMS 136   // smem row stride (conflict-free fragment loads)

template<int FUSE>
__global__ __launch_bounds__(256)
void gemm_tf32(const float* __restrict__ A, const float* __restrict__ Bm,
               float* __restrict__ C, int M, int N, int K)
{
    __shared__ uint32_t As_hi[16][SMS], As_lo[16][SMS];
    __shared__ uint32_t Bs_hi[16][SMS], Bs_lo[16][SMS];

    const int bm = blockIdx.y * 128;
    const int bn = blockIdx.x * 128;
    const int tid = threadIdx.x;

    // staging assignment: row = tid>>1 (0..127), half = tid&1 (k-offset 0 or 8)
    const int srow = tid >> 1;
    const int shalf = (tid & 1) * 8;
    const float* Aptr = A  + (size_t)(bm + srow) * K + shalf;
    const float* Bptr = Bm + (size_t)(bn + srow) * K + shalf;

    // warp/lane decomposition: 2 warps in M (64 each), 4 warps in N (32 each)
    const int wid = tid >> 5, lane = tid & 31;
    const int warp_m = (wid & 1) * 64;
    const int warp_n = (wid >> 1) * 32;
    const int g = lane >> 2, t = lane & 3;

    float acc[4][4][4];
#pragma unroll
    for (int i = 0; i < 4; i++)
#pragma unroll
        for (int j = 0; j < 4; j++)
#pragma unroll
            for (int r = 0; r < 4; r++) acc[i][j][r] = 0.0f;

    const int nchunks = K >> 4;

    // prologue: prefetch chunk 0
    float4 av0 = *(const float4*)(Aptr + 0);
    float4 av1 = *(const float4*)(Aptr + 4);
    float4 bv0 = *(const float4*)(Bptr + 0);
    float4 bv1 = *(const float4*)(Bptr + 4);

    for (int kc = 0; kc < nchunks; kc++) {
        __syncthreads();
        // split + store staged regs
        float afv[8] = {av0.x, av0.y, av0.z, av0.w, av1.x, av1.y, av1.z, av1.w};
        float bfv[8] = {bv0.x, bv0.y, bv0.z, bv0.w, bv1.x, bv1.y, bv1.z, bv1.w};
#pragma unroll
        for (int j = 0; j < 8; j++) {
            uint32_t ah = f32_to_tf32(afv[j]);
            As_hi[shalf + j][srow] = ah;
            As_lo[shalf + j][srow] = f32_to_tf32(afv[j] - __uint_as_float(ah));
            uint32_t bh = f32_to_tf32(bfv[j]);
            Bs_hi[shalf + j][srow] = bh;
            Bs_lo[shalf + j][srow] = f32_to_tf32(bfv[j] - __uint_as_float(bh));
        }
        __syncthreads();

        // prefetch next chunk while computing
        if (kc + 1 < nchunks) {
            const float* An = Aptr + (kc + 1) * 16;
            const float* Bn = Bptr + (kc + 1) * 16;
            av0 = *(const float4*)(An + 0);
            av1 = *(const float4*)(An + 4);
            bv0 = *(const float4*)(Bn + 0);
            bv1 = *(const float4*)(Bn + 4);
        }

#pragma unroll
        for (int ks = 0; ks < 2; ks++) {
            const int kb = ks * 8;
            uint32_t a_hi[4][4], a_lo[4][4], b_hi[4][2], b_lo[4][2];
#pragma unroll
            for (int fm = 0; fm < 4; fm++) {
                int m = warp_m + fm * 16;
                a_hi[fm][0] = As_hi[kb + t][m + g];
                a_hi[fm][1] = As_hi[kb + t][m + g + 8];
                a_hi[fm][2] = As_hi[kb + t + 4][m + g];
                a_hi[fm][3] = As_hi[kb + t + 4][m + g + 8];
                a_lo[fm][0] = As_lo[kb + t][m + g];
                a_lo[fm][1] = As_lo[kb + t][m + g + 8];
                a_lo[fm][2] = As_lo[kb + t + 4][m + g];
                a_lo[fm][3] = As_lo[kb + t + 4][m + g + 8];
            }
#pragma unroll
            for (int fn = 0; fn < 4; fn++) {
                int n = warp_n + fn * 8;
                b_hi[fn][0] = Bs_hi[kb + t][n + g];
                b_hi[fn][1] = Bs_hi[kb + t + 4][n + g];
                b_lo[fn][0] = Bs_lo[kb + t][n + g];
                b_lo[fn][1] = Bs_lo[kb + t + 4][n + g];
            }
#pragma unroll
            for (int fm = 0; fm < 4; fm++)
#pragma unroll
                for (int fn = 0; fn < 4; fn++) {
                    mma_tf32(acc[fm][fn], a_hi[fm], b_lo[fn]);
                    mma_tf32(acc[fm][fn], a_lo[fm], b_hi[fn]);
                    mma_tf32(acc[fm][fn], a_hi[fm], b_hi[fn]);
                }
        }
    }

    // epilogue: c0(row g, col 2t), c1(g, 2t+1), c2(g+8, 2t), c3(g+8, 2t+1)
#pragma unroll
    for (int fm = 0; fm < 4; fm++) {
#pragma unroll
        for (int fn = 0; fn < 4; fn++) {
            int row0 = bm + warp_m + fm * 16 + g;
            int col  = bn + warp_n + fn * 8 + 2 * t;
            float v0 = acc[fm][fn][0], v1 = acc[fm][fn][1];
            float v2 = acc[fm][fn][2], v3 = acc[fm][fn][3];
            if (FUSE == 1) {
                v0 = gelu_tanh(v0); v1 = gelu_tanh(v1);
                v2 = gelu_tanh(v2); v3 = gelu_tanh(v3);
            }
            *(float2*)(C + (size_t)row0 * N + col)       = make_float2(v0, v1);
            *(float2*)(C + (size_t)(row0 + 8) * N + col) = make_float2(v2, v3);
        }
    }
}

// ------------------------------ attention ------------------------------
#define ATTN_SMEM_FLOATS (64*65*3 + 64*64 + 64*3)
__global__ __launch_bounds__(256)
void attn_kernel(const float* __restrict__ Q, const float* __restrict__ K,
                 const float* __restrict__ V, float* __restrict__ O,
                 const float* __restrict__ gate, int causal)
{
    extern __shared__ float sm[];
    float* Qs   = sm;
    float* Ks   = Qs + 64 * 65;
    float* Ss   = Ks + 64 * 65;
    float* Vs   = Ss + 64 * 65;
    float* mrow = Vs + 64 * 64;
    float* lrow = mrow + 64;
    float* arow = lrow + 64;

    const int bh = blockIdx.y;
    const int b  = bh / HEADS_;
    const int h  = bh % HEADS_;
    const int q0 = blockIdx.x * 64;
    const int tid = threadIdx.x;

    const float* Qbase = Q + ((size_t)(b * SEQ_ + q0) * HEADS_ + h) * HD_;

    for (int i = tid; i < 1024; i += 256) {
        int r = i >> 4, c4 = (i & 15) << 2;
        float4 v = *(const float4*)(Qbase + (size_t)r * DIM_ + c4);
        Qs[r * 65 + c4 + 0] = v.x; Qs[r * 65 + c4 + 1] = v.y;
        Qs[r * 65 + c4 + 2] = v.z; Qs[r * 65 + c4 + 3] = v.w;
    }
    if (tid < 64) { mrow[tid] = -3.0e38f; lrow[tid] = 0.0f; }

    const int ty = tid >> 4, tx = tid & 15;
    float acc[4][4];
#pragma unroll
    for (int i = 0; i < 4; i++)
#pragma unroll
        for (int j = 0; j < 4; j++) acc[i][j] = 0.0f;

    const int nkb = causal ? (q0 / 64 + 1) : (SEQ_ / 64);

    for (int kb = 0; kb < nkb; kb++) {
        const int k0 = kb * 64;
        __syncthreads();
        const float* Kbase = K + ((size_t)(b * SEQ_ + k0) * HEADS_ + h) * HD_;
        const float* Vbase = V + ((size_t)(b * SEQ_ + k0) * HEADS_ + h) * HD_;
        for (int i = tid; i < 1024; i += 256) {
            int r = i >> 4, c4 = (i & 15) << 2;
            float4 kv = *(const float4*)(Kbase + (size_t)r * DIM_ + c4);
            Ks[r * 65 + c4 + 0] = kv.x; Ks[r * 65 + c4 + 1] = kv.y;
            Ks[r * 65 + c4 + 2] = kv.z; Ks[r * 65 + c4 + 3] = kv.w;
            float4 vv = *(const float4*)(Vbase + (size_t)r * DIM_ + c4);
            *(float4*)&Vs[r * 64 + c4] = vv;
        }
        __syncthreads();

        float s[4][4];
#pragma unroll
        for (int i = 0; i < 4; i++)
#pragma unroll
            for (int j = 0; j < 4; j++) s[i][j] = 0.0f;
#pragma unroll 8
        for (int d = 0; d < 64; d++) {
            float a0 = Qs[(ty * 4 + 0) * 65 + d];
            float a1 = Qs[(ty * 4 + 1) * 65 + d];
            float a2 = Qs[(ty * 4 + 2) * 65 + d];
            float a3 = Qs[(ty * 4 + 3) * 65 + d];
            float b0 = Ks[(tx * 4 + 0) * 65 + d];
            float b1 = Ks[(tx * 4 + 1) * 65 + d];
            float b2 = Ks[(tx * 4 + 2) * 65 + d];
            float b3 = Ks[(tx * 4 + 3) * 65 + d];
            s[0][0] = fmaf(a0, b0, s[0][0]); s[0][1] = fmaf(a0, b1, s[0][1]);
            s[0][2] = fmaf(a0, b2, s[0][2]); s[0][3] = fmaf(a0, b3, s[0][3]);
            s[1][0] = fmaf(a1, b0, s[1][0]); s[1][1] = fmaf(a1, b1, s[1][1]);
            s[1][2] = fmaf(a1, b2, s[1][2]); s[1][3] = fmaf(a1, b3, s[1][3]);
            s[2][0] = fmaf(a2, b0, s[2][0]); s[2][1] = fmaf(a2, b1, s[2][1]);
            s[2][2] = fmaf(a2, b2, s[2][2]); s[2][3] = fmaf(a2, b3, s[2][3]);
            s[3][0] = fmaf(a3, b0, s[3][0]); s[3][1] = fmaf(a3, b1, s[3][1]);
            s[3][2] = fmaf(a3, b2, s[3][2]); s[3][3] = fmaf(a3, b3, s[3][3]);
        }
#pragma unroll
        for (int i = 0; i < 4; i++)
#pragma unroll
            for (int j = 0; j < 4; j++) {
                float val = s[i][j] * 0.125f;
                if (causal && (k0 + tx * 4 + j > q0 + ty * 4 + i)) val = -3.0e38f;
                Ss[(ty * 4 + i) * 65 + tx * 4 + j] = val;
            }
        __syncthreads();

        {
            int row = tid >> 2, q = tid & 3;
            float mx = -3.0e38f;
            for (int c = q; c < 64; c += 4) mx = fmaxf(mx, Ss[row * 65 + c]);
            mx = fmaxf(mx, __shfl_xor_sync(0xffffffffu, mx, 1));
            mx = fmaxf(mx, __shfl_xor_sync(0xffffffffu, mx, 2));
            float mold = mrow[row];
            float mnew = fmaxf(mold, mx);
            float al = __expf(mold - mnew);
            float ls = 0.0f;
            for (int c = q; c < 64; c += 4) {
                float p = __expf(Ss[row * 65 + c] - mnew);
                Ss[row * 65 + c] = p;
                ls += p;
            }
            ls += __shfl_xor_sync(0xffffffffu, ls, 1);
            ls += __shfl_xor_sync(0xffffffffu, ls, 2);
            if (q == 0) {
                mrow[row] = mnew;
                lrow[row] = lrow[row] * al + ls;
                arow[row] = al;
            }
        }
        __syncthreads();

        float alv[4];
#pragma unroll
        for (int i = 0; i < 4; i++) alv[i] = arow[ty * 4 + i];
#pragma unroll
        for (int i = 0; i < 4; i++)
#pragma unroll
            for (int j = 0; j < 4; j++) acc[i][j] *= alv[i];
#pragma unroll 8
        for (int jj = 0; jj < 64; jj++) {
            float p0 = Ss[(ty * 4 + 0) * 65 + jj];
            float p1 = Ss[(ty * 4 + 1) * 65 + jj];
            float p2 = Ss[(ty * 4 + 2) * 65 + jj];
            float p3 = Ss[(ty * 4 + 3) * 65 + jj];
            float v0 = Vs[jj * 64 + tx * 4 + 0];
            float v1 = Vs[jj * 64 + tx * 4 + 1];
            float v2 = Vs[jj * 64 + tx * 4 + 2];
            float v3 = Vs[jj * 64 + tx * 4 + 3];
            acc[0][0] = fmaf(p0, v0, acc[0][0]); acc[0][1] = fmaf(p0, v1, acc[0][1]);
            acc[0][2] = fmaf(p0, v2, acc[0][2]); acc[0][3] = fmaf(p0, v3, acc[0][3]);
            acc[1][0] = fmaf(p1, v0, acc[1][0]); acc[1][1] = fmaf(p1, v1, acc[1][1]);
            acc[1][2] = fmaf(p1, v2, acc[1][2]); acc[1][3] = fmaf(p1, v3, acc[1][3]);
            acc[2][0] = fmaf(p2, v0, acc[2][0]); acc[2][1] = fmaf(p2, v1, acc[2][1]);
            acc[2][2] = fmaf(p2, v2, acc[2][2]); acc[2][3] = fmaf(p2, v3, acc[2][3]);
            acc[3][0] = fmaf(p3, v0, acc[3][0]); acc[3][1] = fmaf(p3, v1, acc[3][1]);
            acc[3][2] = fmaf(p3, v2, acc[3][2]); acc[3][3] = fmaf(p3, v3, acc[3][3]);
        }
    }
    __syncthreads();

    float gmul = 1.0f;
    if (gate != nullptr) gmul = 1.0f - 1.0f / (1.0f + __expf(-gate[h]));

#pragma unroll
    for (int i = 0; i < 4; i++) {
        int rg = q0 + ty * 4 + i;
        float inv = gmul / lrow[ty * 4 + i];
        float* op = O + ((size_t)(b * SEQ_ + rg) * HEADS_ + h) * HD_ + tx * 4;
        *(float4*)op = make_float4(acc[i][0] * inv, acc[i][1] * inv,
                                   acc[i][2] * inv, acc[i][3] * inv);
    }
}

// ------------------------------ elementwise ------------------------------
__global__ void embed_kernel(const int* __restrict__ x, const float* __restrict__ emb,
                             float* __restrict__ out)
{
    int i = blockIdx.x * blockDim.x + threadIdx.x;
    if (i >= (int)(ACT_ELEMS / 4)) return;
    int row = i >> 8;
    int c4  = i & 255;
    int tok = x[row];
    ((float4*)out)[i] = ((const float4*)(emb + (size_t)tok * DIM_))[c4];
}

__global__ void bcast_init_kernel(const float* __restrict__ i0, const float* __restrict__ i1,
                                  float* __restrict__ S0, float* __restrict__ S1)
{
    int i = blockIdx.x * blockDim.x + threadIdx.x;
    if (i >= (int)(ACT_ELEMS / 4)) return;
    int src = i & (int)(SEQ_ * DIM_ / 4 - 1);
    ((float4*)S0)[i] = ((const float4*)i0)[src];
    ((float4*)S1)[i] = ((const float4*)i1)[src];
}

__global__ void add3_kernel(const float* __restrict__ a, const float* __restrict__ b,
                            const float* __restrict__ c, float* __restrict__ o)
{
    int i = blockIdx.x * blockDim.x + threadIdx.x;
    if (i >= (int)(ACT_ELEMS / 4)) return;
    float4 va = ((const float4*)a)[i];
    float4 vb = ((const float4*)b)[i];
    float4 vc = ((const float4*)c)[i];
    ((float4*)o)[i] = make_float4(va.x + vb.x + vc.x, va.y + vb.y + vc.y,
                                  va.z + vb.z + vc.z, va.w + vb.w + vc.w);
}

__global__ __launch_bounds__(256)
void rmsnorm_add_kernel(const float* __restrict__ a, const float* __restrict__ b,
                        float* __restrict__ o)
{
    int row = blockIdx.x;
    int tid = threadIdx.x;
    const float4* a4 = (const float4*)(a + (size_t)row * DIM_);
    const float4* b4 = (const float4*)(b + (size_t)row * DIM_);
    float4 va = a4[tid], vb = b4[tid];
    float4 s = make_float4(va.x + vb.x, va.y + vb.y, va.z + vb.z, va.w + vb.w);
    float ss = s.x * s.x + s.y * s.y + s.z * s.z + s.w * s.w;
#pragma unroll
    for (int off = 16; off > 0; off >>= 1) ss += __shfl_xor_sync(0xffffffffu, ss, off);
    __shared__ float red[8];
    __shared__ float scale_s;
    if ((tid & 31) == 0) red[tid >> 5] = ss;
    __syncthreads();
    if (tid == 0) {
        float t = 0.0f;
#pragma unroll
        for (int w = 0; w < 8; w++) t += red[w];
        scale_s = rsqrtf(t * (1.0f / DIM_) + 1e-6f);
    }
    __syncthreads();
    float sc = scale_s;
    ((float4*)(o + (size_t)row * DIM_))[tid] =
        make_float4(s.x * sc, s.y * sc, s.z * sc, s.w * sc);
}

__global__ void mean_kernel(const float* __restrict__ S, float* __restrict__ M)
{
    int idx = blockIdx.x * blockDim.x + threadIdx.x;
    if (idx >= B_ * DIM_) return;
    int b = idx >> 10, d = idx & (DIM_ - 1);
    const float* p = S + (size_t)b * SEQ_ * DIM_ + d;
    float s = 0.0f;
    for (int t = 0; t < SEQ_; t++) s += p[(size_t)t * DIM_];
    M[idx] = s * (1.0f / SEQ_);
}

__global__ void qhead_kernel(const float* __restrict__ M, const float* __restrict__ W,
                             float* __restrict__ out)
{
    int w = threadIdx.x >> 5, lane = threadIdx.x & 31;
    int b = w >> 1, o = w & 1;
    const float* m  = M + (size_t)b * DIM_;
    const float* ww = W + (size_t)o * DIM_;
    float s = 0.0f;
    for (int k = lane; k < DIM_; k += 32) s += m[k] * ww[k];
#pragma unroll
    for (int off = 16; off > 0; off >>= 1) s += __shfl_xor_sync(0xffffffffu, s, off);
    if (lane == 0) out[b * 2 + o] = 1.0f / (1.0f + __expf(-s));
}

// ------------------------------ host orchestration ------------------------------
static void launch_gemm(const float* A, const float* B, float* C,
                        int M, int N, int K, int fuse_gelu)
{
    dim3 grid(N / 128, M / 128);
    if (fuse_gelu) gemm_tf32<1><<<grid, 256>>>(A, B, C, M, N, K);
    else           gemm_tf32<0><<<grid, 256>>>(A, B, C, M, N, K);
}

struct LayerP { const float *wq, *wk, *wv, *wo, *w1, *w2; };

static void run_hrm_layer(float* H, const LayerP& p, float* OUT,
                          float* Q, float* Kb, float* V, float* AT,
                          float* T, float* G, float* FF)
{
    launch_gemm(H, p.wq, Q,  ROWS_, DIM_, DIM_, 0);
    launch_gemm(H, p.wk, Kb, ROWS_, DIM_, DIM_, 0);
    launch_gemm(H, p.wv, V,  ROWS_, DIM_, DIM_, 0);
    attn_kernel<<<dim3(SEQ_ / 64, B_ * HEADS_), 256, ATTN_SMEM_FLOATS * 4>>>(
        Q, Kb, V, AT, nullptr, 0);
    launch_gemm(AT, p.wo, T, ROWS_, DIM_, DIM_, 0);
    rmsnorm_add_kernel<<<ROWS_, 256>>>(H, T, G);
    launch_gemm(G, p.w1, FF, ROWS_, FF_, DIM_, 1);
    launch_gemm(FF, p.w2, T, ROWS_, DIM_, FF_, 0);
    rmsnorm_add_kernel<<<ROWS_, 256>>>(G, T, OUT);
}

extern "C" void kernel_launch(void* const* d_in, const int* in_sizes, int n_in,
                              void* d_out, int out_size)
{
    (void)in_sizes; (void)n_in; (void)out_size;
    const int*   x     = (const int*)  d_in[0];
    const float* emb   = (const float*)d_in[1];
    const float* a_wq  = (const float*)d_in[2];
    const float* a_wk  = (const float*)d_in[3];
    const float* a_wv  = (const float*)d_in[4];
    const float* a_wo  = (const float*)d_in[5];
    const float* gate  = (const float*)d_in[6];
    const float* init0 = (const float*)d_in[7];
    const float* init1 = (const float*)d_in[8];
    LayerP lp[2];
    lp[0] = { (const float*)d_in[9],  (const float*)d_in[10], (const float*)d_in[11],
              (const float*)d_in[12], (const float*)d_in[13], (const float*)d_in[14] };
    lp[1] = { (const float*)d_in[15], (const float*)d_in[16], (const float*)d_in[17],
              (const float*)d_in[18], (const float*)d_in[19], (const float*)d_in[20] };
    const float* w_out   = (const float*)d_in[21];
    const float* w_qhead = (const float*)d_in[22];
    float* out = (float*)d_out;

    float *X, *XENR, *S0, *S1, *H0, *H1, *Q, *Kb, *V, *AT, *T, *G, *FF, *MEAN;
    cudaGetSymbolAddress((void**)&X,    g_X);
    cudaGetSymbolAddress((void**)&XENR, g_XENR);
    cudaGetSymbolAddress((void**)&S0,   g_S0);
    cudaGetSymbolAddress((void**)&S1,   g_S1);
    cudaGetSymbolAddress((void**)&H0,   g_H0);
    cudaGetSymbolAddress((void**)&H1,   g_H1);
    cudaGetSymbolAddress((void**)&Q,    g_Q);
    cudaGetSymbolAddress((void**)&Kb,   g_K);
    cudaGetSymbolAddress((void**)&V,    g_V);
    cudaGetSymbolAddress((void**)&AT,   g_AT);
    cudaGetSymbolAddress((void**)&T,    g_T);
    cudaGetSymbolAddress((void**)&G,    g_G);
    cudaGetSymbolAddress((void**)&FF,   g_FF);
    cudaGetSymbolAddress((void**)&MEAN, g_MEAN);

    cudaFuncSetAttribute(attn_kernel, cudaFuncAttributeMaxDynamicSharedMemorySize,
                         ATTN_SMEM_FLOATS * 4);

    const int v4blocks = (int)(ACT_ELEMS / 4 + 255) / 256;

    embed_kernel<<<v4blocks, 256>>>(x, emb, X);

    launch_gemm(X, a_wq, Q,  ROWS_, DIM_, DIM_, 0);
    launch_gemm(X, a_wk, Kb, ROWS_, DIM_, DIM_, 0);
    launch_gemm(X, a_wv, V,  ROWS_, DIM_, DIM_, 0);
    attn_kernel<<<dim3(SEQ_ / 64, B_ * HEADS_), 256, ATTN_SMEM_FLOATS * 4>>>(
        Q, Kb, V, AT, gate, 1);
    launch_gemm(AT, a_wo, XENR, ROWS_, DIM_, DIM_, 0);

    bcast_init_kernel<<<v4blocks, 256>>>(init0, init1, S0, S1);

    for (int step = 0; step < 8; step++) {
        bool u1 = ((step + 1) % 4 == 0);
        add3_kernel<<<v4blocks, 256>>>(S0, XENR, S1, H0);
        if (u1) add3_kernel<<<v4blocks, 256>>>(S1, XENR, S0, H1);
        run_hrm_layer(H0, lp[0], S0, Q, Kb, V, AT, T, G, FF);
        if (u1) run_hrm_layer(H1, lp[1], S1, Q, Kb, V, AT, T, G, FF);
    }

    launch_gemm(S1, w_out, out, ROWS_, VOCAB_, DIM_, 0);
    mean_kernel<<<(B_ * DIM_ + 255) / 256, 256>>>(S1, MEAN);
    qhead_kernel<<<1, 256>>>(MEAN, w_qhead, out + (size_t)ROWS_ * VOCAB_);
}

// round 5
// speedup vs baseline: 1.5112x; 1.3881x over previous
#include <cuda_runtime.h>
#include <cuda_bf16.h>
#include <math.h>
#include <stdint.h>

#define B_    4
#define SEQ_  1024
#define DIM_  1024
#define HEADS_ 16
#define HD_   64
#define VOCAB_ 32000
#define FF_   4096

#define ROWS_ (B_*SEQ_)           // 4096
#define ACT_ELEMS ((size_t)ROWS_*DIM_)   // 4M floats

// ------------------------- scratch (device globals) -------------------------
__device__ float g_X   [ACT_ELEMS];
__device__ float g_XENR[ACT_ELEMS];
__device__ float g_S0  [ACT_ELEMS];
__device__ float g_S1  [ACT_ELEMS];
__device__ float g_H0  [ACT_ELEMS];
__device__ float g_H1  [ACT_ELEMS];
__device__ float g_Q   [ACT_ELEMS];
__device__ float g_K   [ACT_ELEMS];
__device__ float g_V   [ACT_ELEMS];
__device__ float g_AT  [ACT_ELEMS];
__device__ float g_T   [ACT_ELEMS];
__device__ float g_G   [ACT_ELEMS];
__device__ float g_FF  [(size_t)ROWS_*FF_];
__device__ float g_MEAN[B_*DIM_];

__device__ __forceinline__ float gelu_tanh(float x) {
    float x3 = x * x * x;
    return 0.5f * x * (1.0f + tanhf(0.79788456080286535588f * (x + 0.044715f * x3)));
}

__device__ __forceinline__ uint32_t pack_bf16(__nv_bfloat16 lo, __nv_bfloat16 hi) {
    __nv_bfloat162 p;
    p.x = lo; p.y = hi;
    return *reinterpret_cast<uint32_t*>(&p);
}

__device__ __forceinline__ void mma_bf16(float c[4], const uint32_t a[4], const uint32_t b[2]) {
    asm volatile(
        "mma.sync.aligned.m16n8k16.row.col.f32.bf16.bf16.f32 "
        "{%0,%1,%2,%3}, {%4,%5,%6,%7}, {%8,%9}, {%0,%1,%2,%3};"
        : "+f"(c[0]), "+f"(c[1]), "+f"(c[2]), "+f"(c[3])
        : "r"(a[0]), "r"(a[1]), "r"(a[2]), "r"(a[3]), "r"(b[0]), "r"(b[1]));
}

// ------------------------------ bf16-split GEMM (NT) ------------------------------
// C[M,N] = A[M,K] @ B[N,K]^T, split x = hi(bf16)+lo(bf16); acc += hi*lo + lo*hi + hi*hi.
// Block tile 128x128, K-chunk 16, 256 threads (8 warps, 64x32 warp tiles).
// Double-buffered smem, one __syncthreads per chunk.
// smem layout: packed bf16x2 pairs along K: X_hi[buf][k2][row], k2 = k/2 (0..7).
#define SMS 136   // row stride (conflict-free fragment LDS)

template<int FUSE>
__global__ __launch_bounds__(256)
void gemm_bf16s(const float* __restrict__ A, const float* __restrict__ Bm,
                float* __restrict__ C, int M, int N, int K)
{
    __shared__ uint32_t SA_hi[2][8][SMS], SA_lo[2][8][SMS];
    __shared__ uint32_t SB_hi[2][8][SMS], SB_lo[2][8][SMS];

    const int bm = blockIdx.y * 128;
    const int bn = blockIdx.x * 128;
    const int tid = threadIdx.x;

    // staging: row = tid>>1 (0..127), k-offset 0 or 8 via tid&1
    const int srow = tid >> 1;
    const int shalf = (tid & 1) * 8;
    const int k2base = (tid & 1) * 4;
    const int jrot = (tid & 1) * 2;              // STS bank stagger
    const float* Aptr = A  + (size_t)(bm + srow) * K + shalf;
    const float* Bptr = Bm + (size_t)(bn + srow) * K + shalf;

    const int wid = tid >> 5, lane = tid & 31;
    const int warp_m = (wid & 1) * 64;
    const int warp_n = (wid >> 1) * 32;
    const int g = lane >> 2, t = lane & 3;

    float acc[4][4][4];
#pragma unroll
    for (int i = 0; i < 4; i++)
#pragma unroll
        for (int j = 0; j < 4; j++)
#pragma unroll
            for (int r = 0; r < 4; r++) acc[i][j][r] = 0.0f;

    const int nchunks = K >> 4;

    float4 av0 = *(const float4*)(Aptr + 0);
    float4 av1 = *(const float4*)(Aptr + 4);
    float4 bv0 = *(const float4*)(Bptr + 0);
    float4 bv1 = *(const float4*)(Bptr + 4);

    // stage chunk 0 into buffer 0
    {
        float afv[8] = {av0.x, av0.y, av0.z, av0.w, av1.x, av1.y, av1.z, av1.w};
        float bfv[8] = {bv0.x, bv0.y, bv0.z, bv0.w, bv1.x, bv1.y, bv1.z, bv1.w};
#pragma unroll
        for (int jj = 0; jj < 4; jj++) {
            int j = (jj + jrot) & 3;
            float e0 = afv[2*j], e1 = afv[2*j+1];
            __nv_bfloat16 h0 = __float2bfloat16_rn(e0), h1 = __float2bfloat16_rn(e1);
            SA_hi[0][k2base + j][srow] = pack_bf16(h0, h1);
            SA_lo[0][k2base + j][srow] =
                pack_bf16(__float2bfloat16_rn(e0 - __bfloat162float(h0)),
                          __float2bfloat16_rn(e1 - __bfloat162float(h1)));
            float f0 = bfv[2*j], f1 = bfv[2*j+1];
            __nv_bfloat16 g0 = __float2bfloat16_rn(f0), g1 = __float2bfloat16_rn(f1);
            SB_hi[0][k2base + j][srow] = pack_bf16(g0, g1);
            SB_lo[0][k2base + j][srow] =
                pack_bf16(__float2bfloat16_rn(f0 - __bfloat162float(g0)),
                          __float2bfloat16_rn(f1 - __bfloat162float(g1)));
        }
    }

    for (int kc = 0; kc < nchunks; kc++) {
        __syncthreads();

        if (kc + 1 < nchunks) {
            const float* An = Aptr + (kc + 1) * 16;
            const float* Bn = Bptr + (kc + 1) * 16;
            av0 = *(const float4*)(An + 0);
            av1 = *(const float4*)(An + 4);
            bv0 = *(const float4*)(Bn + 0);
            bv1 = *(const float4*)(Bn + 4);
        }

        const int buf = kc & 1;
        uint32_t a_hi[4][4], a_lo[4][4], b_hi[4][2], b_lo[4][2];
#pragma unroll
        for (int fm = 0; fm < 4; fm++) {
            int m = warp_m + fm * 16;
            a_hi[fm][0] = SA_hi[buf][t][m + g];
            a_hi[fm][1] = SA_hi[buf][t][m + g + 8];
            a_hi[fm][2] = SA_hi[buf][t + 4][m + g];
            a_hi[fm][3] = SA_hi[buf][t + 4][m + g + 8];
            a_lo[fm][0] = SA_lo[buf][t][m + g];
            a_lo[fm][1] = SA_lo[buf][t][m + g + 8];
            a_lo[fm][2] = SA_lo[buf][t + 4][m + g];
            a_lo[fm][3] = SA_lo[buf][t + 4][m + g + 8];
        }
#pragma unroll
        for (int fn = 0; fn < 4; fn++) {
            int n = warp_n + fn * 8;
            b_hi[fn][0] = SB_hi[buf][t][n + g];
            b_hi[fn][1] = SB_hi[buf][t + 4][n + g];
            b_lo[fn][0] = SB_lo[buf][t][n + g];
            b_lo[fn][1] = SB_lo[buf][t + 4][n + g];
        }
#pragma unroll
        for (int fm = 0; fm < 4; fm++)
#pragma unroll
            for (int fn = 0; fn < 4; fn++) {
                mma_bf16(acc[fm][fn], a_hi[fm], b_lo[fn]);
                mma_bf16(acc[fm][fn], a_lo[fm], b_hi[fn]);
                mma_bf16(acc[fm][fn], a_hi[fm], b_hi[fn]);
            }

        // stage next chunk into the other buffer (consumed 2 iterations ago;
        // the barrier at the top of this iteration already fenced its readers)
        if (kc + 1 < nchunks) {
            const int nbuf = buf ^ 1;
            float afv[8] = {av0.x, av0.y, av0.z, av0.w, av1.x, av1.y, av1.z, av1.w};
            float bfv[8] = {bv0.x, bv0.y, bv0.z, bv0.w, bv1.x, bv1.y, bv1.z, bv1.w};
#pragma unroll
            for (int jj = 0; jj < 4; jj++) {
                int j = (jj + jrot) & 3;
                float e0 = afv[2*j], e1 = afv[2*j+1];
                __nv_bfloat16 h0 = __float2bfloat16_rn(e0), h1 = __float2bfloat16_rn(e1);
                SA_hi[nbuf][k2base + j][srow] = pack_bf16(h0, h1);
                SA_lo[nbuf][k2base + j][srow] =
                    pack_bf16(__float2bfloat16_rn(e0 - __bfloat162float(h0)),
                              __float2bfloat16_rn(e1 - __bfloat162float(h1)));
                float f0 = bfv[2*j], f1 = bfv[2*j+1];
                __nv_bfloat16 g0 = __float2bfloat16_rn(f0), g1 = __float2bfloat16_rn(f1);
                SB_hi[nbuf][k2base + j][srow] = pack_bf16(g0, g1);
                SB_lo[nbuf][k2base + j][srow] =
                    pack_bf16(__float2bfloat16_rn(f0 - __bfloat162float(g0)),
                              __float2bfloat16_rn(f1 - __bfloat162float(g1)));
            }
        }
    }

    // epilogue: c0(row g, col 2t), c1(g, 2t+1), c2(g+8, 2t), c3(g+8, 2t+1)
#pragma unroll
    for (int fm = 0; fm < 4; fm++) {
#pragma unroll
        for (int fn = 0; fn < 4; fn++) {
            int row0 = bm + warp_m + fm * 16 + g;
            int col  = bn + warp_n + fn * 8 + 2 * t;
            float v0 = acc[fm][fn][0], v1 = acc[fm][fn][1];
            float v2 = acc[fm][fn][2], v3 = acc[fm][fn][3];
            if (FUSE == 1) {
                v0 = gelu_tanh(v0); v1 = gelu_tanh(v1);
                v2 = gelu_tanh(v2); v3 = gelu_tanh(v3);
            }
            *(float2*)(C + (size_t)row0 * N + col)       = make_float2(v0, v1);
            *(float2*)(C + (size_t)(row0 + 8) * N + col) = make_float2(v2, v3);
        }
    }
}

// ------------------------------ attention ------------------------------
#define ATTN_SMEM_FLOATS (64*65*3 + 64*64 + 64*3)
__global__ __launch_bounds__(256)
void attn_kernel(const float* __restrict__ Q, const float* __restrict__ K,
                 const float* __restrict__ V, float* __restrict__ O,
                 const float* __restrict__ gate, int causal)
{
    extern __shared__ float sm[];
    float* Qs   = sm;
    float* Ks   = Qs + 64 * 65;
    float* Ss   = Ks + 64 * 65;
    float* Vs   = Ss + 64 * 65;
    float* mrow = Vs + 64 * 64;
    float* lrow = mrow + 64;
    float* arow = lrow + 64;

    const int bh = blockIdx.y;
    const int b  = bh / HEADS_;
    const int h  = bh % HEADS_;
    const int q0 = blockIdx.x * 64;
    const int tid = threadIdx.x;

    const float* Qbase = Q + ((size_t)(b * SEQ_ + q0) * HEADS_ + h) * HD_;

    for (int i = tid; i < 1024; i += 256) {
        int r = i >> 4, c4 = (i & 15) << 2;
        float4 v = *(const float4*)(Qbase + (size_t)r * DIM_ + c4);
        Qs[r * 65 + c4 + 0] = v.x; Qs[r * 65 + c4 + 1] = v.y;
        Qs[r * 65 + c4 + 2] = v.z; Qs[r * 65 + c4 + 3] = v.w;
    }
    if (tid < 64) { mrow[tid] = -3.0e38f; lrow[tid] = 0.0f; }

    const int ty = tid >> 4, tx = tid & 15;
    float acc[4][4];
#pragma unroll
    for (int i = 0; i < 4; i++)
#pragma unroll
        for (int j = 0; j < 4; j++) acc[i][j] = 0.0f;

    const int nkb = causal ? (q0 / 64 + 1) : (SEQ_ / 64);

    for (int kb = 0; kb < nkb; kb++) {
        const int k0 = kb * 64;
        __syncthreads();
        const float* Kbase = K + ((size_t)(b * SEQ_ + k0) * HEADS_ + h) * HD_;
        const float* Vbase = V + ((size_t)(b * SEQ_ + k0) * HEADS_ + h) * HD_;
        for (int i = tid; i < 1024; i += 256) {
            int r = i >> 4, c4 = (i & 15) << 2;
            float4 kv = *(const float4*)(Kbase + (size_t)r * DIM_ + c4);
            Ks[r * 65 + c4 + 0] = kv.x; Ks[r * 65 + c4 + 1] = kv.y;
            Ks[r * 65 + c4 + 2] = kv.z; Ks[r * 65 + c4 + 3] = kv.w;
            float4 vv = *(const float4*)(Vbase + (size_t)r * DIM_ + c4);
            *(float4*)&Vs[r * 64 + c4] = vv;
        }
        __syncthreads();

        float s[4][4];
#pragma unroll
        for (int i = 0; i < 4; i++)
#pragma unroll
            for (int j = 0; j < 4; j++) s[i][j] = 0.0f;
#pragma unroll 8
        for (int d = 0; d < 64; d++) {
            float a0 = Qs[(ty * 4 + 0) * 65 + d];
            float a1 = Qs[(ty * 4 + 1) * 65 + d];
            float a2 = Qs[(ty * 4 + 2) * 65 + d];
            float a3 = Qs[(ty * 4 + 3) * 65 + d];
            float b0 = Ks[(tx * 4 + 0) * 65 + d];
            float b1 = Ks[(tx * 4 + 1) * 65 + d];
            float b2 = Ks[(tx * 4 + 2) * 65 + d];
            float b3 = Ks[(tx * 4 + 3) * 65 + d];
            s[0][0] = fmaf(a0, b0, s[0][0]); s[0][1] = fmaf(a0, b1, s[0][1]);
            s[0][2] = fmaf(a0, b2, s[0][2]); s[0][3] = fmaf(a0, b3, s[0][3]);
            s[1][0] = fmaf(a1, b0, s[1][0]); s[1][1] = fmaf(a1, b1, s[1][1]);
            s[1][2] = fmaf(a1, b2, s[1][2]); s[1][3] = fmaf(a1, b3, s[1][3]);
            s[2][0] = fmaf(a2, b0, s[2][0]); s[2][1] = fmaf(a2, b1, s[2][1]);
            s[2][2] = fmaf(a2, b2, s[2][2]); s[2][3] = fmaf(a2, b3, s[2][3]);
            s[3][0] = fmaf(a3, b0, s[3][0]); s[3][1] = fmaf(a3, b1, s[3][1]);
            s[3][2] = fmaf(a3, b2, s[3][2]); s[3][3] = fmaf(a3, b3, s[3][3]);
        }
#pragma unroll
        for (int i = 0; i < 4; i++)
#pragma unroll
            for (int j = 0; j < 4; j++) {
                float val = s[i][j] * 0.125f;
                if (causal && (k0 + tx * 4 + j > q0 + ty * 4 + i)) val = -3.0e38f;
                Ss[(ty * 4 + i) * 65 + tx * 4 + j] = val;
            }
        __syncthreads();

        {
            int row = tid >> 2, q = tid & 3;
            float mx = -3.0e38f;
            for (int c = q; c < 64; c += 4) mx = fmaxf(mx, Ss[row * 65 + c]);
            mx = fmaxf(mx, __shfl_xor_sync(0xffffffffu, mx, 1));
            mx = fmaxf(mx, __shfl_xor_sync(0xffffffffu, mx, 2));
            float mold = mrow[row];
            float mnew = fmaxf(mold, mx);
            float al = __expf(mold - mnew);
            float ls = 0.0f;
            for (int c = q; c < 64; c += 4) {
                float p = __expf(Ss[row * 65 + c] - mnew);
                Ss[row * 65 + c] = p;
                ls += p;
            }
            ls += __shfl_xor_sync(0xffffffffu, ls, 1);
            ls += __shfl_xor_sync(0xffffffffu, ls, 2);
            if (q == 0) {
                mrow[row] = mnew;
                lrow[row] = lrow[row] * al + ls;
                arow[row] = al;
            }
        }
        __syncthreads();

        float alv[4];
#pragma unroll
        for (int i = 0; i < 4; i++) alv[i] = arow[ty * 4 + i];
#pragma unroll
        for (int i = 0; i < 4; i++)
#pragma unroll
            for (int j = 0; j < 4; j++) acc[i][j] *= alv[i];
#pragma unroll 8
        for (int jj = 0; jj < 64; jj++) {
            float p0 = Ss[(ty * 4 + 0) * 65 + jj];
            float p1 = Ss[(ty * 4 + 1) * 65 + jj];
            float p2 = Ss[(ty * 4 + 2) * 65 + jj];
            float p3 = Ss[(ty * 4 + 3) * 65 + jj];
            float v0 = Vs[jj * 64 + tx * 4 + 0];
            float v1 = Vs[jj * 64 + tx * 4 + 1];
            float v2 = Vs[jj * 64 + tx * 4 + 2];
            float v3 = Vs[jj * 64 + tx * 4 + 3];
            acc[0][0] = fmaf(p0, v0, acc[0][0]); acc[0][1] = fmaf(p0, v1, acc[0][1]);
            acc[0][2] = fmaf(p0, v2, acc[0][2]); acc[0][3] = fmaf(p0, v3, acc[0][3]);
            acc[1][0] = fmaf(p1, v0, acc[1][0]); acc[1][1] = fmaf(p1, v1, acc[1][1]);
            acc[1][2] = fmaf(p1, v2, acc[1][2]); acc[1][3] = fmaf(p1, v3, acc[1][3]);
            acc[2][0] = fmaf(p2, v0, acc[2][0]); acc[2][1] = fmaf(p2, v1, acc[2][1]);
            acc[2][2] = fmaf(p2, v2, acc[2][2]); acc[2][3] = fmaf(p2, v3, acc[2][3]);
            acc[3][0] = fmaf(p3, v0, acc[3][0]); acc[3][1] = fmaf(p3, v1, acc[3][1]);
            acc[3][2] = fmaf(p3, v2, acc[3][2]); acc[3][3] = fmaf(p3, v3, acc[3][3]);
        }
    }
    __syncthreads();

    float gmul = 1.0f;
    if (gate != nullptr) gmul = 1.0f - 1.0f / (1.0f + __expf(-gate[h]));

#pragma unroll
    for (int i = 0; i < 4; i++) {
        int rg = q0 + ty * 4 + i;
        float inv = gmul / lrow[ty * 4 + i];
        float* op = O + ((size_t)(b * SEQ_ + rg) * HEADS_ + h) * HD_ + tx * 4;
        *(float4*)op = make_float4(acc[i][0] * inv, acc[i][1] * inv,
                                   acc[i][2] * inv, acc[i][3] * inv);
    }
}

// ------------------------------ elementwise ------------------------------
__global__ void embed_kernel(const int* __restrict__ x, const float* __restrict__ emb,
                             float* __restrict__ out)
{
    int i = blockIdx.x * blockDim.x + threadIdx.x;
    if (i >= (int)(ACT_ELEMS / 4)) return;
    int row = i >> 8;
    int c4  = i & 255;
    int tok = x[row];
    ((float4*)out)[i] = ((const float4*)(emb + (size_t)tok * DIM_))[c4];
}

__global__ void bcast_init_kernel(const float* __restrict__ i0, const float* __restrict__ i1,
                                  float* __restrict__ S0, float* __restrict__ S1)
{
    int i = blockIdx.x * blockDim.x + threadIdx.x;
    if (i >= (int)(ACT_ELEMS / 4)) return;
    int src = i & (int)(SEQ_ * DIM_ / 4 - 1);
    ((float4*)S0)[i] = ((const float4*)i0)[src];
    ((float4*)S1)[i] = ((const float4*)i1)[src];
}

__global__ void add3_kernel(const float* __restrict__ a, const float* __restrict__ b,
                            const float* __restrict__ c, float* __restrict__ o)
{
    int i = blockIdx.x * blockDim.x + threadIdx.x;
    if (i >= (int)(ACT_ELEMS / 4)) return;
    float4 va = ((const float4*)a)[i];
    float4 vb = ((const float4*)b)[i];
    float4 vc = ((const float4*)c)[i];
    ((float4*)o)[i] = make_float4(va.x + vb.x + vc.x, va.y + vb.y + vc.y,
                                  va.z + vb.z + vc.z, va.w + vb.w + vc.w);
}

__global__ __launch_bounds__(256)
void rmsnorm_add_kernel(const float* __restrict__ a, const float* __restrict__ b,
                        float* __restrict__ o)
{
    int row = blockIdx.x;
    int tid = threadIdx.x;
    const float4* a4 = (const float4*)(a + (size_t)row * DIM_);
    const float4* b4 = (const float4*)(b + (size_t)row * DIM_);
    float4 va = a4[tid], vb = b4[tid];
    float4 s = make_float4(va.x + vb.x, va.y + vb.y, va.z + vb.z, va.w + vb.w);
    float ss = s.x * s.x + s.y * s.y + s.z * s.z + s.w * s.w;
#pragma unroll
    for (int off = 16; off > 0; off >>= 1) ss += __shfl_xor_sync(0xffffffffu, ss, off);
    __shared__ float red[8];
    __shared__ float scale_s;
    if ((tid & 31) == 0) red[tid >> 5] = ss;
    __syncthreads();
    if (tid == 0) {
        float t = 0.0f;
#pragma unroll
        for (int w = 0; w < 8; w++) t += red[w];
        scale_s = rsqrtf(t * (1.0f / DIM_) + 1e-6f);
    }
    __syncthreads();
    float sc = scale_s;
    ((float4*)(o + (size_t)row * DIM_))[tid] =
        make_float4(s.x * sc, s.y * sc, s.z * sc, s.w * sc);
}

__global__ void mean_kernel(const float* __restrict__ S, float* __restrict__ M)
{
    int idx = blockIdx.x * blockDim.x + threadIdx.x;
    if (idx >= B_ * DIM_) return;
    int b = idx >> 10, d = idx & (DIM_ - 1);
    const float* p = S + (size_t)b * SEQ_ * DIM_ + d;
    float s = 0.0f;
    for (int t = 0; t < SEQ_; t++) s += p[(size_t)t * DIM_];
    M[idx] = s * (1.0f / SEQ_);
}

__global__ void qhead_kernel(const float* __restrict__ M, const float* __restrict__ W,
                             float* __restrict__ out)
{
    int w = threadIdx.x >> 5, lane = threadIdx.x & 31;
    int b = w >> 1, o = w & 1;
    const float* m  = M + (size_t)b * DIM_;
    const float* ww = W + (size_t)o * DIM_;
    float s = 0.0f;
    for (int k = lane; k < DIM_; k += 32) s += m[k] * ww[k];
#pragma unroll
    for (int off = 16; off > 0; off >>= 1) s += __shfl_xor_sync(0xffffffffu, s, off);
    if (lane == 0) out[b * 2 + o] = 1.0f / (1.0f + __expf(-s));
}

// ------------------------------ host orchestration ------------------------------
static void launch_gemm(const float* A, const float* B, float* C,
                        int M, int N, int K, int fuse_gelu)
{
    dim3 grid(N / 128, M / 128);
    if (fuse_gelu) gemm_bf16s<1><<<grid, 256>>>(A, B, C, M, N, K);
    else           gemm_bf16s<0><<<grid, 256>>>(A, B, C, M, N, K);
}

struct LayerP { const float *wq, *wk, *wv, *wo, *w1, *w2; };

static void run_hrm_layer(float* H, const LayerP& p, float* OUT,
                          float* Q, float* Kb, float* V, float* AT,
                          float* T, float* G, float* FF)
{
    launch_gemm(H, p.wq, Q,  ROWS_, DIM_, DIM_, 0);
    launch_gemm(H, p.wk, Kb, ROWS_, DIM_, DIM_, 0);
    launch_gemm(H, p.wv, V,  ROWS_, DIM_, DIM_, 0);
    attn_kernel<<<dim3(SEQ_ / 64, B_ * HEADS_), 256, ATTN_SMEM_FLOATS * 4>>>(
        Q, Kb, V, AT, nullptr, 0);
    launch_gemm(AT, p.wo, T, ROWS_, DIM_, DIM_, 0);
    rmsnorm_add_kernel<<<ROWS_, 256>>>(H, T, G);
    launch_gemm(G, p.w1, FF, ROWS_, FF_, DIM_, 1);
    launch_gemm(FF, p.w2, T, ROWS_, DIM_, FF_, 0);
    rmsnorm_add_kernel<<<ROWS_, 256>>>(G, T, OUT);
}

extern "C" void kernel_launch(void* const* d_in, const int* in_sizes, int n_in,
                              void* d_out, int out_size)
{
    (void)in_sizes; (void)n_in; (void)out_size;
    const int*   x     = (const int*)  d_in[0];
    const float* emb   = (const float*)d_in[1];
    const float* a_wq  = (const float*)d_in[2];
    const float* a_wk  = (const float*)d_in[3];
    const float* a_wv  = (const float*)d_in[4];
    const float* a_wo  = (const float*)d_in[5];
    const float* gate  = (const float*)d_in[6];
    const float* init0 = (const float*)d_in[7];
    const float* init1 = (const float*)d_in[8];
    LayerP lp[2];
    lp[0] = { (const float*)d_in[9],  (const float*)d_in[10], (const float*)d_in[11],
              (const float*)d_in[12], (const float*)d_in[13], (const float*)d_in[14] };
    lp[1] = { (const float*)d_in[15], (const float*)d_in[16], (const float*)d_in[17],
              (const float*)d_in[18], (const float*)d_in[19], (const float*)d_in[20] };
    const float* w_out   = (const float*)d_in[21];
    const float* w_qhead = (const float*)d_in[22];
    float* out = (float*)d_out;

    float *X, *XENR, *S0, *S1, *H0, *H1, *Q, *Kb, *V, *AT, *T, *G, *FF, *MEAN;
    cudaGetSymbolAddress((void**)&X,    g_X);
    cudaGetSymbolAddress((void**)&XENR, g_XENR);
    cudaGetSymbolAddress((void**)&S0,   g_S0);
    cudaGetSymbolAddress((void**)&S1,   g_S1);
    cudaGetSymbolAddress((void**)&H0,   g_H0);
    cudaGetSymbolAddress((void**)&H1,   g_H1);
    cudaGetSymbolAddress((void**)&Q,    g_Q);
    cudaGetSymbolAddress((void**)&Kb,   g_K);
    cudaGetSymbolAddress((void**)&V,    g_V);
    cudaGetSymbolAddress((void**)&AT,   g_AT);
    cudaGetSymbolAddress((void**)&T,    g_T);
    cudaGetSymbolAddress((void**)&G,    g_G);
    cudaGetSymbolAddress((void**)&FF,   g_FF);
    cudaGetSymbolAddress((void**)&MEAN, g_MEAN);

    cudaFuncSetAttribute(attn_kernel, cudaFuncAttributeMaxDynamicSharedMemorySize,
                         ATTN_SMEM_FLOATS * 4);

    const int v4blocks = (int)(ACT_ELEMS / 4 + 255) / 256;

    embed_kernel<<<v4blocks, 256>>>(x, emb, X);

    launch_gemm(X, a_wq, Q,  ROWS_, DIM_, DIM_, 0);
    launch_gemm(X, a_wk, Kb, ROWS_, DIM_, DIM_, 0);
    launch_gemm(X, a_wv, V,  ROWS_, DIM_, DIM_, 0);
    attn_kernel<<<dim3(SEQ_ / 64, B_ * HEADS_), 256, ATTN_SMEM_FLOATS * 4>>>(
        Q, Kb, V, AT, gate, 1);
    launch_gemm(AT, a_wo, XENR, ROWS_, DIM_, DIM_, 0);

    bcast_init_kernel<<<v4blocks, 256>>>(init0, init1, S0, S1);

    for (int step = 0; step < 8; step++) {
        bool u1 = ((step + 1) % 4 == 0);
        add3_kernel<<<v4blocks, 256>>>(S0, XENR, S1, H0);
        if (u1) add3_kernel<<<v4blocks, 256>>>(S1, XENR, S0, H1);
        run_hrm_layer(H0, lp[0], S0, Q, Kb, V, AT, T, G, FF);
        if (u1) run_hrm_layer(H1, lp[1], S1, Q, Kb, V, AT, T, G, FF);
    }

    launch_gemm(S1, w_out, out, ROWS_, VOCAB_, DIM_, 0);
    mean_kernel<<<(B_ * DIM_ + 255) / 256, 256>>>(S1, MEAN);
    qhead_kernel<<<1, 256>>>(MEAN, w_qhead, out + (size_t)ROWS_ * VOCAB_);
}

// round 6
// speedup vs baseline: 1.7372x; 1.1495x over previous
#include <cuda_runtime.h>
#include <cuda_bf16.h>
#include <math.h>
#include <stdint.h>

#define B_    4
#define SEQ_  1024
#define DIM_  1024
#define HEADS_ 16
#define HD_   64
#define VOCAB_ 32000
#define FF_   4096

#define ROWS_ (B_*SEQ_)                    // 4096
#define ACT_ELEMS ((size_t)ROWS_*DIM_)     // 4M floats
#define ACT_PAIRS (ACT_ELEMS/2)            // 2M uint32

// ------------------------- fp32 scratch -------------------------
__device__ float g_XENR[ACT_ELEMS];
__device__ float g_S0  [ACT_ELEMS];
__device__ float g_S1  [ACT_ELEMS];
__device__ float g_H0  [ACT_ELEMS];
__device__ float g_H1  [ACT_ELEMS];
__device__ float g_Q   [ACT_ELEMS];
__device__ float g_K   [ACT_ELEMS];
__device__ float g_V   [ACT_ELEMS];
__device__ float g_T   [ACT_ELEMS];
__device__ float g_G   [ACT_ELEMS];
__device__ float g_MEAN[B_*DIM_];

// ------------------------- packed bf16 hi/lo scratch (uint32 = bf16x2) -------------------------
__device__ __align__(16) uint32_t g_cXhi [ACT_PAIRS],     g_cXlo [ACT_PAIRS];
__device__ __align__(16) uint32_t g_cH0hi[ACT_PAIRS],     g_cH0lo[ACT_PAIRS];
__device__ __align__(16) uint32_t g_cH1hi[ACT_PAIRS],     g_cH1lo[ACT_PAIRS];
__device__ __align__(16) uint32_t g_cAThi[ACT_PAIRS],     g_cATlo[ACT_PAIRS];
__device__ __align__(16) uint32_t g_cGhi [ACT_PAIRS],     g_cGlo [ACT_PAIRS];
__device__ __align__(16) uint32_t g_cFFhi[(size_t)ROWS_*FF_/2], g_cFFlo[(size_t)ROWS_*FF_/2];
__device__ __align__(16) uint32_t g_cS1hi[ACT_PAIRS],     g_cS1lo[ACT_PAIRS];

// weights, packed: slots of 0.5M uint32 (= one 1024x1024 matrix)
#define WSZ 524288ull
#define W_TOTAL 31064064ull   // 28*WSZ + 32000*1024/2
__device__ __align__(16) uint32_t g_WHI[W_TOTAL];
__device__ __align__(16) uint32_t g_WLO[W_TOTAL];
// slot offsets (units of WSZ): awq0 awk1 awv2 awo3 | l0: q4 k5 v6 o7 w1@8(x4) w2@12(x4)
// l1: q16 k17 v18 o19 w1@20 w2@24 | w_out@28

// ------------------------------ helpers ------------------------------
__device__ __forceinline__ float gelu_tanh(float x) {
    float x3 = x * x * x;
    return 0.5f * x * (1.0f + tanhf(0.79788456080286535588f * (x + 0.044715f * x3)));
}
__device__ __forceinline__ uint32_t pack_bf16(__nv_bfloat16 lo, __nv_bfloat16 hi) {
    __nv_bfloat162 p; p.x = lo; p.y = hi;
    return *reinterpret_cast<uint32_t*>(&p);
}
__device__ __forceinline__ void split2(float v0, float v1, uint32_t& hi, uint32_t& lo) {
    __nv_bfloat16 h0 = __float2bfloat16_rn(v0), h1 = __float2bfloat16_rn(v1);
    hi = pack_bf16(h0, h1);
    lo = pack_bf16(__float2bfloat16_rn(v0 - __bfloat162float(h0)),
                   __float2bfloat16_rn(v1 - __bfloat162float(h1)));
}
__device__ __forceinline__ void mma_bf16(float c[4], const uint32_t a[4], const uint32_t b[2]) {
    asm volatile(
        "mma.sync.aligned.m16n8k16.row.col.f32.bf16.bf16.f32 "
        "{%0,%1,%2,%3}, {%4,%5,%6,%7}, {%8,%9}, {%0,%1,%2,%3};"
        : "+f"(c[0]), "+f"(c[1]), "+f"(c[2]), "+f"(c[3])
        : "r"(a[0]), "r"(a[1]), "r"(a[2]), "r"(a[3]), "r"(b[0]), "r"(b[1]));
}
__device__ __forceinline__ void ldsm_x4(uint32_t r[4], uint32_t addr) {
    asm volatile("ldmatrix.sync.aligned.m8n8.x4.shared.b16 {%0,%1,%2,%3}, [%4];"
                 : "=r"(r[0]), "=r"(r[1]), "=r"(r[2]), "=r"(r[3]) : "r"(addr));
}
__device__ __forceinline__ void ldsm_x2(uint32_t r[2], uint32_t addr) {
    asm volatile("ldmatrix.sync.aligned.m8n8.x2.shared.b16 {%0,%1}, [%2];"
                 : "=r"(r[0]), "=r"(r[1]) : "r"(addr));
}
__device__ __forceinline__ void cp16(uint32_t saddr, const void* g) {
    asm volatile("cp.async.cg.shared.global [%0], [%1], 16;" :: "r"(saddr), "l"(g));
}

// ------------------------------ GEMM (packed operands, cp.async, ldmatrix) ------------------------------
// C[M,N] = A[M,K] @ B[N,K]^T, operands pre-split into packed bf16 hi/lo (uint32 = 2 K-elems).
// acc += hi*lo + lo*hi + hi*hi. 128x128 tile, K-chunk 16, 256 threads, 3-stage cp.async.
// MODE 0: fp32 out to C.  MODE 1: gelu + split to Chi/Clo (no fp32 out).
#define RST 12                    // smem row stride in uint32 (conflict-free)
#define ARR_B 6144                // bytes per array: 128*12*4
#define STAGE_B 24576             // 4 arrays
#define GEMM_SMEM (3*STAGE_B)     // 73728

template<int MODE>
__global__ __launch_bounds__(256)
void gemm_cp(const uint32_t* __restrict__ Ahi, const uint32_t* __restrict__ Alo,
             const uint32_t* __restrict__ Bhi, const uint32_t* __restrict__ Blo,
             float* __restrict__ C, uint32_t* __restrict__ Chi, uint32_t* __restrict__ Clo,
             int M, int N, int K)
{
    extern __shared__ uint32_t smem[];
    const uint32_t smem_base = (uint32_t)__cvta_generic_to_shared(smem);

    const int K2 = K >> 1;
    const int bm = blockIdx.y * 128;
    const int bn = blockIdx.x * 128;
    const int tid = threadIdx.x;

    // staging: row = tid>>1 (0..127), half = tid&1 -> 16B each of 32B row-chunk
    const int row = tid >> 1, half = tid & 1;
    const uint32_t* pAhi = Ahi + (size_t)(bm + row) * K2 + half * 4;
    const uint32_t* pAlo = Alo + (size_t)(bm + row) * K2 + half * 4;
    const uint32_t* pBhi = Bhi + (size_t)(bn + row) * K2 + half * 4;
    const uint32_t* pBlo = Blo + (size_t)(bn + row) * K2 + half * 4;
    const uint32_t dst0 = smem_base + (uint32_t)((row * RST + half * 4) * 4);

    const int wid = tid >> 5, lane = tid & 31;
    const int warp_m = (wid & 1) * 64;
    const int warp_n = (wid >> 1) * 32;
    const int g = lane >> 2, t = lane & 3;

    // ldmatrix lane addresses (byte offsets within a stage)
    uint32_t aoff[4], boff[4];
    {
        int arow = lane & 15, acol = (lane >> 4) * 4;
        int brow = lane & 7,  bcol = ((lane >> 3) & 1) * 4;
#pragma unroll
        for (int fm = 0; fm < 4; fm++)
            aoff[fm] = (uint32_t)(((warp_m + fm * 16 + arow) * RST + acol) * 4);
#pragma unroll
        for (int fn = 0; fn < 4; fn++)
            boff[fn] = (uint32_t)(2 * ARR_B + ((warp_n + fn * 8 + brow) * RST + bcol) * 4);
    }

    float acc[4][4][4];
#pragma unroll
    for (int i = 0; i < 4; i++)
#pragma unroll
        for (int j = 0; j < 4; j++)
#pragma unroll
            for (int r = 0; r < 4; r++) acc[i][j][r] = 0.0f;

    const int nch = K >> 4;

    auto issue = [&](int kc, int s) {
        uint32_t d = dst0 + (uint32_t)(s * STAGE_B);
        cp16(d,             pAhi + (size_t)kc * 8);
        cp16(d + ARR_B,     pAlo + (size_t)kc * 8);
        cp16(d + 2 * ARR_B, pBhi + (size_t)kc * 8);
        cp16(d + 3 * ARR_B, pBlo + (size_t)kc * 8);
        asm volatile("cp.async.commit_group;");
    };

    issue(0, 0);
    if (nch > 1) issue(1, 1);

    for (int kc = 0; kc < nch; kc++) {
        asm volatile("cp.async.wait_group 1;");
        __syncthreads();
        if (kc + 2 < nch) issue(kc + 2, (kc + 2) % 3);

        const uint32_t sb = smem_base + (uint32_t)((kc % 3) * STAGE_B);
        uint32_t ahi[4][4], alo[4][4], bhi[4][2], blo[4][2];
#pragma unroll
        for (int fm = 0; fm < 4; fm++) {
            ldsm_x4(ahi[fm], sb + aoff[fm]);
            ldsm_x4(alo[fm], sb + aoff[fm] + ARR_B);
        }
#pragma unroll
        for (int fn = 0; fn < 4; fn++) {
            ldsm_x2(bhi[fn], sb + boff[fn]);
            ldsm_x2(blo[fn], sb + boff[fn] + ARR_B);
        }
#pragma unroll
        for (int fm = 0; fm < 4; fm++)
#pragma unroll
            for (int fn = 0; fn < 4; fn++) {
                mma_bf16(acc[fm][fn], ahi[fm], blo[fn]);
                mma_bf16(acc[fm][fn], alo[fm], bhi[fn]);
                mma_bf16(acc[fm][fn], ahi[fm], bhi[fn]);
            }
    }

    // epilogue: c0(row g, col 2t), c1(g,2t+1), c2(g+8,2t), c3(g+8,2t+1)
#pragma unroll
    for (int fm = 0; fm < 4; fm++) {
#pragma unroll
        for (int fn = 0; fn < 4; fn++) {
            int row0 = bm + warp_m + fm * 16 + g;
            int col  = bn + warp_n + fn * 8 + 2 * t;
            float v0 = acc[fm][fn][0], v1 = acc[fm][fn][1];
            float v2 = acc[fm][fn][2], v3 = acc[fm][fn][3];
            if (MODE == 1) {
                v0 = gelu_tanh(v0); v1 = gelu_tanh(v1);
                v2 = gelu_tanh(v2); v3 = gelu_tanh(v3);
                int N2 = N >> 1;
                int cp0 = col >> 1;
                uint32_t h, l;
                split2(v0, v1, h, l);
                Chi[(size_t)row0 * N2 + cp0] = h;  Clo[(size_t)row0 * N2 + cp0] = l;
                split2(v2, v3, h, l);
                Chi[(size_t)(row0 + 8) * N2 + cp0] = h;  Clo[(size_t)(row0 + 8) * N2 + cp0] = l;
            } else {
                *(float2*)(C + (size_t)row0 * N + col)       = make_float2(v0, v1);
                *(float2*)(C + (size_t)(row0 + 8) * N + col) = make_float2(v2, v3);
            }
        }
    }
}

// ------------------------------ attention (fp32 in, packed hi/lo out) ------------------------------
#define ATTN_SMEM_FLOATS (64*65*3 + 64*64 + 64*3)
__global__ __launch_bounds__(256)
void attn_kernel(const float* __restrict__ Q, const float* __restrict__ K,
                 const float* __restrict__ V,
                 uint32_t* __restrict__ Ohi, uint32_t* __restrict__ Olo,
                 const float* __restrict__ gate, int causal)
{
    extern __shared__ float sm[];
    float* Qs   = sm;
    float* Ks   = Qs + 64 * 65;
    float* Ss   = Ks + 64 * 65;
    float* Vs   = Ss + 64 * 65;
    float* mrow = Vs + 64 * 64;
    float* lrow = mrow + 64;
    float* arow = lrow + 64;

    const int bh = blockIdx.y;
    const int b  = bh / HEADS_;
    const int h  = bh % HEADS_;
    const int q0 = blockIdx.x * 64;
    const int tid = threadIdx.x;

    const float* Qbase = Q + ((size_t)(b * SEQ_ + q0) * HEADS_ + h) * HD_;

    for (int i = tid; i < 1024; i += 256) {
        int r = i >> 4, c4 = (i & 15) << 2;
        float4 v = *(const float4*)(Qbase + (size_t)r * DIM_ + c4);
        Qs[r * 65 + c4 + 0] = v.x; Qs[r * 65 + c4 + 1] = v.y;
        Qs[r * 65 + c4 + 2] = v.z; Qs[r * 65 + c4 + 3] = v.w;
    }
    if (tid < 64) { mrow[tid] = -3.0e38f; lrow[tid] = 0.0f; }

    const int ty = tid >> 4, tx = tid & 15;
    float acc[4][4];
#pragma unroll
    for (int i = 0; i < 4; i++)
#pragma unroll
        for (int j = 0; j < 4; j++) acc[i][j] = 0.0f;

    const int nkb = causal ? (q0 / 64 + 1) : (SEQ_ / 64);

    for (int kb = 0; kb < nkb; kb++) {
        const int k0 = kb * 64;
        __syncthreads();
        const float* Kbase = K + ((size_t)(b * SEQ_ + k0) * HEADS_ + h) * HD_;
        const float* Vbase = V + ((size_t)(b * SEQ_ + k0) * HEADS_ + h) * HD_;
        for (int i = tid; i < 1024; i += 256) {
            int r = i >> 4, c4 = (i & 15) << 2;
            float4 kv = *(const float4*)(Kbase + (size_t)r * DIM_ + c4);
            Ks[r * 65 + c4 + 0] = kv.x; Ks[r * 65 + c4 + 1] = kv.y;
            Ks[r * 65 + c4 + 2] = kv.z; Ks[r * 65 + c4 + 3] = kv.w;
            float4 vv = *(const float4*)(Vbase + (size_t)r * DIM_ + c4);
            *(float4*)&Vs[r * 64 + c4] = vv;
        }
        __syncthreads();

        float s[4][4];
#pragma unroll
        for (int i = 0; i < 4; i++)
#pragma unroll
            for (int j = 0; j < 4; j++) s[i][j] = 0.0f;
#pragma unroll 8
        for (int d = 0; d < 64; d++) {
            float a0 = Qs[(ty * 4 + 0) * 65 + d];
            float a1 = Qs[(ty * 4 + 1) * 65 + d];
            float a2 = Qs[(ty * 4 + 2) * 65 + d];
            float a3 = Qs[(ty * 4 + 3) * 65 + d];
            float b0 = Ks[(tx * 4 + 0) * 65 + d];
            float b1 = Ks[(tx * 4 + 1) * 65 + d];
            float b2 = Ks[(tx * 4 + 2) * 65 + d];
            float b3 = Ks[(tx * 4 + 3) * 65 + d];
            s[0][0] = fmaf(a0, b0, s[0][0]); s[0][1] = fmaf(a0, b1, s[0][1]);
            s[0][2] = fmaf(a0, b2, s[0][2]); s[0][3] = fmaf(a0, b3, s[0][3]);
            s[1][0] = fmaf(a1, b0, s[1][0]); s[1][1] = fmaf(a1, b1, s[1][1]);
            s[1][2] = fmaf(a1, b2, s[1][2]); s[1][3] = fmaf(a1, b3, s[1][3]);
            s[2][0] = fmaf(a2, b0, s[2][0]); s[2][1] = fmaf(a2, b1, s[2][1]);
            s[2][2] = fmaf(a2, b2, s[2][2]); s[2][3] = fmaf(a2, b3, s[2][3]);
            s[3][0] = fmaf(a3, b0, s[3][0]); s[3][1] = fmaf(a3, b1, s[3][1]);
            s[3][2] = fmaf(a3, b2, s[3][2]); s[3][3] = fmaf(a3, b3, s[3][3]);
        }
#pragma unroll
        for (int i = 0; i < 4; i++)
#pragma unroll
            for (int j = 0; j < 4; j++) {
                float val = s[i][j] * 0.125f;
                if (causal && (k0 + tx * 4 + j > q0 + ty * 4 + i)) val = -3.0e38f;
                Ss[(ty * 4 + i) * 65 + tx * 4 + j] = val;
            }
        __syncthreads();

        {
            int row = tid >> 2, q = tid & 3;
            float mx = -3.0e38f;
            for (int c = q; c < 64; c += 4) mx = fmaxf(mx, Ss[row * 65 + c]);
            mx = fmaxf(mx, __shfl_xor_sync(0xffffffffu, mx, 1));
            mx = fmaxf(mx, __shfl_xor_sync(0xffffffffu, mx, 2));
            float mold = mrow[row];
            float mnew = fmaxf(mold, mx);
            float al = __expf(mold - mnew);
            float ls = 0.0f;
            for (int c = q; c < 64; c += 4) {
                float p = __expf(Ss[row * 65 + c] - mnew);
                Ss[row * 65 + c] = p;
                ls += p;
            }
            ls += __shfl_xor_sync(0xffffffffu, ls, 1);
            ls += __shfl_xor_sync(0xffffffffu, ls, 2);
            if (q == 0) {
                mrow[row] = mnew;
                lrow[row] = lrow[row] * al + ls;
                arow[row] = al;
            }
        }
        __syncthreads();

        float alv[4];
#pragma unroll
        for (int i = 0; i < 4; i++) alv[i] = arow[ty * 4 + i];
#pragma unroll
        for (int i = 0; i < 4; i++)
#pragma unroll
            for (int j = 0; j < 4; j++) acc[i][j] *= alv[i];
#pragma unroll 8
        for (int jj = 0; jj < 64; jj++) {
            float p0 = Ss[(ty * 4 + 0) * 65 + jj];
            float p1 = Ss[(ty * 4 + 1) * 65 + jj];
            float p2 = Ss[(ty * 4 + 2) * 65 + jj];
            float p3 = Ss[(ty * 4 + 3) * 65 + jj];
            float v0 = Vs[jj * 64 + tx * 4 + 0];
            float v1 = Vs[jj * 64 + tx * 4 + 1];
            float v2 = Vs[jj * 64 + tx * 4 + 2];
            float v3 = Vs[jj * 64 + tx * 4 + 3];
            acc[0][0] = fmaf(p0, v0, acc[0][0]); acc[0][1] = fmaf(p0, v1, acc[0][1]);
            acc[0][2] = fmaf(p0, v2, acc[0][2]); acc[0][3] = fmaf(p0, v3, acc[0][3]);
            acc[1][0] = fmaf(p1, v0, acc[1][0]); acc[1][1] = fmaf(p1, v1, acc[1][1]);
            acc[1][2] = fmaf(p1, v2, acc[1][2]); acc[1][3] = fmaf(p1, v3, acc[1][3]);
            acc[2][0] = fmaf(p2, v0, acc[2][0]); acc[2][1] = fmaf(p2, v1, acc[2][1]);
            acc[2][2] = fmaf(p2, v2, acc[2][2]); acc[2][3] = fmaf(p2, v3, acc[2][3]);
            acc[3][0] = fmaf(p3, v0, acc[3][0]); acc[3][1] = fmaf(p3, v1, acc[3][1]);
            acc[3][2] = fmaf(p3, v2, acc[3][2]); acc[3][3] = fmaf(p3, v3, acc[3][3]);
        }
    }
    __syncthreads();

    float gmul = 1.0f;
    if (gate != nullptr) gmul = 1.0f - 1.0f / (1.0f + __expf(-gate[h]));

#pragma unroll
    for (int i = 0; i < 4; i++) {
        int rg = q0 + ty * 4 + i;
        float inv = gmul / lrow[ty * 4 + i];
        int base = (((b * SEQ_ + rg) * HEADS_ + h) * HD_ + tx * 4) >> 1;
        uint32_t h0, l0, h1, l1;
        split2(acc[i][0] * inv, acc[i][1] * inv, h0, l0);
        split2(acc[i][2] * inv, acc[i][3] * inv, h1, l1);
        Ohi[base] = h0; Ohi[base + 1] = h1;
        Olo[base] = l0; Olo[base + 1] = l1;
    }
}

// ------------------------------ elementwise ------------------------------
// generic fp32 -> packed hi/lo (used for weights and final S1)
__global__ void pack_split_kernel(const float* __restrict__ in,
                                  uint32_t* __restrict__ hi, uint32_t* __restrict__ lo,
                                  int n4)
{
    int i = blockIdx.x * blockDim.x + threadIdx.x;
    if (i >= n4) return;
    float4 v = ((const float4*)in)[i];
    uint32_t h0, l0, h1, l1;
    split2(v.x, v.y, h0, l0);
    split2(v.z, v.w, h1, l1);
    hi[2 * i] = h0; hi[2 * i + 1] = h1;
    lo[2 * i] = l0; lo[2 * i + 1] = l1;
}

__global__ void embed_pack_kernel(const int* __restrict__ x, const float* __restrict__ emb,
                                  uint32_t* __restrict__ hi, uint32_t* __restrict__ lo)
{
    int i = blockIdx.x * blockDim.x + threadIdx.x;
    if (i >= (int)(ACT_ELEMS / 4)) return;
    int row = i >> 8, c4 = i & 255;
    int tok = x[row];
    float4 v = ((const float4*)(emb + (size_t)tok * DIM_))[c4];
    uint32_t h0, l0, h1, l1;
    split2(v.x, v.y, h0, l0);
    split2(v.z, v.w, h1, l1);
    hi[2 * i] = h0; hi[2 * i + 1] = h1;
    lo[2 * i] = l0; lo[2 * i + 1] = l1;
}

__global__ void bcast_init_kernel(const float* __restrict__ i0, const float* __restrict__ i1,
                                  float* __restrict__ S0, float* __restrict__ S1)
{
    int i = blockIdx.x * blockDim.x + threadIdx.x;
    if (i >= (int)(ACT_ELEMS / 4)) return;
    int src = i & (int)(SEQ_ * DIM_ / 4 - 1);
    ((float4*)S0)[i] = ((const float4*)i0)[src];
    ((float4*)S1)[i] = ((const float4*)i1)[src];
}

__global__ void add3_pack_kernel(const float* __restrict__ a, const float* __restrict__ b,
                                 const float* __restrict__ c, float* __restrict__ o,
                                 uint32_t* __restrict__ hi, uint32_t* __restrict__ lo)
{
    int i = blockIdx.x * blockDim.x + threadIdx.x;
    if (i >= (int)(ACT_ELEMS / 4)) return;
    float4 va = ((const float4*)a)[i];
    float4 vb = ((const float4*)b)[i];
    float4 vc = ((const float4*)c)[i];
    float4 s = make_float4(va.x + vb.x + vc.x, va.y + vb.y + vc.y,
                           va.z + vb.z + vc.z, va.w + vb.w + vc.w);
    ((float4*)o)[i] = s;
    uint32_t h0, l0, h1, l1;
    split2(s.x, s.y, h0, l0);
    split2(s.z, s.w, h1, l1);
    hi[2 * i] = h0; hi[2 * i + 1] = h1;
    lo[2 * i] = l0; lo[2 * i + 1] = l1;
}

template<int PACK>
__global__ __launch_bounds__(256)
void rmsnorm_add_kernel(const float* __restrict__ a, const float* __restrict__ b,
                        float* __restrict__ o,
                        uint32_t* __restrict__ hi, uint32_t* __restrict__ lo)
{
    int row = blockIdx.x;
    int tid = threadIdx.x;
    const float4* a4 = (const float4*)(a + (size_t)row * DIM_);
    const float4* b4 = (const float4*)(b + (size_t)row * DIM_);
    float4 va = a4[tid], vb = b4[tid];
    float4 s = make_float4(va.x + vb.x, va.y + vb.y, va.z + vb.z, va.w + vb.w);
    float ss = s.x * s.x + s.y * s.y + s.z * s.z + s.w * s.w;
#pragma unroll
    for (int off = 16; off > 0; off >>= 1) ss += __shfl_xor_sync(0xffffffffu, ss, off);
    __shared__ float red[8];
    __shared__ float scale_s;
    if ((tid & 31) == 0) red[tid >> 5] = ss;
    __syncthreads();
    if (tid == 0) {
        float t = 0.0f;
#pragma unroll
        for (int w = 0; w < 8; w++) t += red[w];
        scale_s = rsqrtf(t * (1.0f / DIM_) + 1e-6f);
    }
    __syncthreads();
    float sc = scale_s;
    float4 r = make_float4(s.x * sc, s.y * sc, s.z * sc, s.w * sc);
    ((float4*)(o + (size_t)row * DIM_))[tid] = r;
    if (PACK) {
        uint32_t h0, l0, h1, l1;
        split2(r.x, r.y, h0, l0);
        split2(r.z, r.w, h1, l1);
        size_t pidx = (size_t)row * (DIM_ / 2) + tid * 2;
        hi[pidx] = h0; hi[pidx + 1] = h1;
        lo[pidx] = l0; lo[pidx + 1] = l1;
    }
}

__global__ void mean_kernel(const float* __restrict__ S, float* __restrict__ M)
{
    int idx = blockIdx.x * blockDim.x + threadIdx.x;
    if (idx >= B_ * DIM_) return;
    int b = idx >> 10, d = idx & (DIM_ - 1);
    const float* p = S + (size_t)b * SEQ_ * DIM_ + d;
    float s = 0.0f;
    for (int t = 0; t < SEQ_; t++) s += p[(size_t)t * DIM_];
    M[idx] = s * (1.0f / SEQ_);
}

__global__ void qhead_kernel(const float* __restrict__ M, const float* __restrict__ W,
                             float* __restrict__ out)
{
    int w = threadIdx.x >> 5, lane = threadIdx.x & 31;
    int b = w >> 1, o = w & 1;
    const float* m  = M + (size_t)b * DIM_;
    const float* ww = W + (size_t)o * DIM_;
    float s = 0.0f;
    for (int k = lane; k < DIM_; k += 32) s += m[k] * ww[k];
#pragma unroll
    for (int off = 16; off > 0; off >>= 1) s += __shfl_xor_sync(0xffffffffu, s, off);
    if (lane == 0) out[b * 2 + o] = 1.0f / (1.0f + __expf(-s));
}

// ------------------------------ host orchestration ------------------------------
static void launch_gemm(const uint32_t* Ahi, const uint32_t* Alo,
                        const uint32_t* Bhi, const uint32_t* Blo,
                        float* C, uint32_t* Chi, uint32_t* Clo,
                        int M, int N, int K, int mode)
{
    dim3 grid(N / 128, M / 128);
    if (mode) gemm_cp<1><<<grid, 256, GEMM_SMEM>>>(Ahi, Alo, Bhi, Blo, C, Chi, Clo, M, N, K);
    else      gemm_cp<0><<<grid, 256, GEMM_SMEM>>>(Ahi, Alo, Bhi, Blo, C, Chi, Clo, M, N, K);
}

struct WOffs { size_t wq, wk, wv, wo, w1, w2; };

extern "C" void kernel_launch(void* const* d_in, const int* in_sizes, int n_in,
                              void* d_out, int out_size)
{
    (void)in_sizes; (void)n_in; (void)out_size;
    const int*   x     = (const int*)  d_in[0];
    const float* emb   = (const float*)d_in[1];
    const float* gate  = (const float*)d_in[6];
    const float* init0 = (const float*)d_in[7];
    const float* init1 = (const float*)d_in[8];
    const float* w_out   = (const float*)d_in[21];
    const float* w_qhead = (const float*)d_in[22];
    float* out = (float*)d_out;

    float *XENR, *S0, *S1, *H0, *H1, *Q, *Kb, *V, *T, *G, *MEAN;
    cudaGetSymbolAddress((void**)&XENR, g_XENR);
    cudaGetSymbolAddress((void**)&S0,   g_S0);
    cudaGetSymbolAddress((void**)&S1,   g_S1);
    cudaGetSymbolAddress((void**)&H0,   g_H0);
    cudaGetSymbolAddress((void**)&H1,   g_H1);
    cudaGetSymbolAddress((void**)&Q,    g_Q);
    cudaGetSymbolAddress((void**)&Kb,   g_K);
    cudaGetSymbolAddress((void**)&V,    g_V);
    cudaGetSymbolAddress((void**)&T,    g_T);
    cudaGetSymbolAddress((void**)&G,    g_G);
    cudaGetSymbolAddress((void**)&MEAN, g_MEAN);

    uint32_t *cXhi, *cXlo, *cH0hi, *cH0lo, *cH1hi, *cH1lo, *cAThi, *cATlo;
    uint32_t *cGhi, *cGlo, *cFFhi, *cFFlo, *cS1hi, *cS1lo, *WHI, *WLO;
    cudaGetSymbolAddress((void**)&cXhi,  g_cXhi);  cudaGetSymbolAddress((void**)&cXlo,  g_cXlo);
    cudaGetSymbolAddress((void**)&cH0hi, g_cH0hi); cudaGetSymbolAddress((void**)&cH0lo, g_cH0lo);
    cudaGetSymbolAddress((void**)&cH1hi, g_cH1hi); cudaGetSymbolAddress((void**)&cH1lo, g_cH1lo);
    cudaGetSymbolAddress((void**)&cAThi, g_cAThi); cudaGetSymbolAddress((void**)&cATlo, g_cATlo);
    cudaGetSymbolAddress((void**)&cGhi,  g_cGhi);  cudaGetSymbolAddress((void**)&cGlo,  g_cGlo);
    cudaGetSymbolAddress((void**)&cFFhi, g_cFFhi); cudaGetSymbolAddress((void**)&cFFlo, g_cFFlo);
    cudaGetSymbolAddress((void**)&cS1hi, g_cS1hi); cudaGetSymbolAddress((void**)&cS1lo, g_cS1lo);
    cudaGetSymbolAddress((void**)&WHI,   g_WHI);   cudaGetSymbolAddress((void**)&WLO,   g_WLO);

    cudaFuncSetAttribute(attn_kernel, cudaFuncAttributeMaxDynamicSharedMemorySize,
                         ATTN_SMEM_FLOATS * 4);
    cudaFuncSetAttribute(gemm_cp<0>, cudaFuncAttributeMaxDynamicSharedMemorySize, GEMM_SMEM);
    cudaFuncSetAttribute(gemm_cp<1>, cudaFuncAttributeMaxDynamicSharedMemorySize, GEMM_SMEM);

    // ---- weight pre-split (once per launch) ----
    // slot indices (units of WSZ): see table at g_WHI
    const int widx[14]  = {2, 3, 4, 5,   9, 10, 11, 12, 13, 14,   15, 16, 17, 18};
    const size_t woff[14] = {0, 1*WSZ, 2*WSZ, 3*WSZ,
                             4*WSZ, 5*WSZ, 6*WSZ, 7*WSZ, 8*WSZ, 12*WSZ,
                             16*WSZ, 17*WSZ, 18*WSZ, 19*WSZ};
    const size_t wel[14]  = {1u<<20, 1u<<20, 1u<<20, 1u<<20,
                             1u<<20, 1u<<20, 1u<<20, 1u<<20, 1u<<22, 1u<<22,
                             1u<<20, 1u<<20, 1u<<20, 1u<<20};
    // mapping: widx -> l1_w1 @20*WSZ, l1_w2 @24*WSZ handled below
    for (int i = 0; i < 14; i++) {
        size_t off = woff[i];
        size_t elems = wel[i];
        if (i >= 10) { // l1 wq..wo at 16..19
            off = (size_t)(16 + (i - 10)) * WSZ;
            elems = 1u << 20;
        }
        int n4 = (int)(elems / 4);
        pack_split_kernel<<<(n4 + 255) / 256, 256>>>((const float*)d_in[widx[i]],
                                                     WHI + off, WLO + off, n4);
    }
    { // l1_w1, l1_w2, w_out
        int n4 = (1 << 22) / 4;
        pack_split_kernel<<<(n4 + 255) / 256, 256>>>((const float*)d_in[19], WHI + 20*WSZ, WLO + 20*WSZ, n4);
        pack_split_kernel<<<(n4 + 255) / 256, 256>>>((const float*)d_in[20], WHI + 24*WSZ, WLO + 24*WSZ, n4);
        int n4v = VOCAB_ * DIM_ / 4;
        pack_split_kernel<<<(n4v + 255) / 256, 256>>>(w_out, WHI + 28*WSZ, WLO + 28*WSZ, n4v);
    }

    WOffs lw[2];
    lw[0] = { 4*WSZ, 5*WSZ, 6*WSZ, 7*WSZ, 8*WSZ, 12*WSZ };
    lw[1] = { 16*WSZ, 17*WSZ, 18*WSZ, 19*WSZ, 20*WSZ, 24*WSZ };

    const int v4blocks = (int)(ACT_ELEMS / 4 + 255) / 256;

    // ---- embedding (packed only) ----
    embed_pack_kernel<<<v4blocks, 256>>>(x, emb, cXhi, cXlo);

    // ---- infini attention (memory==0 => combined = (1-sigmoid(gate))*local) ----
    launch_gemm(cXhi, cXlo, WHI + 0*WSZ, WLO + 0*WSZ, Q,  0, 0, ROWS_, DIM_, DIM_, 0);
    launch_gemm(cXhi, cXlo, WHI + 1*WSZ, WLO + 1*WSZ, Kb, 0, 0, ROWS_, DIM_, DIM_, 0);
    launch_gemm(cXhi, cXlo, WHI + 2*WSZ, WLO + 2*WSZ, V,  0, 0, ROWS_, DIM_, DIM_, 0);
    attn_kernel<<<dim3(SEQ_ / 64, B_ * HEADS_), 256, ATTN_SMEM_FLOATS * 4>>>(
        Q, Kb, V, cAThi, cATlo, gate, 1);
    launch_gemm(cAThi, cATlo, WHI + 3*WSZ, WLO + 3*WSZ, XENR, 0, 0, ROWS_, DIM_, DIM_, 0);

    bcast_init_kernel<<<v4blocks, 256>>>(init0, init1, S0, S1);

    // ---- HRM steps ----
    for (int step = 0; step < 8; step++) {
        bool u1 = ((step + 1) % 4 == 0);
        add3_pack_kernel<<<v4blocks, 256>>>(S0, XENR, S1, H0, cH0hi, cH0lo);
        if (u1) add3_pack_kernel<<<v4blocks, 256>>>(S1, XENR, S0, H1, cH1hi, cH1lo);
        for (int li = 0; li < (u1 ? 2 : 1); li++) {
            const WOffs& o = lw[li];
            uint32_t* hHi = li ? cH1hi : cH0hi;
            uint32_t* hLo = li ? cH1lo : cH0lo;
            float* Hres = li ? H1 : H0;
            float* OUT  = li ? S1 : S0;
            launch_gemm(hHi, hLo, WHI + o.wq, WLO + o.wq, Q,  0, 0, ROWS_, DIM_, DIM_, 0);
            launch_gemm(hHi, hLo, WHI + o.wk, WLO + o.wk, Kb, 0, 0, ROWS_, DIM_, DIM_, 0);
            launch_gemm(hHi, hLo, WHI + o.wv, WLO + o.wv, V,  0, 0, ROWS_, DIM_, DIM_, 0);
            attn_kernel<<<dim3(SEQ_ / 64, B_ * HEADS_), 256, ATTN_SMEM_FLOATS * 4>>>(
                Q, Kb, V, cAThi, cATlo, nullptr, 0);
            launch_gemm(cAThi, cATlo, WHI + o.wo, WLO + o.wo, T, 0, 0, ROWS_, DIM_, DIM_, 0);
            rmsnorm_add_kernel<1><<<ROWS_, 256>>>(Hres, T, G, cGhi, cGlo);
            launch_gemm(cGhi, cGlo, WHI + o.w1, WLO + o.w1, 0, cFFhi, cFFlo, ROWS_, FF_, DIM_, 1);
            launch_gemm(cFFhi, cFFlo, WHI + o.w2, WLO + o.w2, T, 0, 0, ROWS_, DIM_, FF_, 0);
            rmsnorm_add_kernel<0><<<ROWS_, 256>>>(G, T, OUT, 0, 0);
        }
    }

    // ---- outputs ----
    pack_split_kernel<<<v4blocks, 256>>>(S1, cS1hi, cS1lo, (int)(ACT_ELEMS / 4));
    launch_gemm(cS1hi, cS1lo, WHI + 28*WSZ, WLO + 28*WSZ, out, 0, 0, ROWS_, VOCAB_, DIM_, 0);
    mean_kernel<<<(B_ * DIM_ + 255) / 256, 256>>>(S1, MEAN);
    qhead_kernel<<<1, 256>>>(MEAN, w_qhead, out + (size_t)ROWS_ * VOCAB_);
}

// round 7
// speedup vs baseline: 2.0513x; 1.1808x over previous
#include <cuda_runtime.h>
#include <cuda_bf16.h>
#include <math.h>
#include <stdint.h>

#define B_    4
#define SEQ_  1024
#define DIM_  1024
#define HEADS_ 16
#define HD_   64
#define VOCAB_ 32000
#define FF_   4096

#define ROWS_ (B_*SEQ_)                    // 4096
#define ACT_ELEMS ((size_t)ROWS_*DIM_)     // 4M floats
#define ACT_PAIRS (ACT_ELEMS/2)            // 2M uint32

// ------------------------- fp32 scratch -------------------------
__device__ float g_XENR[ACT_ELEMS];
__device__ float g_S0  [ACT_ELEMS];
__device__ float g_S1  [ACT_ELEMS];
__device__ float g_H0  [ACT_ELEMS];
__device__ float g_H1  [ACT_ELEMS];
__device__ float g_Q   [ACT_ELEMS];
__device__ float g_K   [ACT_ELEMS];
__device__ float g_V   [ACT_ELEMS];
__device__ float g_T   [ACT_ELEMS];
__device__ float g_G   [ACT_ELEMS];
__device__ float g_MEAN[B_*DIM_];

// ------------------------- packed bf16 hi/lo scratch (uint32 = bf16x2) -------------------------
__device__ __align__(16) uint32_t g_cXhi [ACT_PAIRS],     g_cXlo [ACT_PAIRS];
__device__ __align__(16) uint32_t g_cH0hi[ACT_PAIRS],     g_cH0lo[ACT_PAIRS];
__device__ __align__(16) uint32_t g_cH1hi[ACT_PAIRS],     g_cH1lo[ACT_PAIRS];
__device__ __align__(16) uint32_t g_cAThi[ACT_PAIRS],     g_cATlo[ACT_PAIRS];
__device__ __align__(16) uint32_t g_cGhi [ACT_PAIRS],     g_cGlo [ACT_PAIRS];
__device__ __align__(16) uint32_t g_cFFhi[(size_t)ROWS_*FF_/2], g_cFFlo[(size_t)ROWS_*FF_/2];
__device__ __align__(16) uint32_t g_cS1hi[ACT_PAIRS],     g_cS1lo[ACT_PAIRS];

// weights, packed: slots of 0.5M uint32 (= one 1024x1024 matrix)
#define WSZ 524288ull
#define W_TOTAL 31064064ull   // 28*WSZ + 32000*1024/2
__device__ __align__(16) uint32_t g_WHI[W_TOTAL];
__device__ __align__(16) uint32_t g_WLO[W_TOTAL];
// slot offsets (units of WSZ): awq0 awk1 awv2 awo3 | l0: q4 k5 v6 o7 w1@8(x4) w2@12(x4)
// l1: q16 k17 v18 o19 w1@20 w2@24 | w_out@28

// ------------------------------ helpers ------------------------------
__device__ __forceinline__ float gelu_tanh(float x) {
    float x3 = x * x * x;
    return 0.5f * x * (1.0f + tanhf(0.79788456080286535588f * (x + 0.044715f * x3)));
}
__device__ __forceinline__ uint32_t pack_bf16(__nv_bfloat16 lo, __nv_bfloat16 hi) {
    __nv_bfloat162 p; p.x = lo; p.y = hi;
    return *reinterpret_cast<uint32_t*>(&p);
}
__device__ __forceinline__ void split2(float v0, float v1, uint32_t& hi, uint32_t& lo) {
    __nv_bfloat16 h0 = __float2bfloat16_rn(v0), h1 = __float2bfloat16_rn(v1);
    hi = pack_bf16(h0, h1);
    lo = pack_bf16(__float2bfloat16_rn(v0 - __bfloat162float(h0)),
                   __float2bfloat16_rn(v1 - __bfloat162float(h1)));
}
__device__ __forceinline__ void mma_bf16(float c[4], const uint32_t a[4], const uint32_t b[2]) {
    asm volatile(
        "mma.sync.aligned.m16n8k16.row.col.f32.bf16.bf16.f32 "
        "{%0,%1,%2,%3}, {%4,%5,%6,%7}, {%8,%9}, {%0,%1,%2,%3};"
        : "+f"(c[0]), "+f"(c[1]), "+f"(c[2]), "+f"(c[3])
        : "r"(a[0]), "r"(a[1]), "r"(a[2]), "r"(a[3]), "r"(b[0]), "r"(b[1]));
}
__device__ __forceinline__ void ldsm_x4(uint32_t r[4], uint32_t addr) {
    asm volatile("ldmatrix.sync.aligned.m8n8.x4.shared.b16 {%0,%1,%2,%3}, [%4];"
                 : "=r"(r[0]), "=r"(r[1]), "=r"(r[2]), "=r"(r[3]) : "r"(addr));
}
__device__ __forceinline__ void ldsm_x2(uint32_t r[2], uint32_t addr) {
    asm volatile("ldmatrix.sync.aligned.m8n8.x2.shared.b16 {%0,%1}, [%2];"
                 : "=r"(r[0]), "=r"(r[1]) : "r"(addr));
}
__device__ __forceinline__ void cp16(uint32_t saddr, const void* g) {
    asm volatile("cp.async.cg.shared.global [%0], [%1], 16;" :: "r"(saddr), "l"(g));
}

// ------------------------------ GEMM (packed operands, cp.async, ldmatrix) ------------------------------
// C[M,N] = A[M,K] @ B[N,K]^T, operands pre-split into packed bf16 hi/lo (uint32 = 2 K-elems).
// acc += hi*lo + lo*hi + hi*hi. 128x128 tile, K-chunk 16, 256 threads, 3-stage cp.async.
// __launch_bounds__(256,2): cap regs at 128 so 2 CTAs co-reside per SM (hide MMA/LDSM latency).
// MODE 0: fp32 out to C.  MODE 1: gelu + split to Chi/Clo (no fp32 out).
#define RST 12                    // smem row stride in uint32 (conflict-free)
#define ARR_B 6144                // bytes per array: 128*12*4
#define STAGE_B 24576             // 4 arrays
#define GEMM_SMEM (3*STAGE_B)     // 73728

template<int MODE>
__global__ __launch_bounds__(256, 2)
void gemm_cp(const uint32_t* __restrict__ Ahi, const uint32_t* __restrict__ Alo,
             const uint32_t* __restrict__ Bhi, const uint32_t* __restrict__ Blo,
             float* __restrict__ C, uint32_t* __restrict__ Chi, uint32_t* __restrict__ Clo,
             int M, int N, int K)
{
    extern __shared__ uint32_t smem[];
    const uint32_t smem_base = (uint32_t)__cvta_generic_to_shared(smem);

    const int K2 = K >> 1;
    const int bm = blockIdx.y * 128;
    const int bn = blockIdx.x * 128;
    const int tid = threadIdx.x;

    // staging: row = tid>>1 (0..127), half = tid&1 -> 16B each of 32B row-chunk
    const int row = tid >> 1, half = tid & 1;
    const uint32_t* pAhi = Ahi + (size_t)(bm + row) * K2 + half * 4;
    const uint32_t* pAlo = Alo + (size_t)(bm + row) * K2 + half * 4;
    const uint32_t* pBhi = Bhi + (size_t)(bn + row) * K2 + half * 4;
    const uint32_t* pBlo = Blo + (size_t)(bn + row) * K2 + half * 4;
    const uint32_t dst0 = smem_base + (uint32_t)((row * RST + half * 4) * 4);

    const int wid = tid >> 5, lane = tid & 31;
    const int warp_m = (wid & 1) * 64;
    const int warp_n = (wid >> 1) * 32;
    const int g = lane >> 2, t = lane & 3;

    // ldmatrix lane addresses (byte offsets within a stage)
    uint32_t aoff[4], boff[4];
    {
        int arow = lane & 15, acol = (lane >> 4) * 4;
        int brow = lane & 7,  bcol = ((lane >> 3) & 1) * 4;
#pragma unroll
        for (int fm = 0; fm < 4; fm++)
            aoff[fm] = (uint32_t)(((warp_m + fm * 16 + arow) * RST + acol) * 4);
#pragma unroll
        for (int fn = 0; fn < 4; fn++)
            boff[fn] = (uint32_t)(2 * ARR_B + ((warp_n + fn * 8 + brow) * RST + bcol) * 4);
    }

    float acc[4][4][4];
#pragma unroll
    for (int i = 0; i < 4; i++)
#pragma unroll
        for (int j = 0; j < 4; j++)
#pragma unroll
            for (int r = 0; r < 4; r++) acc[i][j][r] = 0.0f;

    const int nch = K >> 4;

    auto issue = [&](int kc, int s) {
        uint32_t d = dst0 + (uint32_t)(s * STAGE_B);
        cp16(d,             pAhi + (size_t)kc * 8);
        cp16(d + ARR_B,     pAlo + (size_t)kc * 8);
        cp16(d + 2 * ARR_B, pBhi + (size_t)kc * 8);
        cp16(d + 3 * ARR_B, pBlo + (size_t)kc * 8);
        asm volatile("cp.async.commit_group;");
    };

    issue(0, 0);
    if (nch > 1) issue(1, 1);

    for (int kc = 0; kc < nch; kc++) {
        asm volatile("cp.async.wait_group 1;");
        __syncthreads();
        if (kc + 2 < nch) issue(kc + 2, (kc + 2) % 3);

        const uint32_t sb = smem_base + (uint32_t)((kc % 3) * STAGE_B);
        // B fragments resident for the whole chunk (16 regs)
        uint32_t bhi[4][2], blo[4][2];
#pragma unroll
        for (int fn = 0; fn < 4; fn++) {
            ldsm_x2(bhi[fn], sb + boff[fn]);
            ldsm_x2(blo[fn], sb + boff[fn] + ARR_B);
        }
        // A fragments loaded per-fm (8 regs live), then 12 MMAs immediately
#pragma unroll
        for (int fm = 0; fm < 4; fm++) {
            uint32_t ahi[4], alo[4];
            ldsm_x4(ahi, sb + aoff[fm]);
            ldsm_x4(alo, sb + aoff[fm] + ARR_B);
#pragma unroll
            for (int fn = 0; fn < 4; fn++) {
                mma_bf16(acc[fm][fn], ahi, blo[fn]);
                mma_bf16(acc[fm][fn], alo, bhi[fn]);
                mma_bf16(acc[fm][fn], ahi, bhi[fn]);
            }
        }
    }

    // epilogue: c0(row g, col 2t), c1(g,2t+1), c2(g+8,2t), c3(g+8,2t+1)
#pragma unroll
    for (int fm = 0; fm < 4; fm++) {
#pragma unroll
        for (int fn = 0; fn < 4; fn++) {
            int row0 = bm + warp_m + fm * 16 + g;
            int col  = bn + warp_n + fn * 8 + 2 * t;
            float v0 = acc[fm][fn][0], v1 = acc[fm][fn][1];
            float v2 = acc[fm][fn][2], v3 = acc[fm][fn][3];
            if (MODE == 1) {
                v0 = gelu_tanh(v0); v1 = gelu_tanh(v1);
                v2 = gelu_tanh(v2); v3 = gelu_tanh(v3);
                int N2 = N >> 1;
                int cp0 = col >> 1;
                uint32_t h, l;
                split2(v0, v1, h, l);
                Chi[(size_t)row0 * N2 + cp0] = h;  Clo[(size_t)row0 * N2 + cp0] = l;
                split2(v2, v3, h, l);
                Chi[(size_t)(row0 + 8) * N2 + cp0] = h;  Clo[(size_t)(row0 + 8) * N2 + cp0] = l;
            } else {
                *(float2*)(C + (size_t)row0 * N + col)       = make_float2(v0, v1);
                *(float2*)(C + (size_t)(row0 + 8) * N + col) = make_float2(v2, v3);
            }
        }
    }
}

// ------------------------------ attention (fp32 in, packed hi/lo out) ------------------------------
#define ATTN_SMEM_FLOATS (64*65*3 + 64*64 + 64*3)
__global__ __launch_bounds__(256)
void attn_kernel(const float* __restrict__ Q, const float* __restrict__ K,
                 const float* __restrict__ V,
                 uint32_t* __restrict__ Ohi, uint32_t* __restrict__ Olo,
                 const float* __restrict__ gate, int causal)
{
    extern __shared__ float sm[];
    float* Qs   = sm;
    float* Ks   = Qs + 64 * 65;
    float* Ss   = Ks + 64 * 65;
    float* Vs   = Ss + 64 * 65;
    float* mrow = Vs + 64 * 64;
    float* lrow = mrow + 64;
    float* arow = lrow + 64;

    const int bh = blockIdx.y;
    const int b  = bh / HEADS_;
    const int h  = bh % HEADS_;
    const int q0 = blockIdx.x * 64;
    const int tid = threadIdx.x;

    const float* Qbase = Q + ((size_t)(b * SEQ_ + q0) * HEADS_ + h) * HD_;

    for (int i = tid; i < 1024; i += 256) {
        int r = i >> 4, c4 = (i & 15) << 2;
        float4 v = *(const float4*)(Qbase + (size_t)r * DIM_ + c4);
        Qs[r * 65 + c4 + 0] = v.x; Qs[r * 65 + c4 + 1] = v.y;
        Qs[r * 65 + c4 + 2] = v.z; Qs[r * 65 + c4 + 3] = v.w;
    }
    if (tid < 64) { mrow[tid] = -3.0e38f; lrow[tid] = 0.0f; }

    const int ty = tid >> 4, tx = tid & 15;
    float acc[4][4];
#pragma unroll
    for (int i = 0; i < 4; i++)
#pragma unroll
        for (int j = 0; j < 4; j++) acc[i][j] = 0.0f;

    const int nkb = causal ? (q0 / 64 + 1) : (SEQ_ / 64);

    for (int kb = 0; kb < nkb; kb++) {
        const int k0 = kb * 64;
        __syncthreads();
        const float* Kbase = K + ((size_t)(b * SEQ_ + k0) * HEADS_ + h) * HD_;
        const float* Vbase = V + ((size_t)(b * SEQ_ + k0) * HEADS_ + h) * HD_;
        for (int i = tid; i < 1024; i += 256) {
            int r = i >> 4, c4 = (i & 15) << 2;
            float4 kv = *(const float4*)(Kbase + (size_t)r * DIM_ + c4);
            Ks[r * 65 + c4 + 0] = kv.x; Ks[r * 65 + c4 + 1] = kv.y;
            Ks[r * 65 + c4 + 2] = kv.z; Ks[r * 65 + c4 + 3] = kv.w;
            float4 vv = *(const float4*)(Vbase + (size_t)r * DIM_ + c4);
            *(float4*)&Vs[r * 64 + c4] = vv;
        }
        __syncthreads();

        float s[4][4];
#pragma unroll
        for (int i = 0; i < 4; i++)
#pragma unroll
            for (int j = 0; j < 4; j++) s[i][j] = 0.0f;
#pragma unroll 8
        for (int d = 0; d < 64; d++) {
            float a0 = Qs[(ty * 4 + 0) * 65 + d];
            float a1 = Qs[(ty * 4 + 1) * 65 + d];
            float a2 = Qs[(ty * 4 + 2) * 65 + d];
            float a3 = Qs[(ty * 4 + 3) * 65 + d];
            float b0 = Ks[(tx * 4 + 0) * 65 + d];
            float b1 = Ks[(tx * 4 + 1) * 65 + d];
            float b2 = Ks[(tx * 4 + 2) * 65 + d];
            float b3 = Ks[(tx * 4 + 3) * 65 + d];
            s[0][0] = fmaf(a0, b0, s[0][0]); s[0][1] = fmaf(a0, b1, s[0][1]);
            s[0][2] = fmaf(a0, b2, s[0][2]); s[0][3] = fmaf(a0, b3, s[0][3]);
            s[1][0] = fmaf(a1, b0, s[1][0]); s[1][1] = fmaf(a1, b1, s[1][1]);
            s[1][2] = fmaf(a1, b2, s[1][2]); s[1][3] = fmaf(a1, b3, s[1][3]);
            s[2][0] = fmaf(a2, b0, s[2][0]); s[2][1] = fmaf(a2, b1, s[2][1]);
            s[2][2] = fmaf(a2, b2, s[2][2]); s[2][3] = fmaf(a2, b3, s[2][3]);
            s[3][0] = fmaf(a3, b0, s[3][0]); s[3][1] = fmaf(a3, b1, s[3][1]);
            s[3][2] = fmaf(a3, b2, s[3][2]); s[3][3] = fmaf(a3, b3, s[3][3]);
        }
#pragma unroll
        for (int i = 0; i < 4; i++)
#pragma unroll
            for (int j = 0; j < 4; j++) {
                float val = s[i][j] * 0.125f;
                if (causal && (k0 + tx * 4 + j > q0 + ty * 4 + i)) val = -3.0e38f;
                Ss[(ty * 4 + i) * 65 + tx * 4 + j] = val;
            }
        __syncthreads();

        {
            int row = tid >> 2, q = tid & 3;
            float mx = -3.0e38f;
            for (int c = q; c < 64; c += 4) mx = fmaxf(mx, Ss[row * 65 + c]);
            mx = fmaxf(mx, __shfl_xor_sync(0xffffffffu, mx, 1));
            mx = fmaxf(mx, __shfl_xor_sync(0xffffffffu, mx, 2));
            float mold = mrow[row];
            float mnew = fmaxf(mold, mx);
            float al = __expf(mold - mnew);
            float ls = 0.0f;
            for (int c = q; c < 64; c += 4) {
                float p = __expf(Ss[row * 65 + c] - mnew);
                Ss[row * 65 + c] = p;
                ls += p;
            }
            ls += __shfl_xor_sync(0xffffffffu, ls, 1);
            ls += __shfl_xor_sync(0xffffffffu, ls, 2);
            if (q == 0) {
                mrow[row] = mnew;
                lrow[row] = lrow[row] * al + ls;
                arow[row] = al;
            }
        }
        __syncthreads();

        float alv[4];
#pragma unroll
        for (int i = 0; i < 4; i++) alv[i] = arow[ty * 4 + i];
#pragma unroll
        for (int i = 0; i < 4; i++)
#pragma unroll
            for (int j = 0; j < 4; j++) acc[i][j] *= alv[i];
#pragma unroll 8
        for (int jj = 0; jj < 64; jj++) {
            float p0 = Ss[(ty * 4 + 0) * 65 + jj];
            float p1 = Ss[(ty * 4 + 1) * 65 + jj];
            float p2 = Ss[(ty * 4 + 2) * 65 + jj];
            float p3 = Ss[(ty * 4 + 3) * 65 + jj];
            float v0 = Vs[jj * 64 + tx * 4 + 0];
            float v1 = Vs[jj * 64 + tx * 4 + 1];
            float v2 = Vs[jj * 64 + tx * 4 + 2];
            float v3 = Vs[jj * 64 + tx * 4 + 3];
            acc[0][0] = fmaf(p0, v0, acc[0][0]); acc[0][1] = fmaf(p0, v1, acc[0][1]);
            acc[0][2] = fmaf(p0, v2, acc[0][2]); acc[0][3] = fmaf(p0, v3, acc[0][3]);
            acc[1][0] = fmaf(p1, v0, acc[1][0]); acc[1][1] = fmaf(p1, v1, acc[1][1]);
            acc[1][2] = fmaf(p1, v2, acc[1][2]); acc[1][3] = fmaf(p1, v3, acc[1][3]);
            acc[2][0] = fmaf(p2, v0, acc[2][0]); acc[2][1] = fmaf(p2, v1, acc[2][1]);
            acc[2][2] = fmaf(p2, v2, acc[2][2]); acc[2][3] = fmaf(p2, v3, acc[2][3]);
            acc[3][0] = fmaf(p3, v0, acc[3][0]); acc[3][1] = fmaf(p3, v1, acc[3][1]);
            acc[3][2] = fmaf(p3, v2, acc[3][2]); acc[3][3] = fmaf(p3, v3, acc[3][3]);
        }
    }
    __syncthreads();

    float gmul = 1.0f;
    if (gate != nullptr) gmul = 1.0f - 1.0f / (1.0f + __expf(-gate[h]));

#pragma unroll
    for (int i = 0; i < 4; i++) {
        int rg = q0 + ty * 4 + i;
        float inv = gmul / lrow[ty * 4 + i];
        int base = (((b * SEQ_ + rg) * HEADS_ + h) * HD_ + tx * 4) >> 1;
        uint32_t h0, l0, h1, l1;
        split2(acc[i][0] * inv, acc[i][1] * inv, h0, l0);
        split2(acc[i][2] * inv, acc[i][3] * inv, h1, l1);
        Ohi[base] = h0; Ohi[base + 1] = h1;
        Olo[base] = l0; Olo[base + 1] = l1;
    }
}

// ------------------------------ elementwise ------------------------------
// generic fp32 -> packed hi/lo (used for weights and final S1)
__global__ void pack_split_kernel(const float* __restrict__ in,
                                  uint32_t* __restrict__ hi, uint32_t* __restrict__ lo,
                                  int n4)
{
    int i = blockIdx.x * blockDim.x + threadIdx.x;
    if (i >= n4) return;
    float4 v = ((const float4*)in)[i];
    uint32_t h0, l0, h1, l1;
    split2(v.x, v.y, h0, l0);
    split2(v.z, v.w, h1, l1);
    hi[2 * i] = h0; hi[2 * i + 1] = h1;
    lo[2 * i] = l0; lo[2 * i + 1] = l1;
}

__global__ void embed_pack_kernel(const int* __restrict__ x, const float* __restrict__ emb,
                                  uint32_t* __restrict__ hi, uint32_t* __restrict__ lo)
{
    int i = blockIdx.x * blockDim.x + threadIdx.x;
    if (i >= (int)(ACT_ELEMS / 4)) return;
    int row = i >> 8, c4 = i & 255;
    int tok = x[row];
    float4 v = ((const float4*)(emb + (size_t)tok * DIM_))[c4];
    uint32_t h0, l0, h1, l1;
    split2(v.x, v.y, h0, l0);
    split2(v.z, v.w, h1, l1);
    hi[2 * i] = h0; hi[2 * i + 1] = h1;
    lo[2 * i] = l0; lo[2 * i + 1] = l1;
}

__global__ void bcast_init_kernel(const float* __restrict__ i0, const float* __restrict__ i1,
                                  float* __restrict__ S0, float* __restrict__ S1)
{
    int i = blockIdx.x * blockDim.x + threadIdx.x;
    if (i >= (int)(ACT_ELEMS / 4)) return;
    int src = i & (int)(SEQ_ * DIM_ / 4 - 1);
    ((float4*)S0)[i] = ((const float4*)i0)[src];
    ((float4*)S1)[i] = ((const float4*)i1)[src];
}

__global__ void add3_pack_kernel(const float* __restrict__ a, const float* __restrict__ b,
                                 const float* __restrict__ c, float* __restrict__ o,
                                 uint32_t* __restrict__ hi, uint32_t* __restrict__ lo)
{
    int i = blockIdx.x * blockDim.x + threadIdx.x;
    if (i >= (int)(ACT_ELEMS / 4)) return;
    float4 va = ((const float4*)a)[i];
    float4 vb = ((const float4*)b)[i];
    float4 vc = ((const float4*)c)[i];
    float4 s = make_float4(va.x + vb.x + vc.x, va.y + vb.y + vc.y,
                           va.z + vb.z + vc.z, va.w + vb.w + vc.w);
    ((float4*)o)[i] = s;
    uint32_t h0, l0, h1, l1;
    split2(s.x, s.y, h0, l0);
    split2(s.z, s.w, h1, l1);
    hi[2 * i] = h0; hi[2 * i + 1] = h1;
    lo[2 * i] = l0; lo[2 * i + 1] = l1;
}

template<int PACK>
__global__ __launch_bounds__(256)
void rmsnorm_add_kernel(const float* __restrict__ a, const float* __restrict__ b,
                        float* __restrict__ o,
                        uint32_t* __restrict__ hi, uint32_t* __restrict__ lo)
{
    int row = blockIdx.x;
    int tid = threadIdx.x;
    const float4* a4 = (const float4*)(a + (size_t)row * DIM_);
    const float4* b4 = (const float4*)(b + (size_t)row * DIM_);
    float4 va = a4[tid], vb = b4[tid];
    float4 s = make_float4(va.x + vb.x, va.y + vb.y, va.z + vb.z, va.w + vb.w);
    float ss = s.x * s.x + s.y * s.y + s.z * s.z + s.w * s.w;
#pragma unroll
    for (int off = 16; off > 0; off >>= 1) ss += __shfl_xor_sync(0xffffffffu, ss, off);
    __shared__ float red[8];
    __shared__ float scale_s;
    if ((tid & 31) == 0) red[tid >> 5] = ss;
    __syncthreads();
    if (tid == 0) {
        float t = 0.0f;
#pragma unroll
        for (int w = 0; w < 8; w++) t += red[w];
        scale_s = rsqrtf(t * (1.0f / DIM_) + 1e-6f);
    }
    __syncthreads();
    float sc = scale_s;
    float4 r = make_float4(s.x * sc, s.y * sc, s.z * sc, s.w * sc);
    ((float4*)(o + (size_t)row * DIM_))[tid] = r;
    if (PACK) {
        uint32_t h0, l0, h1, l1;
        split2(r.x, r.y, h0, l0);
        split2(r.z, r.w, h1, l1);
        size_t pidx = (size_t)row * (DIM_ / 2) + tid * 2;
        hi[pidx] = h0; hi[pidx + 1] = h1;
        lo[pidx] = l0; lo[pidx + 1] = l1;
    }
}

__global__ void mean_kernel(const float* __restrict__ S, float* __restrict__ M)
{
    int idx = blockIdx.x * blockDim.x + threadIdx.x;
    if (idx >= B_ * DIM_) return;
    int b = idx >> 10, d = idx & (DIM_ - 1);
    const float* p = S + (size_t)b * SEQ_ * DIM_ + d;
    float s = 0.0f;
    for (int t = 0; t < SEQ_; t++) s += p[(size_t)t * DIM_];
    M[idx] = s * (1.0f / SEQ_);
}

__global__ void qhead_kernel(const float* __restrict__ M, const float* __restrict__ W,
                             float* __restrict__ out)
{
    int w = threadIdx.x >> 5, lane = threadIdx.x & 31;
    int b = w >> 1, o = w & 1;
    const float* m  = M + (size_t)b * DIM_;
    const float* ww = W + (size_t)o * DIM_;
    float s = 0.0f;
    for (int k = lane; k < DIM_; k += 32) s += m[k] * ww[k];
#pragma unroll
    for (int off = 16; off > 0; off >>= 1) s += __shfl_xor_sync(0xffffffffu, s, off);
    if (lane == 0) out[b * 2 + o] = 1.0f / (1.0f + __expf(-s));
}

// ------------------------------ host orchestration ------------------------------
static void launch_gemm(const uint32_t* Ahi, const uint32_t* Alo,
                        const uint32_t* Bhi, const uint32_t* Blo,
                        float* C, uint32_t* Chi, uint32_t* Clo,
                        int M, int N, int K, int mode)
{
    dim3 grid(N / 128, M / 128);
    if (mode) gemm_cp<1><<<grid, 256, GEMM_SMEM>>>(Ahi, Alo, Bhi, Blo, C, Chi, Clo, M, N, K);
    else      gemm_cp<0><<<grid, 256, GEMM_SMEM>>>(Ahi, Alo, Bhi, Blo, C, Chi, Clo, M, N, K);
}

struct WOffs { size_t wq, wk, wv, wo, w1, w2; };

extern "C" void kernel_launch(void* const* d_in, const int* in_sizes, int n_in,
                              void* d_out, int out_size)
{
    (void)in_sizes; (void)n_in; (void)out_size;
    const int*   x     = (const int*)  d_in[0];
    const float* emb   = (const float*)d_in[1];
    const float* gate  = (const float*)d_in[6];
    const float* init0 = (const float*)d_in[7];
    const float* init1 = (const float*)d_in[8];
    const float* w_out   = (const float*)d_in[21];
    const float* w_qhead = (const float*)d_in[22];
    float* out = (float*)d_out;

    float *XENR, *S0, *S1, *H0, *H1, *Q, *Kb, *V, *T, *G, *MEAN;
    cudaGetSymbolAddress((void**)&XENR, g_XENR);
    cudaGetSymbolAddress((void**)&S0,   g_S0);
    cudaGetSymbolAddress((void**)&S1,   g_S1);
    cudaGetSymbolAddress((void**)&H0,   g_H0);
    cudaGetSymbolAddress((void**)&H1,   g_H1);
    cudaGetSymbolAddress((void**)&Q,    g_Q);
    cudaGetSymbolAddress((void**)&Kb,   g_K);
    cudaGetSymbolAddress((void**)&V,    g_V);
    cudaGetSymbolAddress((void**)&T,    g_T);
    cudaGetSymbolAddress((void**)&G,    g_G);
    cudaGetSymbolAddress((void**)&MEAN, g_MEAN);

    uint32_t *cXhi, *cXlo, *cH0hi, *cH0lo, *cH1hi, *cH1lo, *cAThi, *cATlo;
    uint32_t *cGhi, *cGlo, *cFFhi, *cFFlo, *cS1hi, *cS1lo, *WHI, *WLO;
    cudaGetSymbolAddress((void**)&cXhi,  g_cXhi);  cudaGetSymbolAddress((void**)&cXlo,  g_cXlo);
    cudaGetSymbolAddress((void**)&cH0hi, g_cH0hi); cudaGetSymbolAddress((void**)&cH0lo, g_cH0lo);
    cudaGetSymbolAddress((void**)&cH1hi, g_cH1hi); cudaGetSymbolAddress((void**)&cH1lo, g_cH1lo);
    cudaGetSymbolAddress((void**)&cAThi, g_cAThi); cudaGetSymbolAddress((void**)&cATlo, g_cATlo);
    cudaGetSymbolAddress((void**)&cGhi,  g_cGhi);  cudaGetSymbolAddress((void**)&cGlo,  g_cGlo);
    cudaGetSymbolAddress((void**)&cFFhi, g_cFFhi); cudaGetSymbolAddress((void**)&cFFlo, g_cFFlo);
    cudaGetSymbolAddress((void**)&cS1hi, g_cS1hi); cudaGetSymbolAddress((void**)&cS1lo, g_cS1lo);
    cudaGetSymbolAddress((void**)&WHI,   g_WHI);   cudaGetSymbolAddress((void**)&WLO,   g_WLO);

    cudaFuncSetAttribute(attn_kernel, cudaFuncAttributeMaxDynamicSharedMemorySize,
                         ATTN_SMEM_FLOATS * 4);
    cudaFuncSetAttribute(gemm_cp<0>, cudaFuncAttributeMaxDynamicSharedMemorySize, GEMM_SMEM);
    cudaFuncSetAttribute(gemm_cp<1>, cudaFuncAttributeMaxDynamicSharedMemorySize, GEMM_SMEM);

    // ---- weight pre-split (once per launch) ----
    const int widx[14]  = {2, 3, 4, 5,   9, 10, 11, 12, 13, 14,   15, 16, 17, 18};
    const size_t woff[14] = {0, 1*WSZ, 2*WSZ, 3*WSZ,
                             4*WSZ, 5*WSZ, 6*WSZ, 7*WSZ, 8*WSZ, 12*WSZ,
                             16*WSZ, 17*WSZ, 18*WSZ, 19*WSZ};
    const size_t wel[14]  = {1u<<20, 1u<<20, 1u<<20, 1u<<20,
                             1u<<20, 1u<<20, 1u<<20, 1u<<20, 1u<<22, 1u<<22,
                             1u<<20, 1u<<20, 1u<<20, 1u<<20};
    for (int i = 0; i < 14; i++) {
        size_t off = woff[i];
        size_t elems = wel[i];
        if (i >= 10) {
            off = (size_t)(16 + (i - 10)) * WSZ;
            elems = 1u << 20;
        }
        int n4 = (int)(elems / 4);
        pack_split_kernel<<<(n4 + 255) / 256, 256>>>((const float*)d_in[widx[i]],
                                                     WHI + off, WLO + off, n4);
    }
    {
        int n4 = (1 << 22) / 4;
        pack_split_kernel<<<(n4 + 255) / 256, 256>>>((const float*)d_in[19], WHI + 20*WSZ, WLO + 20*WSZ, n4);
        pack_split_kernel<<<(n4 + 255) / 256, 256>>>((const float*)d_in[20], WHI + 24*WSZ, WLO + 24*WSZ, n4);
        int n4v = VOCAB_ * DIM_ / 4;
        pack_split_kernel<<<(n4v + 255) / 256, 256>>>(w_out, WHI + 28*WSZ, WLO + 28*WSZ, n4v);
    }

    WOffs lw[2];
    lw[0] = { 4*WSZ, 5*WSZ, 6*WSZ, 7*WSZ, 8*WSZ, 12*WSZ };
    lw[1] = { 16*WSZ, 17*WSZ, 18*WSZ, 19*WSZ, 20*WSZ, 24*WSZ };

    const int v4blocks = (int)(ACT_ELEMS / 4 + 255) / 256;

    // ---- embedding (packed only) ----
    embed_pack_kernel<<<v4blocks, 256>>>(x, emb, cXhi, cXlo);

    // ---- infini attention (memory==0 => combined = (1-sigmoid(gate))*local) ----
    launch_gemm(cXhi, cXlo, WHI + 0*WSZ, WLO + 0*WSZ, Q,  0, 0, ROWS_, DIM_, DIM_, 0);
    launch_gemm(cXhi, cXlo, WHI + 1*WSZ, WLO + 1*WSZ, Kb, 0, 0, ROWS_, DIM_, DIM_, 0);
    launch_gemm(cXhi, cXlo, WHI + 2*WSZ, WLO + 2*WSZ, V,  0, 0, ROWS_, DIM_, DIM_, 0);
    attn_kernel<<<dim3(SEQ_ / 64, B_ * HEADS_), 256, ATTN_SMEM_FLOATS * 4>>>(
        Q, Kb, V, cAThi, cATlo, gate, 1);
    launch_gemm(cAThi, cATlo, WHI + 3*WSZ, WLO + 3*WSZ, XENR, 0, 0, ROWS_, DIM_, DIM_, 0);

    bcast_init_kernel<<<v4blocks, 256>>>(init0, init1, S0, S1);

    // ---- HRM steps ----
    for (int step = 0; step < 8; step++) {
        bool u1 = ((step + 1) % 4 == 0);
        add3_pack_kernel<<<v4blocks, 256>>>(S0, XENR, S1, H0, cH0hi, cH0lo);
        if (u1) add3_pack_kernel<<<v4blocks, 256>>>(S1, XENR, S0, H1, cH1hi, cH1lo);
        for (int li = 0; li < (u1 ? 2 : 1); li++) {
            const WOffs& o = lw[li];
            uint32_t* hHi = li ? cH1hi : cH0hi;
            uint32_t* hLo = li ? cH1lo : cH0lo;
            float* Hres = li ? H1 : H0;
            float* OUT  = li ? S1 : S0;
            launch_gemm(hHi, hLo, WHI + o.wq, WLO + o.wq, Q,  0, 0, ROWS_, DIM_, DIM_, 0);
            launch_gemm(hHi, hLo, WHI + o.wk, WLO + o.wk, Kb, 0, 0, ROWS_, DIM_, DIM_, 0);
            launch_gemm(hHi, hLo, WHI + o.wv, WLO + o.wv, V,  0, 0, ROWS_, DIM_, DIM_, 0);
            attn_kernel<<<dim3(SEQ_ / 64, B_ * HEADS_), 256, ATTN_SMEM_FLOATS * 4>>>(
                Q, Kb, V, cAThi, cATlo, nullptr, 0);
            launch_gemm(cAThi, cATlo, WHI + o.wo, WLO + o.wo, T, 0, 0, ROWS_, DIM_, DIM_, 0);
            rmsnorm_add_kernel<1><<<ROWS_, 256>>>(Hres, T, G, cGhi, cGlo);
            launch_gemm(cGhi, cGlo, WHI + o.w1, WLO + o.w1, 0, cFFhi, cFFlo, ROWS_, FF_, DIM_, 1);
            launch_gemm(cFFhi, cFFlo, WHI + o.w2, WLO + o.w2, T, 0, 0, ROWS_, DIM_, FF_, 0);
            rmsnorm_add_kernel<0><<<ROWS_, 256>>>(G, T, OUT, 0, 0);
        }
    }

    // ---- outputs ----
    pack_split_kernel<<<v4blocks, 256>>>(S1, cS1hi, cS1lo, (int)(ACT_ELEMS / 4));
    launch_gemm(cS1hi, cS1lo, WHI + 28*WSZ, WLO + 28*WSZ, out, 0, 0, ROWS_, VOCAB_, DIM_, 0);
    mean_kernel<<<(B_ * DIM_ + 255) / 256, 256>>>(S1, MEAN);
    qhead_kernel<<<1, 256>>>(MEAN, w_qhead, out + (size_t)ROWS_ * VOCAB_);
}

// round 9
// speedup vs baseline: 2.6024x; 1.2686x over previous
#include <cuda_runtime.h>
#include <cuda_bf16.h>
#include <math.h>
#include <stdint.h>

#define B_    4
#define SEQ_  1024
#define DIM_  1024
#define HEADS_ 16
#define HD_   64
#define VOCAB_ 32000
#define FF_   4096

#define ROWS_ (B_*SEQ_)                    // 4096
#define ACT_ELEMS ((size_t)ROWS_*DIM_)     // 4M floats
#define ACT_PAIRS (ACT_ELEMS/2)            // 2M uint32

// ------------------------- fp32 scratch -------------------------
__device__ float g_XENR[ACT_ELEMS];
__device__ float g_S0  [ACT_ELEMS];
__device__ float g_S1  [ACT_ELEMS];
__device__ float g_H0  [ACT_ELEMS];
__device__ float g_H1  [ACT_ELEMS];
__device__ float g_T   [ACT_ELEMS];
__device__ float g_G   [ACT_ELEMS];
__device__ float g_MEAN[B_*DIM_];

// ------------------------- packed bf16 hi/lo scratch (uint32 = bf16x2) -------------------------
__device__ __align__(16) uint32_t g_cXhi [ACT_PAIRS],     g_cXlo [ACT_PAIRS];
__device__ __align__(16) uint32_t g_cH0hi[ACT_PAIRS],     g_cH0lo[ACT_PAIRS];
__device__ __align__(16) uint32_t g_cH1hi[ACT_PAIRS],     g_cH1lo[ACT_PAIRS];
__device__ __align__(16) uint32_t g_cAThi[ACT_PAIRS],     g_cATlo[ACT_PAIRS];
__device__ __align__(16) uint32_t g_cGhi [ACT_PAIRS],     g_cGlo [ACT_PAIRS];
__device__ __align__(16) uint32_t g_cFFhi[(size_t)ROWS_*FF_/2], g_cFFlo[(size_t)ROWS_*FF_/2];
__device__ __align__(16) uint32_t g_cS1hi[ACT_PAIRS],     g_cS1lo[ACT_PAIRS];
// head-major [B,H,S,HD] packed QKV for attention
__device__ __align__(16) uint32_t g_cQhi [ACT_PAIRS],     g_cQlo [ACT_PAIRS];
__device__ __align__(16) uint32_t g_cKhi [ACT_PAIRS],     g_cKlo [ACT_PAIRS];
__device__ __align__(16) uint32_t g_cVhi [ACT_PAIRS],     g_cVlo [ACT_PAIRS];

// weights, packed: slots of 0.5M uint32 (= one 1024x1024 matrix)
#define WSZ 524288ull
#define W_TOTAL 31064064ull   // 28*WSZ + 32000*1024/2
__device__ __align__(16) uint32_t g_WHI[W_TOTAL];
__device__ __align__(16) uint32_t g_WLO[W_TOTAL];

// ------------------------------ helpers ------------------------------
__device__ __forceinline__ float gelu_tanh(float x) {
    float x3 = x * x * x;
    return 0.5f * x * (1.0f + tanhf(0.79788456080286535588f * (x + 0.044715f * x3)));
}
__device__ __forceinline__ uint32_t pack_bf16(__nv_bfloat16 lo, __nv_bfloat16 hi) {
    __nv_bfloat162 p; p.x = lo; p.y = hi;
    return *reinterpret_cast<uint32_t*>(&p);
}
__device__ __forceinline__ void split2(float v0, float v1, uint32_t& hi, uint32_t& lo) {
    __nv_bfloat16 h0 = __float2bfloat16_rn(v0), h1 = __float2bfloat16_rn(v1);
    hi = pack_bf16(h0, h1);
    lo = pack_bf16(__float2bfloat16_rn(v0 - __bfloat162float(h0)),
                   __float2bfloat16_rn(v1 - __bfloat162float(h1)));
}
__device__ __forceinline__ void mma_bf16(float c[4], const uint32_t a[4], const uint32_t b[2]) {
    asm volatile(
        "mma.sync.aligned.m16n8k16.row.col.f32.bf16.bf16.f32 "
        "{%0,%1,%2,%3}, {%4,%5,%6,%7}, {%8,%9}, {%0,%1,%2,%3};"
        : "+f"(c[0]), "+f"(c[1]), "+f"(c[2]), "+f"(c[3])
        : "r"(a[0]), "r"(a[1]), "r"(a[2]), "r"(a[3]), "r"(b[0]), "r"(b[1]));
}
__device__ __forceinline__ void ldsm_x4(uint32_t r[4], uint32_t addr) {
    asm volatile("ldmatrix.sync.aligned.m8n8.x4.shared.b16 {%0,%1,%2,%3}, [%4];"
                 : "=r"(r[0]), "=r"(r[1]), "=r"(r[2]), "=r"(r[3]) : "r"(addr));
}
__device__ __forceinline__ void ldsm_x2(uint32_t r[2], uint32_t addr) {
    asm volatile("ldmatrix.sync.aligned.m8n8.x2.shared.b16 {%0,%1}, [%2];"
                 : "=r"(r[0]), "=r"(r[1]) : "r"(addr));
}
__device__ __forceinline__ void ldsm_x2_trans(uint32_t r[2], uint32_t addr) {
    asm volatile("ldmatrix.sync.aligned.m8n8.x2.trans.shared.b16 {%0,%1}, [%2];"
                 : "=r"(r[0]), "=r"(r[1]) : "r"(addr));
}
__device__ __forceinline__ void cp16(uint32_t saddr, const void* g) {
    asm volatile("cp.async.cg.shared.global [%0], [%1], 16;" :: "r"(saddr), "l"(g));
}

// ------------------------------ GEMM (packed operands, cp.async, ldmatrix) ------------------------------
// MODE 0: fp32 out. MODE 1: gelu + packed hi/lo row-major. MODE 2: packed hi/lo head-major [B,H,S,HD].
#define RST 12
#define ARR_B 6144
#define STAGE_B 24576
#define GEMM_SMEM (3*STAGE_B)

template<int MODE>
__global__ __launch_bounds__(256, 2)
void gemm_cp(const uint32_t* __restrict__ Ahi, const uint32_t* __restrict__ Alo,
             const uint32_t* __restrict__ Bhi, const uint32_t* __restrict__ Blo,
             float* __restrict__ C, uint32_t* __restrict__ Chi, uint32_t* __restrict__ Clo,
             int M, int N, int K)
{
    extern __shared__ uint32_t smem[];
    const uint32_t smem_base = (uint32_t)__cvta_generic_to_shared(smem);

    const int K2 = K >> 1;
    const int bm = blockIdx.y * 128;
    const int bn = blockIdx.x * 128;
    const int tid = threadIdx.x;

    const int row = tid >> 1, half = tid & 1;
    const uint32_t* pAhi = Ahi + (size_t)(bm + row) * K2 + half * 4;
    const uint32_t* pAlo = Alo + (size_t)(bm + row) * K2 + half * 4;
    const uint32_t* pBhi = Bhi + (size_t)(bn + row) * K2 + half * 4;
    const uint32_t* pBlo = Blo + (size_t)(bn + row) * K2 + half * 4;
    const uint32_t dst0 = smem_base + (uint32_t)((row * RST + half * 4) * 4);

    const int wid = tid >> 5, lane = tid & 31;
    const int warp_m = (wid & 1) * 64;
    const int warp_n = (wid >> 1) * 32;
    const int g = lane >> 2, t = lane & 3;

    uint32_t aoff[4], boff[4];
    {
        int arow = lane & 15, acol = (lane >> 4) * 4;
        int brow = lane & 7,  bcol = ((lane >> 3) & 1) * 4;
#pragma unroll
        for (int fm = 0; fm < 4; fm++)
            aoff[fm] = (uint32_t)(((warp_m + fm * 16 + arow) * RST + acol) * 4);
#pragma unroll
        for (int fn = 0; fn < 4; fn++)
            boff[fn] = (uint32_t)(2 * ARR_B + ((warp_n + fn * 8 + brow) * RST + bcol) * 4);
    }

    float acc[4][4][4];
#pragma unroll
    for (int i = 0; i < 4; i++)
#pragma unroll
        for (int j = 0; j < 4; j++)
#pragma unroll
            for (int r = 0; r < 4; r++) acc[i][j][r] = 0.0f;

    const int nch = K >> 4;

    auto issue = [&](int kc, int s) {
        uint32_t d = dst0 + (uint32_t)(s * STAGE_B);
        cp16(d,             pAhi + (size_t)kc * 8);
        cp16(d + ARR_B,     pAlo + (size_t)kc * 8);
        cp16(d + 2 * ARR_B, pBhi + (size_t)kc * 8);
        cp16(d + 3 * ARR_B, pBlo + (size_t)kc * 8);
        asm volatile("cp.async.commit_group;");
    };

    issue(0, 0);
    if (nch > 1) issue(1, 1);

    for (int kc = 0; kc < nch; kc++) {
        asm volatile("cp.async.wait_group 1;");
        __syncthreads();
        if (kc + 2 < nch) issue(kc + 2, (kc + 2) % 3);

        const uint32_t sb = smem_base + (uint32_t)((kc % 3) * STAGE_B);
        uint32_t bhi[4][2], blo[4][2];
#pragma unroll
        for (int fn = 0; fn < 4; fn++) {
            ldsm_x2(bhi[fn], sb + boff[fn]);
            ldsm_x2(blo[fn], sb + boff[fn] + ARR_B);
        }
#pragma unroll
        for (int fm = 0; fm < 4; fm++) {
            uint32_t ahi[4], alo[4];
            ldsm_x4(ahi, sb + aoff[fm]);
            ldsm_x4(alo, sb + aoff[fm] + ARR_B);
#pragma unroll
            for (int fn = 0; fn < 4; fn++) {
                mma_bf16(acc[fm][fn], ahi, blo[fn]);
                mma_bf16(acc[fm][fn], alo, bhi[fn]);
                mma_bf16(acc[fm][fn], ahi, bhi[fn]);
            }
        }
    }

#pragma unroll
    for (int fm = 0; fm < 4; fm++) {
#pragma unroll
        for (int fn = 0; fn < 4; fn++) {
            int row0 = bm + warp_m + fm * 16 + g;
            int col  = bn + warp_n + fn * 8 + 2 * t;
            float v0 = acc[fm][fn][0], v1 = acc[fm][fn][1];
            float v2 = acc[fm][fn][2], v3 = acc[fm][fn][3];
            if (MODE == 1) {
                v0 = gelu_tanh(v0); v1 = gelu_tanh(v1);
                v2 = gelu_tanh(v2); v3 = gelu_tanh(v3);
                int N2 = N >> 1;
                int cp0 = col >> 1;
                uint32_t h, l;
                split2(v0, v1, h, l);
                Chi[(size_t)row0 * N2 + cp0] = h;  Clo[(size_t)row0 * N2 + cp0] = l;
                split2(v2, v3, h, l);
                Chi[(size_t)(row0 + 8) * N2 + cp0] = h;  Clo[(size_t)(row0 + 8) * N2 + cp0] = l;
            } else if (MODE == 2) {
                // head-major packed: [B,H,S,HD]; rows row0 (v0,v1) and row0+8 (v2,v3)
                int bb = row0 >> 10, ss = row0 & 1023;
                int hh = col >> 6, hd = col & 63;
                size_t base = (((size_t)(bb * HEADS_ + hh)) * SEQ_ + ss) * HD_ + hd;
                size_t pidx0 = base >> 1;
                size_t pidx1 = (base + 8 * HD_) >> 1;   // ss+8, same b/h/hd
                uint32_t h, l;
                split2(v0, v1, h, l);
                Chi[pidx0] = h;  Clo[pidx0] = l;
                split2(v2, v3, h, l);
                Chi[pidx1] = h;  Clo[pidx1] = l;
            } else {
                *(float2*)(C + (size_t)row0 * N + col)       = make_float2(v0, v1);
                *(float2*)(C + (size_t)(row0 + 8) * N + col) = make_float2(v2, v3);
            }
        }
    }
}

// ------------------------------ MMA flash attention ------------------------------
// Inputs: packed bf16 hi/lo Q,K,V in head-major [B,H,S,HD]. Output: packed hi/lo
// in [B,S,H*HD] row-major (feeds wo GEMM). 128 threads, warp = 16 q-rows.
#define A_RST 36
#define A_QHI 0
#define A_QLO 2304
#define A_BUF0 4608
#define A_BUFSZ 9216          // uint32: Khi,Klo,Vhi,Vlo (4 x 2304)
#define ATTN_SMEM_B ((A_BUF0 + 2*A_BUFSZ)*4)   // 92160 bytes

__global__ __launch_bounds__(128)
void attn_mma(const uint32_t* __restrict__ Qhi, const uint32_t* __restrict__ Qlo,
              const uint32_t* __restrict__ Khi, const uint32_t* __restrict__ Klo,
              const uint32_t* __restrict__ Vhi, const uint32_t* __restrict__ Vlo,
              uint32_t* __restrict__ Ohi, uint32_t* __restrict__ Olo,
              const float* __restrict__ gate, int causal)
{
    extern __shared__ uint32_t smem[];
    const uint32_t smem_base = (uint32_t)__cvta_generic_to_shared(smem);

    const int qb  = blockIdx.x;          // q-block (16)
    const int bh  = blockIdx.y;          // b*H + h (64)
    const int b   = bh >> 4, h = bh & 15;
    const int q0  = qb * 64;
    const int tid = threadIdx.x;
    const int wid = tid >> 5, lane = tid & 31;
    const int g = lane >> 2, t = lane & 3;

    const size_t plane = (size_t)bh * (SEQ_ * (HD_ / 2));   // uint32 offset

    // ---- stage Q tile (64 rows x 32 uint32) into padded smem ----
#pragma unroll
    for (int i = 0; i < 4; i++) {
        int idx = i * 128 + tid;          // 0..511
        int r = idx >> 3, ch = idx & 7;
        const uint4* sh = (const uint4*)(Qhi + plane + (size_t)(q0 + r) * 32 + ch * 4);
        const uint4* sl = (const uint4*)(Qlo + plane + (size_t)(q0 + r) * 32 + ch * 4);
        *(uint4*)&smem[A_QHI + r * A_RST + ch * 4] = *sh;
        *(uint4*)&smem[A_QLO + r * A_RST + ch * 4] = *sl;
    }

    // ---- K/V cp.async staging ----
    auto issueKV = [&](int kb, int buf) {
        uint32_t dbase = smem_base + (uint32_t)((A_BUF0 + buf * A_BUFSZ) * 4);
        size_t src = plane + (size_t)(kb * 64) * 32;
#pragma unroll
        for (int i = 0; i < 4; i++) {
            int idx = i * 128 + tid;
            int r = idx >> 3, ch = idx & 7;
            uint32_t doff = (uint32_t)((r * A_RST + ch * 4) * 4);
            size_t soff = src + (size_t)r * 32 + ch * 4;
            cp16(dbase + doff,                Khi + soff);
            cp16(dbase + 2304 * 4 + doff,     Klo + soff);
            cp16(dbase + 4608 * 4 + doff,     Vhi + soff);
            cp16(dbase + 6912 * 4 + doff,     Vlo + soff);
        }
        asm volatile("cp.async.commit_group;");
    };

    const int nkb = causal ? (qb + 1) : (SEQ_ / 64);
    issueKV(0, 0);

    // fragment address components
    const int l15 = lane & 15;
    const uint32_t qrow_off = (uint32_t)((wid * 16 + l15) * A_RST * 4);
    const uint32_t qk_half  = (uint32_t)((lane >> 4) * 16);   // bytes
    const uint32_t krow_base = (uint32_t)((lane & 7) * A_RST * 4);
    const uint32_t kk_half   = (uint32_t)(((lane >> 3) & 1) * 16);

    float sacc[8][4], oacc[8][4];
    float m0 = -3.0e38f, m1 = -3.0e38f, l0 = 0.0f, l1 = 0.0f;
#pragma unroll
    for (int fn = 0; fn < 8; fn++)
#pragma unroll
        for (int j = 0; j < 4; j++) oacc[fn][j] = 0.0f;

    for (int kb = 0; kb < nkb; kb++) {
        asm volatile("cp.async.wait_group 0;");
        __syncthreads();
        if (kb + 1 < nkb) issueKV(kb + 1, (kb + 1) & 1);

        const uint32_t sb = smem_base + (uint32_t)((A_BUF0 + (kb & 1) * A_BUFSZ) * 4);
        const uint32_t sbK = sb, sbKlo = sb + 2304 * 4;
        const uint32_t sbV = sb + 4608 * 4, sbVlo = sb + 6912 * 4;

#pragma unroll
        for (int fn = 0; fn < 8; fn++)
#pragma unroll
            for (int j = 0; j < 4; j++) sacc[fn][j] = 0.0f;

        // S = Q K^T (3-term split)
#pragma unroll
        for (int kk = 0; kk < 4; kk++) {
            uint32_t qhi[4], qlo[4];
            uint32_t qa = (uint32_t)(qrow_off + kk * 32 + qk_half);
            ldsm_x4(qhi, smem_base + A_QHI * 4 + qa);
            ldsm_x4(qlo, smem_base + A_QLO * 4 + qa);
#pragma unroll
            for (int fn = 0; fn < 8; fn++) {
                uint32_t khi[2], klo[2];
                uint32_t ka = (uint32_t)(fn * 8 * A_RST * 4 + krow_base + kk * 32 + kk_half);
                ldsm_x2(khi, sbK + ka);
                ldsm_x2(klo, sbKlo + ka);
                mma_bf16(sacc[fn], qhi, klo);
                mma_bf16(sacc[fn], qlo, khi);
                mma_bf16(sacc[fn], qhi, khi);
            }
        }

        // online softmax (rows wid*16+g and +8)
        const int rq0 = q0 + wid * 16 + g;
        const int rq1 = rq0 + 8;
        const bool maskblk = causal && (kb == qb);
        float mx0 = -3.0e38f, mx1 = -3.0e38f;
#pragma unroll
        for (int fn = 0; fn < 8; fn++) {
            int c0 = kb * 64 + fn * 8 + 2 * t;
#pragma unroll
            for (int j = 0; j < 4; j++) {
                float v = sacc[fn][j] * 0.125f;
                int cc = c0 + (j & 1);
                int rr = (j < 2) ? rq0 : rq1;
                if (maskblk && cc > rr) v = -3.0e38f;
                sacc[fn][j] = v;
            }
            mx0 = fmaxf(mx0, fmaxf(sacc[fn][0], sacc[fn][1]));
            mx1 = fmaxf(mx1, fmaxf(sacc[fn][2], sacc[fn][3]));
        }
        mx0 = fmaxf(mx0, __shfl_xor_sync(0xffffffffu, mx0, 1));
        mx0 = fmaxf(mx0, __shfl_xor_sync(0xffffffffu, mx0, 2));
        mx1 = fmaxf(mx1, __shfl_xor_sync(0xffffffffu, mx1, 1));
        mx1 = fmaxf(mx1, __shfl_xor_sync(0xffffffffu, mx1, 2));

        float mn0 = fmaxf(m0, mx0), mn1 = fmaxf(m1, mx1);
        float al0 = __expf(m0 - mn0), al1 = __expf(m1 - mn1);
        m0 = mn0; m1 = mn1;

        uint32_t ph[8][2], pl[8][2];
        float ls0 = 0.0f, ls1 = 0.0f;
#pragma unroll
        for (int fn = 0; fn < 8; fn++) {
            float p0 = __expf(sacc[fn][0] - m0);
            float p1 = __expf(sacc[fn][1] - m0);
            float p2 = __expf(sacc[fn][2] - m1);
            float p3 = __expf(sacc[fn][3] - m1);
            ls0 += p0 + p1; ls1 += p2 + p3;
            split2(p0, p1, ph[fn][0], pl[fn][0]);
            split2(p2, p3, ph[fn][1], pl[fn][1]);
        }
        ls0 += __shfl_xor_sync(0xffffffffu, ls0, 1);
        ls0 += __shfl_xor_sync(0xffffffffu, ls0, 2);
        ls1 += __shfl_xor_sync(0xffffffffu, ls1, 1);
        ls1 += __shfl_xor_sync(0xffffffffu, ls1, 2);
        l0 = l0 * al0 + ls0;
        l1 = l1 * al1 + ls1;

#pragma unroll
        for (int fn = 0; fn < 8; fn++) {
            oacc[fn][0] *= al0; oacc[fn][1] *= al0;
            oacc[fn][2] *= al1; oacc[fn][3] *= al1;
        }

        // O += P V (3-term split); V fragment via ldmatrix.trans
#pragma unroll
        for (int kk = 0; kk < 4; kk++) {
            uint32_t ahi[4] = {ph[2*kk][0], ph[2*kk][1], ph[2*kk+1][0], ph[2*kk+1][1]};
            uint32_t alo[4] = {pl[2*kk][0], pl[2*kk][1], pl[2*kk+1][0], pl[2*kk+1][1]};
            uint32_t vrow = (uint32_t)((kk * 16 + l15) * A_RST * 4);
#pragma unroll
            for (int fo = 0; fo < 8; fo++) {
                uint32_t vhi[2], vlo[2];
                uint32_t va = vrow + (uint32_t)(fo * 16);
                ldsm_x2_trans(vhi, sbV + va);
                ldsm_x2_trans(vlo, sbVlo + va);
                mma_bf16(oacc[fo], ahi, vlo);
                mma_bf16(oacc[fo], alo, vhi);
                mma_bf16(oacc[fo], ahi, vhi);
            }
        }
    }

    // epilogue
    float gmul = 1.0f;
    if (gate != nullptr) gmul = 1.0f - 1.0f / (1.0f + __expf(-gate[h]));
    float inv0 = gmul / l0, inv1 = gmul / l1;

    const int rq0 = q0 + wid * 16 + g;
#pragma unroll
    for (int fo = 0; fo < 8; fo++) {
        int col = h * HD_ + fo * 8 + 2 * t;
        size_t p0 = ((size_t)(b * SEQ_ + rq0) * DIM_ + col) >> 1;
        size_t p1 = ((size_t)(b * SEQ_ + rq0 + 8) * DIM_ + col) >> 1;
        uint32_t hh, ll;
        split2(oacc[fo][0] * inv0, oacc[fo][1] * inv0, hh, ll);
        Ohi[p0] = hh; Olo[p0] = ll;
        split2(oacc[fo][2] * inv1, oacc[fo][3] * inv1, hh, ll);
        Ohi[p1] = hh; Olo[p1] = ll;
    }
}

// ------------------------------ elementwise ------------------------------
__global__ void pack_split_kernel(const float* __restrict__ in,
                                  uint32_t* __restrict__ hi, uint32_t* __restrict__ lo,
                                  int n4)
{
    int i = blockIdx.x * blockDim.x + threadIdx.x;
    if (i >= n4) return;
    float4 v = ((const float4*)in)[i];
    uint32_t h0, l0, h1, l1;
    split2(v.x, v.y, h0, l0);
    split2(v.z, v.w, h1, l1);
    hi[2 * i] = h0; hi[2 * i + 1] = h1;
    lo[2 * i] = l0; lo[2 * i + 1] = l1;
}

__global__ void embed_pack_kernel(const int* __restrict__ x, const float* __restrict__ emb,
                                  uint32_t* __restrict__ hi, uint32_t* __restrict__ lo)
{
    int i = blockIdx.x * blockDim.x + threadIdx.x;
    if (i >= (int)(ACT_ELEMS / 4)) return;
    int row = i >> 8, c4 = i & 255;
    int tok = x[row];
    float4 v = ((const float4*)(emb + (size_t)tok * DIM_))[c4];
    uint32_t h0, l0, h1, l1;
    split2(v.x, v.y, h0, l0);
    split2(v.z, v.w, h1, l1);
    hi[2 * i] = h0; hi[2 * i + 1] = h1;
    lo[2 * i] = l0; lo[2 * i + 1] = l1;
}

__global__ void bcast_init_kernel(const float* __restrict__ i0, const float* __restrict__ i1,
                                  float* __restrict__ S0, float* __restrict__ S1)
{
    int i = blockIdx.x * blockDim.x + threadIdx.x;
    if (i >= (int)(ACT_ELEMS / 4)) return;
    int src = i & (int)(SEQ_ * DIM_ / 4 - 1);
    ((float4*)S0)[i] = ((const float4*)i0)[src];
    ((float4*)S1)[i] = ((const float4*)i1)[src];
}

__global__ void add3_pack_kernel(const float* __restrict__ a, const float* __restrict__ b,
                                 const float* __restrict__ c, float* __restrict__ o,
                                 uint32_t* __restrict__ hi, uint32_t* __restrict__ lo)
{
    int i = blockIdx.x * blockDim.x + threadIdx.x;
    if (i >= (int)(ACT_ELEMS / 4)) return;
    float4 va = ((const float4*)a)[i];
    float4 vb = ((const float4*)b)[i];
    float4 vc = ((const float4*)c)[i];
    float4 s = make_float4(va.x + vb.x + vc.x, va.y + vb.y + vc.y,
                           va.z + vb.z + vc.z, va.w + vb.w + vc.w);
    ((float4*)o)[i] = s;
    uint32_t h0, l0, h1, l1;
    split2(s.x, s.y, h0, l0);
    split2(s.z, s.w, h1, l1);
    hi[2 * i] = h0; hi[2 * i + 1] = h1;
    lo[2 * i] = l0; lo[2 * i + 1] = l1;
}

template<int PACK>
__global__ __launch_bounds__(256)
void rmsnorm_add_kernel(const float* __restrict__ a, const float* __restrict__ b,
                        float* __restrict__ o,
                        uint32_t* __restrict__ hi, uint32_t* __restrict__ lo)
{
    int row = blockIdx.x;
    int tid = threadIdx.x;
    const float4* a4 = (const float4*)(a + (size_t)row * DIM_);
    const float4* b4 = (const float4*)(b + (size_t)row * DIM_);
    float4 va = a4[tid], vb = b4[tid];
    float4 s = make_float4(va.x + vb.x, va.y + vb.y, va.z + vb.z, va.w + vb.w);
    float ss = s.x * s.x + s.y * s.y + s.z * s.z + s.w * s.w;
#pragma unroll
    for (int off = 16; off > 0; off >>= 1) ss += __shfl_xor_sync(0xffffffffu, ss, off);
    __shared__ float red[8];
    __shared__ float scale_s;
    if ((tid & 31) == 0) red[tid >> 5] = ss;
    __syncthreads();
    if (tid == 0) {
        float tacc = 0.0f;
#pragma unroll
        for (int w = 0; w < 8; w++) tacc += red[w];
        scale_s = rsqrtf(tacc * (1.0f / DIM_) + 1e-6f);
    }
    __syncthreads();
    float sc = scale_s;
    float4 r = make_float4(s.x * sc, s.y * sc, s.z * sc, s.w * sc);
    ((float4*)(o + (size_t)row * DIM_))[tid] = r;
    if (PACK) {
        uint32_t h0, l0, h1, l1;
        split2(r.x, r.y, h0, l0);
        split2(r.z, r.w, h1, l1);
        size_t pidx = (size_t)row * (DIM_ / 2) + tid * 2;
        hi[pidx] = h0; hi[pidx + 1] = h1;
        lo[pidx] = l0; lo[pidx + 1] = l1;
    }
}

__global__ void mean_kernel(const float* __restrict__ S, float* __restrict__ M)
{
    int idx = blockIdx.x * blockDim.x + threadIdx.x;
    if (idx >= B_ * DIM_) return;
    int b = idx >> 10, d = idx & (DIM_ - 1);
    const float* p = S + (size_t)b * SEQ_ * DIM_ + d;
    float s = 0.0f;
    for (int t = 0; t < SEQ_; t++) s += p[(size_t)t * DIM_];
    M[idx] = s * (1.0f / SEQ_);
}

__global__ void qhead_kernel(const float* __restrict__ M, const float* __restrict__ W,
                             float* __restrict__ out)
{
    int w = threadIdx.x >> 5, lane = threadIdx.x & 31;
    int b = w >> 1, o = w & 1;
    const float* m  = M + (size_t)b * DIM_;
    const float* ww = W + (size_t)o * DIM_;
    float s = 0.0f;
    for (int k = lane; k < DIM_; k += 32) s += m[k] * ww[k];
#pragma unroll
    for (int off = 16; off > 0; off >>= 1) s += __shfl_xor_sync(0xffffffffu, s, off);
    if (lane == 0) out[b * 2 + o] = 1.0f / (1.0f + __expf(-s));
}

// ------------------------------ host orchestration ------------------------------
static void launch_gemm(const uint32_t* Ahi, const uint32_t* Alo,
                        const uint32_t* Bhi, const uint32_t* Blo,
                        float* C, uint32_t* Chi, uint32_t* Clo,
                        int M, int N, int K, int mode)
{
    dim3 grid(N / 128, M / 128);
    if (mode == 1)      gemm_cp<1><<<grid, 256, GEMM_SMEM>>>(Ahi, Alo, Bhi, Blo, C, Chi, Clo, M, N, K);
    else if (mode == 2) gemm_cp<2><<<grid, 256, GEMM_SMEM>>>(Ahi, Alo, Bhi, Blo, C, Chi, Clo, M, N, K);
    else                gemm_cp<0><<<grid, 256, GEMM_SMEM>>>(Ahi, Alo, Bhi, Blo, C, Chi, Clo, M, N, K);
}

struct WOffs { size_t wq, wk, wv, wo, w1, w2; };

extern "C" void kernel_launch(void* const* d_in, const int* in_sizes, int n_in,
                              void* d_out, int out_size)
{
    (void)in_sizes; (void)n_in; (void)out_size;
    const int*   x     = (const int*)  d_in[0];
    const float* emb   = (const float*)d_in[1];
    const float* gate  = (const float*)d_in[6];
    const float* init0 = (const float*)d_in[7];
    const float* init1 = (const float*)d_in[8];
    const float* w_out   = (const float*)d_in[21];
    const float* w_qhead = (const float*)d_in[22];
    float* out = (float*)d_out;

    float *XENR, *S0, *S1, *H0, *H1, *T, *G, *MEAN;
    cudaGetSymbolAddress((void**)&XENR, g_XENR);
    cudaGetSymbolAddress((void**)&S0,   g_S0);
    cudaGetSymbolAddress((void**)&S1,   g_S1);
    cudaGetSymbolAddress((void**)&H0,   g_H0);
    cudaGetSymbolAddress((void**)&H1,   g_H1);
    cudaGetSymbolAddress((void**)&T,    g_T);
    cudaGetSymbolAddress((void**)&G,    g_G);
    cudaGetSymbolAddress((void**)&MEAN, g_MEAN);

    uint32_t *cXhi, *cXlo, *cH0hi, *cH0lo, *cH1hi, *cH1lo, *cAThi, *cATlo;
    uint32_t *cGhi, *cGlo, *cFFhi, *cFFlo, *cS1hi, *cS1lo, *WHI, *WLO;
    uint32_t *cQhi, *cQlo, *cKhi, *cKlo, *cVhi, *cVlo;
    cudaGetSymbolAddress((void**)&cXhi,  g_cXhi);  cudaGetSymbolAddress((void**)&cXlo,  g_cXlo);
    cudaGetSymbolAddress((void**)&cH0hi, g_cH0hi); cudaGetSymbolAddress((void**)&cH0lo, g_cH0lo);
    cudaGetSymbolAddress((void**)&cH1hi, g_cH1hi); cudaGetSymbolAddress((void**)&cH1lo, g_cH1lo);
    cudaGetSymbolAddress((void**)&cAThi, g_cAThi); cudaGetSymbolAddress((void**)&cATlo, g_cATlo);
    cudaGetSymbolAddress((void**)&cGhi,  g_cGhi);  cudaGetSymbolAddress((void**)&cGlo,  g_cGlo);
    cudaGetSymbolAddress((void**)&cFFhi, g_cFFhi); cudaGetSymbolAddress((void**)&cFFlo, g_cFFlo);
    cudaGetSymbolAddress((void**)&cS1hi, g_cS1hi); cudaGetSymbolAddress((void**)&cS1lo, g_cS1lo);
    cudaGetSymbolAddress((void**)&cQhi,  g_cQhi);  cudaGetSymbolAddress((void**)&cQlo,  g_cQlo);
    cudaGetSymbolAddress((void**)&cKhi,  g_cKhi);  cudaGetSymbolAddress((void**)&cKlo,  g_cKlo);
    cudaGetSymbolAddress((void**)&cVhi,  g_cVhi);  cudaGetSymbolAddress((void**)&cVlo,  g_cVlo);
    cudaGetSymbolAddress((void**)&WHI,   g_WHI);   cudaGetSymbolAddress((void**)&WLO,   g_WLO);

    cudaFuncSetAttribute(attn_mma, cudaFuncAttributeMaxDynamicSharedMemorySize, ATTN_SMEM_B);
    cudaFuncSetAttribute(gemm_cp<0>, cudaFuncAttributeMaxDynamicSharedMemorySize, GEMM_SMEM);
    cudaFuncSetAttribute(gemm_cp<1>, cudaFuncAttributeMaxDynamicSharedMemorySize, GEMM_SMEM);
    cudaFuncSetAttribute(gemm_cp<2>, cudaFuncAttributeMaxDynamicSharedMemorySize, GEMM_SMEM);

    // ---- weight pre-split (once per launch) ----
    const int widx[14]  = {2, 3, 4, 5,   9, 10, 11, 12, 13, 14,   15, 16, 17, 18};
    const size_t woff[14] = {0, 1*WSZ, 2*WSZ, 3*WSZ,
                             4*WSZ, 5*WSZ, 6*WSZ, 7*WSZ, 8*WSZ, 12*WSZ,
                             16*WSZ, 17*WSZ, 18*WSZ, 19*WSZ};
    const size_t wel[14]  = {1u<<20, 1u<<20, 1u<<20, 1u<<20,
                             1u<<20, 1u<<20, 1u<<20, 1u<<20, 1u<<22, 1u<<22,
                             1u<<20, 1u<<20, 1u<<20, 1u<<20};
    for (int i = 0; i < 14; i++) {
        size_t off = woff[i];
        size_t elems = wel[i];
        if (i >= 10) {
            off = (size_t)(16 + (i - 10)) * WSZ;
            elems = 1u << 20;
        }
        int n4 = (int)(elems / 4);
        pack_split_kernel<<<(n4 + 255) / 256, 256>>>((const float*)d_in[widx[i]],
                                                     WHI + off, WLO + off, n4);
    }
    {
        int n4 = (1 << 22) / 4;
        pack_split_kernel<<<(n4 + 255) / 256, 256>>>((const float*)d_in[19], WHI + 20*WSZ, WLO + 20*WSZ, n4);
        pack_split_kernel<<<(n4 + 255) / 256, 256>>>((const float*)d_in[20], WHI + 24*WSZ, WLO + 24*WSZ, n4);
        int n4v = VOCAB_ * DIM_ / 4;
        pack_split_kernel<<<(n4v + 255) / 256, 256>>>(w_out, WHI + 28*WSZ, WLO + 28*WSZ, n4v);
    }

    WOffs lw[2];
    lw[0] = { 4*WSZ, 5*WSZ, 6*WSZ, 7*WSZ, 8*WSZ, 12*WSZ };
    lw[1] = { 16*WSZ, 17*WSZ, 18*WSZ, 19*WSZ, 20*WSZ, 24*WSZ };

    const int v4blocks = (int)(ACT_ELEMS / 4 + 255) / 256;
    const dim3 agrid(SEQ_ / 64, B_ * HEADS_);

    // ---- embedding ----
    embed_pack_kernel<<<v4blocks, 256>>>(x, emb, cXhi, cXlo);

    // ---- infini attention (memory==0 => combined = (1-sigmoid(gate))*local) ----
    launch_gemm(cXhi, cXlo, WHI + 0*WSZ, WLO + 0*WSZ, 0, cQhi, cQlo, ROWS_, DIM_, DIM_, 2);
    launch_gemm(cXhi, cXlo, WHI + 1*WSZ, WLO + 1*WSZ, 0, cKhi, cKlo, ROWS_, DIM_, DIM_, 2);
    launch_gemm(cXhi, cXlo, WHI + 2*WSZ, WLO + 2*WSZ, 0, cVhi, cVlo, ROWS_, DIM_, DIM_, 2);
    attn_mma<<<agrid, 128, ATTN_SMEM_B>>>(cQhi, cQlo, cKhi, cKlo, cVhi, cVlo,
                                          cAThi, cATlo, gate, 1);
    launch_gemm(cAThi, cATlo, WHI + 3*WSZ, WLO + 3*WSZ, XENR, 0, 0, ROWS_, DIM_, DIM_, 0);

    bcast_init_kernel<<<v4blocks, 256>>>(init0, init1, S0, S1);

    // ---- HRM steps ----
    for (int step = 0; step < 8; step++) {
        bool u1 = ((step + 1) % 4 == 0);
        add3_pack_kernel<<<v4blocks, 256>>>(S0, XENR, S1, H0, cH0hi, cH0lo);
        if (u1) add3_pack_kernel<<<v4blocks, 256>>>(S1, XENR, S0, H1, cH1hi, cH1lo);
        for (int li = 0; li < (u1 ? 2 : 1); li++) {
            const WOffs& o = lw[li];
            uint32_t* hHi = li ? cH1hi : cH0hi;
            uint32_t* hLo = li ? cH1lo : cH0lo;
            float* Hres = li ? H1 : H0;
            float* OUT  = li ? S1 : S0;
            launch_gemm(hHi, hLo, WHI + o.wq, WLO + o.wq, 0, cQhi, cQlo, ROWS_, DIM_, DIM_, 2);
            launch_gemm(hHi, hLo, WHI + o.wk, WLO + o.wk, 0, cKhi, cKlo, ROWS_, DIM_, DIM_, 2);
            launch_gemm(hHi, hLo, WHI + o.wv, WLO + o.wv, 0, cVhi, cVlo, ROWS_, DIM_, DIM_, 2);
            attn_mma<<<agrid, 128, ATTN_SMEM_B>>>(cQhi, cQlo, cKhi, cKlo, cVhi, cVlo,
                                                  cAThi, cATlo, nullptr, 0);
            launch_gemm(cAThi, cATlo, WHI + o.wo, WLO + o.wo, T, 0, 0, ROWS_, DIM_, DIM_, 0);
            rmsnorm_add_kernel<1><<<ROWS_, 256>>>(Hres, T, G, cGhi, cGlo);
            launch_gemm(cGhi, cGlo, WHI + o.w1, WLO + o.w1, 0, cFFhi, cFFlo, ROWS_, FF_, DIM_, 1);
            launch_gemm(cFFhi, cFFlo, WHI + o.w2, WLO + o.w2, T, 0, 0, ROWS_, DIM_, FF_, 0);
            rmsnorm_add_kernel<0><<<ROWS_, 256>>>(G, T, OUT, 0, 0);
        }
    }

    // ---- outputs ----
    pack_split_kernel<<<v4blocks, 256>>>(S1, cS1hi, cS1lo, (int)(ACT_ELEMS / 4));
    launch_gemm(cS1hi, cS1lo, WHI + 28*WSZ, WLO + 28*WSZ, out, 0, 0, ROWS_, VOCAB_, DIM_, 0);
    mean_kernel<<<(B_ * DIM_ + 255) / 256, 256>>>(S1, MEAN);
    qhead_kernel<<<1, 256>>>(MEAN, w_qhead, out + (size_t)ROWS_ * VOCAB_);
}

// round 10
// speedup vs baseline: 2.8352x; 1.0895x over previous
#include <cuda_runtime.h>
#include <cuda_bf16.h>
#include <math.h>
#include <stdint.h>

#define B_    4
#define SEQ_  1024
#define DIM_  1024
#define HEADS_ 16
#define HD_   64
#define VOCAB_ 32000
#define FF_   4096

#define ROWS_ (B_*SEQ_)                    // 4096
#define ACT_ELEMS ((size_t)ROWS_*DIM_)     // 4M floats
#define ACT_PAIRS (ACT_ELEMS/2)            // 2M uint32

// ------------------------- fp32 scratch -------------------------
__device__ float g_XENR[ACT_ELEMS];
__device__ float g_S0  [ACT_ELEMS];
__device__ float g_S1  [ACT_ELEMS];
__device__ float g_H0  [ACT_ELEMS];
__device__ float g_H1  [ACT_ELEMS];
__device__ float g_T   [ACT_ELEMS];
__device__ float g_G   [ACT_ELEMS];
__device__ float g_MEAN[B_*DIM_];

// ------------------------- packed bf16 hi/lo scratch (uint32 = bf16x2) -------------------------
__device__ __align__(16) uint32_t g_cXhi [ACT_PAIRS],     g_cXlo [ACT_PAIRS];
__device__ __align__(16) uint32_t g_cH0hi[ACT_PAIRS],     g_cH0lo[ACT_PAIRS];
__device__ __align__(16) uint32_t g_cH1hi[ACT_PAIRS],     g_cH1lo[ACT_PAIRS];
__device__ __align__(16) uint32_t g_cAThi[ACT_PAIRS],     g_cATlo[ACT_PAIRS];
__device__ __align__(16) uint32_t g_cGhi [ACT_PAIRS],     g_cGlo [ACT_PAIRS];
__device__ __align__(16) uint32_t g_cFFhi[(size_t)ROWS_*FF_/2], g_cFFlo[(size_t)ROWS_*FF_/2];
__device__ __align__(16) uint32_t g_cS1hi[ACT_PAIRS],     g_cS1lo[ACT_PAIRS];
// fused head-major QKV: [3][B,H,S,HD] packed (Q at 0, K at ACT_PAIRS, V at 2*ACT_PAIRS)
__device__ __align__(16) uint32_t g_cQKVhi[3*ACT_PAIRS],  g_cQKVlo[3*ACT_PAIRS];

// weights, packed: slots of 0.5M uint32 (= one 1024x1024 matrix)
#define WSZ 524288ull
#define W_TOTAL 31064064ull   // 28*WSZ + 32000*1024/2
__device__ __align__(16) uint32_t g_WHI[W_TOTAL];
__device__ __align__(16) uint32_t g_WLO[W_TOTAL];
// slots: awq0 awk1 awv2 (contiguous QKV) awo3 | l0: q4 k5 v6 o7 w1@8 w2@12
// l1: q16 k17 v18 o19 w1@20 w2@24 | w_out@28

// ------------------------------ helpers ------------------------------
__device__ __forceinline__ float gelu_tanh(float x) {
    float x3 = x * x * x;
    return 0.5f * x * (1.0f + tanhf(0.79788456080286535588f * (x + 0.044715f * x3)));
}
__device__ __forceinline__ uint32_t pack_bf16(__nv_bfloat16 lo, __nv_bfloat16 hi) {
    __nv_bfloat162 p; p.x = lo; p.y = hi;
    return *reinterpret_cast<uint32_t*>(&p);
}
__device__ __forceinline__ void split2(float v0, float v1, uint32_t& hi, uint32_t& lo) {
    __nv_bfloat16 h0 = __float2bfloat16_rn(v0), h1 = __float2bfloat16_rn(v1);
    hi = pack_bf16(h0, h1);
    lo = pack_bf16(__float2bfloat16_rn(v0 - __bfloat162float(h0)),
                   __float2bfloat16_rn(v1 - __bfloat162float(h1)));
}
__device__ __forceinline__ void mma_bf16(float c[4], const uint32_t a[4], const uint32_t b[2]) {
    asm volatile(
        "mma.sync.aligned.m16n8k16.row.col.f32.bf16.bf16.f32 "
        "{%0,%1,%2,%3}, {%4,%5,%6,%7}, {%8,%9}, {%0,%1,%2,%3};"
        : "+f"(c[0]), "+f"(c[1]), "+f"(c[2]), "+f"(c[3])
        : "r"(a[0]), "r"(a[1]), "r"(a[2]), "r"(a[3]), "r"(b[0]), "r"(b[1]));
}
__device__ __forceinline__ void ldsm_x4(uint32_t r[4], uint32_t addr) {
    asm volatile("ldmatrix.sync.aligned.m8n8.x4.shared.b16 {%0,%1,%2,%3}, [%4];"
                 : "=r"(r[0]), "=r"(r[1]), "=r"(r[2]), "=r"(r[3]) : "r"(addr));
}
__device__ __forceinline__ void ldsm_x2(uint32_t r[2], uint32_t addr) {
    asm volatile("ldmatrix.sync.aligned.m8n8.x2.shared.b16 {%0,%1}, [%2];"
                 : "=r"(r[0]), "=r"(r[1]) : "r"(addr));
}
__device__ __forceinline__ void ldsm_x2_trans(uint32_t r[2], uint32_t addr) {
    asm volatile("ldmatrix.sync.aligned.m8n8.x2.trans.shared.b16 {%0,%1}, [%2];"
                 : "=r"(r[0]), "=r"(r[1]) : "r"(addr));
}
__device__ __forceinline__ void cp16(uint32_t saddr, const void* g) {
    asm volatile("cp.async.cg.shared.global [%0], [%1], 16;" :: "r"(saddr), "l"(g));
}

// ------------------------------ GEMM (K-chunk 32, 2-stage, x4-B ldmatrix) ------------------------------
// MODE 0: fp32 out. MODE 1: gelu + packed hi/lo row-major.
// MODE 2: packed hi/lo head-major, fused QKV: col>>10 selects matrix (Chi/Clo + mat*ACT_PAIRS).
#define RST2 20                    // smem row stride in uint32 (16 data + 4 pad; conflict-free)
#define ARR2_B 10240               // bytes per array: 128*20*4
#define STAGE2_B 40960             // 4 arrays
#define GEMM_SMEM (2*STAGE2_B)     // 81920

template<int MODE>
__global__ __launch_bounds__(256, 2)
void gemm_cp(const uint32_t* __restrict__ Ahi, const uint32_t* __restrict__ Alo,
             const uint32_t* __restrict__ Bhi, const uint32_t* __restrict__ Blo,
             float* __restrict__ C, uint32_t* __restrict__ Chi, uint32_t* __restrict__ Clo,
             int M, int N, int K)
{
    extern __shared__ uint32_t smem[];
    const uint32_t smem_base = (uint32_t)__cvta_generic_to_shared(smem);

    const int K2 = K >> 1;
    const int bm = blockIdx.y * 128;
    const int bn = blockIdx.x * 128;
    const int tid = threadIdx.x;

    // staging: row = tid>>1 (0..127), half = tid&1 -> 32B each of 64B row-chunk
    const int row = tid >> 1, half = tid & 1;
    const uint32_t* pAhi = Ahi + (size_t)(bm + row) * K2 + half * 8;
    const uint32_t* pAlo = Alo + (size_t)(bm + row) * K2 + half * 8;
    const uint32_t* pBhi = Bhi + (size_t)(bn + row) * K2 + half * 8;
    const uint32_t* pBlo = Blo + (size_t)(bn + row) * K2 + half * 8;
    const uint32_t dst0 = smem_base + (uint32_t)((row * RST2 + half * 8) * 4);

    const int wid = tid >> 5, lane = tid & 31;
    const int warp_m = (wid & 1) * 64;
    const int warp_n = (wid >> 1) * 32;
    const int g = lane >> 2, t = lane & 3;

    // ldmatrix lane byte-offsets within an array (k-group offset added per kk)
    uint32_t aoff[4], boff[2];
    {
        int arow = lane & 15, ahalf = (lane >> 4) * 16;   // bytes
#pragma unroll
        for (int fm = 0; fm < 4; fm++)
            aoff[fm] = (uint32_t)((warp_m + fm * 16 + arow) * RST2 * 4 + ahalf);
        // B x4: lanes 0-7 (n0..7,klo), 8-15 (n0..7,khi), 16-23 (n8..15,klo), 24-31 (n8..15,khi)
        int brow = (lane & 7) + ((lane >> 4) & 1) * 8;
        int bhalf = ((lane >> 3) & 1) * 16;               // bytes
#pragma unroll
        for (int fn2 = 0; fn2 < 2; fn2++)
            boff[fn2] = (uint32_t)((warp_n + fn2 * 16 + brow) * RST2 * 4 + bhalf);
    }

    float acc[4][4][4];
#pragma unroll
    for (int i = 0; i < 4; i++)
#pragma unroll
        for (int j = 0; j < 4; j++)
#pragma unroll
            for (int r = 0; r < 4; r++) acc[i][j][r] = 0.0f;

    const int nch = K >> 5;    // K-chunk 32

    auto issue = [&](int kc, int s) {
        uint32_t d = dst0 + (uint32_t)(s * STAGE2_B);
        size_t go = (size_t)kc * 16;
        cp16(d,                  pAhi + go);
        cp16(d + 16,             pAhi + go + 4);
        cp16(d + ARR2_B,         pAlo + go);
        cp16(d + ARR2_B + 16,    pAlo + go + 4);
        cp16(d + 2*ARR2_B,       pBhi + go);
        cp16(d + 2*ARR2_B + 16,  pBhi + go + 4);
        cp16(d + 3*ARR2_B,       pBlo + go);
        cp16(d + 3*ARR2_B + 16,  pBlo + go + 4);
        asm volatile("cp.async.commit_group;");
    };

    issue(0, 0);

    for (int kc = 0; kc < nch; kc++) {
        asm volatile("cp.async.wait_group 0;");
        __syncthreads();
        if (kc + 1 < nch) issue(kc + 1, (kc + 1) & 1);

        const uint32_t sb = smem_base + (uint32_t)((kc & 1) * STAGE2_B);
        const uint32_t sbAlo = sb + ARR2_B;
        const uint32_t sbB   = sb + 2*ARR2_B;
        const uint32_t sbBlo = sb + 3*ARR2_B;

#pragma unroll
        for (int kk = 0; kk < 2; kk++) {
            const uint32_t ko = (uint32_t)(kk * 32);   // byte offset of k16 group
            uint32_t bhi[4][2], blo[4][2];
#pragma unroll
            for (int fn2 = 0; fn2 < 2; fn2++) {
                uint32_t r[4];
                ldsm_x4(r, sbB + boff[fn2] + ko);
                bhi[2*fn2][0] = r[0]; bhi[2*fn2][1] = r[1];
                bhi[2*fn2+1][0] = r[2]; bhi[2*fn2+1][1] = r[3];
                ldsm_x4(r, sbBlo + boff[fn2] + ko);
                blo[2*fn2][0] = r[0]; blo[2*fn2][1] = r[1];
                blo[2*fn2+1][0] = r[2]; blo[2*fn2+1][1] = r[3];
            }
#pragma unroll
            for (int fm = 0; fm < 4; fm++) {
                uint32_t ahi[4], alo[4];
                ldsm_x4(ahi, sb + aoff[fm] + ko);
                ldsm_x4(alo, sbAlo + aoff[fm] + ko);
#pragma unroll
                for (int fn = 0; fn < 4; fn++) {
                    mma_bf16(acc[fm][fn], ahi, blo[fn]);
                    mma_bf16(acc[fm][fn], alo, bhi[fn]);
                    mma_bf16(acc[fm][fn], ahi, bhi[fn]);
                }
            }
        }
    }

    // epilogue: c0(row g, col 2t), c1(g,2t+1), c2(g+8,2t), c3(g+8,2t+1)
#pragma unroll
    for (int fm = 0; fm < 4; fm++) {
#pragma unroll
        for (int fn = 0; fn < 4; fn++) {
            int row0 = bm + warp_m + fm * 16 + g;
            int col  = bn + warp_n + fn * 8 + 2 * t;
            float v0 = acc[fm][fn][0], v1 = acc[fm][fn][1];
            float v2 = acc[fm][fn][2], v3 = acc[fm][fn][3];
            if (MODE == 1) {
                v0 = gelu_tanh(v0); v1 = gelu_tanh(v1);
                v2 = gelu_tanh(v2); v3 = gelu_tanh(v3);
                int N2 = N >> 1;
                int cp0 = col >> 1;
                uint32_t h, l;
                split2(v0, v1, h, l);
                Chi[(size_t)row0 * N2 + cp0] = h;  Clo[(size_t)row0 * N2 + cp0] = l;
                split2(v2, v3, h, l);
                Chi[(size_t)(row0 + 8) * N2 + cp0] = h;  Clo[(size_t)(row0 + 8) * N2 + cp0] = l;
            } else if (MODE == 2) {
                // fused QKV head-major: mat = col>>10; within-matrix col -> [B,H,S,HD]
                int mat = col >> 10;
                int c   = col & 1023;
                int bb = row0 >> 10, ss = row0 & 1023;
                int hh = c >> 6, hd = c & 63;
                size_t e0 = (((size_t)(bb * HEADS_ + hh)) * SEQ_ + ss) * HD_ + hd;
                size_t pidx0 = (size_t)mat * ACT_PAIRS + (e0 >> 1);
                size_t pidx1 = (size_t)mat * ACT_PAIRS + ((e0 + 8 * HD_) >> 1);
                uint32_t h, l;
                split2(v0, v1, h, l);
                Chi[pidx0] = h;  Clo[pidx0] = l;
                split2(v2, v3, h, l);
                Chi[pidx1] = h;  Clo[pidx1] = l;
            } else {
                *(float2*)(C + (size_t)row0 * N + col)       = make_float2(v0, v1);
                *(float2*)(C + (size_t)(row0 + 8) * N + col) = make_float2(v2, v3);
            }
        }
    }
}

// ------------------------------ MMA flash attention ------------------------------
#define A_RST 36
#define A_QHI 0
#define A_QLO 2304
#define A_BUF0 4608
#define A_BUFSZ 9216
#define ATTN_SMEM_B ((A_BUF0 + 2*A_BUFSZ)*4)   // 92160 bytes

__global__ __launch_bounds__(128)
void attn_mma(const uint32_t* __restrict__ Qhi, const uint32_t* __restrict__ Qlo,
              const uint32_t* __restrict__ Khi, const uint32_t* __restrict__ Klo,
              const uint32_t* __restrict__ Vhi, const uint32_t* __restrict__ Vlo,
              uint32_t* __restrict__ Ohi, uint32_t* __restrict__ Olo,
              const float* __restrict__ gate, int causal)
{
    extern __shared__ uint32_t smem[];
    const uint32_t smem_base = (uint32_t)__cvta_generic_to_shared(smem);

    const int qb  = blockIdx.x;
    const int bh  = blockIdx.y;
    const int b   = bh >> 4, h = bh & 15;
    const int q0  = qb * 64;
    const int tid = threadIdx.x;
    const int wid = tid >> 5, lane = tid & 31;
    const int g = lane >> 2, t = lane & 3;

    const size_t plane = (size_t)bh * (SEQ_ * (HD_ / 2));

#pragma unroll
    for (int i = 0; i < 4; i++) {
        int idx = i * 128 + tid;
        int r = idx >> 3, ch = idx & 7;
        const uint4* sh = (const uint4*)(Qhi + plane + (size_t)(q0 + r) * 32 + ch * 4);
        const uint4* sl = (const uint4*)(Qlo + plane + (size_t)(q0 + r) * 32 + ch * 4);
        *(uint4*)&smem[A_QHI + r * A_RST + ch * 4] = *sh;
        *(uint4*)&smem[A_QLO + r * A_RST + ch * 4] = *sl;
    }

    auto issueKV = [&](int kb, int buf) {
        uint32_t dbase = smem_base + (uint32_t)((A_BUF0 + buf * A_BUFSZ) * 4);
        size_t src = plane + (size_t)(kb * 64) * 32;
#pragma unroll
        for (int i = 0; i < 4; i++) {
            int idx = i * 128 + tid;
            int r = idx >> 3, ch = idx & 7;
            uint32_t doff = (uint32_t)((r * A_RST + ch * 4) * 4);
            size_t soff = src + (size_t)r * 32 + ch * 4;
            cp16(dbase + doff,                Khi + soff);
            cp16(dbase + 2304 * 4 + doff,     Klo + soff);
            cp16(dbase + 4608 * 4 + doff,     Vhi + soff);
            cp16(dbase + 6912 * 4 + doff,     Vlo + soff);
        }
        asm volatile("cp.async.commit_group;");
    };

    const int nkb = causal ? (qb + 1) : (SEQ_ / 64);
    issueKV(0, 0);

    const int l15 = lane & 15;
    const uint32_t qrow_off = (uint32_t)((wid * 16 + l15) * A_RST * 4);
    const uint32_t qk_half  = (uint32_t)((lane >> 4) * 16);
    const uint32_t krow_base = (uint32_t)((lane & 7) * A_RST * 4);
    const uint32_t kk_half   = (uint32_t)(((lane >> 3) & 1) * 16);

    float sacc[8][4], oacc[8][4];
    float m0 = -3.0e38f, m1 = -3.0e38f, l0 = 0.0f, l1 = 0.0f;
#pragma unroll
    for (int fn = 0; fn < 8; fn++)
#pragma unroll
        for (int j = 0; j < 4; j++) oacc[fn][j] = 0.0f;

    for (int kb = 0; kb < nkb; kb++) {
        asm volatile("cp.async.wait_group 0;");
        __syncthreads();
        if (kb + 1 < nkb) issueKV(kb + 1, (kb + 1) & 1);

        const uint32_t sb = smem_base + (uint32_t)((A_BUF0 + (kb & 1) * A_BUFSZ) * 4);
        const uint32_t sbK = sb, sbKlo = sb + 2304 * 4;
        const uint32_t sbV = sb + 4608 * 4, sbVlo = sb + 6912 * 4;

#pragma unroll
        for (int fn = 0; fn < 8; fn++)
#pragma unroll
            for (int j = 0; j < 4; j++) sacc[fn][j] = 0.0f;

#pragma unroll
        for (int kk = 0; kk < 4; kk++) {
            uint32_t qhi[4], qlo[4];
            uint32_t qa = (uint32_t)(qrow_off + kk * 32 + qk_half);
            ldsm_x4(qhi, smem_base + A_QHI * 4 + qa);
            ldsm_x4(qlo, smem_base + A_QLO * 4 + qa);
#pragma unroll
            for (int fn = 0; fn < 8; fn++) {
                uint32_t khi[2], klo[2];
                uint32_t ka = (uint32_t)(fn * 8 * A_RST * 4 + krow_base + kk * 32 + kk_half);
                ldsm_x2(khi, sbK + ka);
                ldsm_x2(klo, sbKlo + ka);
                mma_bf16(sacc[fn], qhi, klo);
                mma_bf16(sacc[fn], qlo, khi);
                mma_bf16(sacc[fn], qhi, khi);
            }
        }

        const int rq0 = q0 + wid * 16 + g;
        const int rq1 = rq0 + 8;
        const bool maskblk = causal && (kb == qb);
        float mx0 = -3.0e38f, mx1 = -3.0e38f;
#pragma unroll
        for (int fn = 0; fn < 8; fn++) {
            int c0 = kb * 64 + fn * 8 + 2 * t;
#pragma unroll
            for (int j = 0; j < 4; j++) {
                float v = sacc[fn][j] * 0.125f;
                int cc = c0 + (j & 1);
                int rr = (j < 2) ? rq0 : rq1;
                if (maskblk && cc > rr) v = -3.0e38f;
                sacc[fn][j] = v;
            }
            mx0 = fmaxf(mx0, fmaxf(sacc[fn][0], sacc[fn][1]));
            mx1 = fmaxf(mx1, fmaxf(sacc[fn][2], sacc[fn][3]));
        }
        mx0 = fmaxf(mx0, __shfl_xor_sync(0xffffffffu, mx0, 1));
        mx0 = fmaxf(mx0, __shfl_xor_sync(0xffffffffu, mx0, 2));
        mx1 = fmaxf(mx1, __shfl_xor_sync(0xffffffffu, mx1, 1));
        mx1 = fmaxf(mx1, __shfl_xor_sync(0xffffffffu, mx1, 2));

        float mn0 = fmaxf(m0, mx0), mn1 = fmaxf(m1, mx1);
        float al0 = __expf(m0 - mn0), al1 = __expf(m1 - mn1);
        m0 = mn0; m1 = mn1;

        uint32_t ph[8][2], pl[8][2];
        float ls0 = 0.0f, ls1 = 0.0f;
#pragma unroll
        for (int fn = 0; fn < 8; fn++) {
            float p0 = __expf(sacc[fn][0] - m0);
            float p1 = __expf(sacc[fn][1] - m0);
            float p2 = __expf(sacc[fn][2] - m1);
            float p3 = __expf(sacc[fn][3] - m1);
            ls0 += p0 + p1; ls1 += p2 + p3;
            split2(p0, p1, ph[fn][0], pl[fn][0]);
            split2(p2, p3, ph[fn][1], pl[fn][1]);
        }
        ls0 += __shfl_xor_sync(0xffffffffu, ls0, 1);
        ls0 += __shfl_xor_sync(0xffffffffu, ls0, 2);
        ls1 += __shfl_xor_sync(0xffffffffu, ls1, 1);
        ls1 += __shfl_xor_sync(0xffffffffu, ls1, 2);
        l0 = l0 * al0 + ls0;
        l1 = l1 * al1 + ls1;

#pragma unroll
        for (int fn = 0; fn < 8; fn++) {
            oacc[fn][0] *= al0; oacc[fn][1] *= al0;
            oacc[fn][2] *= al1; oacc[fn][3] *= al1;
        }

#pragma unroll
        for (int kk = 0; kk < 4; kk++) {
            uint32_t ahi[4] = {ph[2*kk][0], ph[2*kk][1], ph[2*kk+1][0], ph[2*kk+1][1]};
            uint32_t alo[4] = {pl[2*kk][0], pl[2*kk][1], pl[2*kk+1][0], pl[2*kk+1][1]};
            uint32_t vrow = (uint32_t)((kk * 16 + l15) * A_RST * 4);
#pragma unroll
            for (int fo = 0; fo < 8; fo++) {
                uint32_t vhi[2], vlo[2];
                uint32_t va = vrow + (uint32_t)(fo * 16);
                ldsm_x2_trans(vhi, sbV + va);
                ldsm_x2_trans(vlo, sbVlo + va);
                mma_bf16(oacc[fo], ahi, vlo);
                mma_bf16(oacc[fo], alo, vhi);
                mma_bf16(oacc[fo], ahi, vhi);
            }
        }
    }

    float gmul = 1.0f;
    if (gate != nullptr) gmul = 1.0f - 1.0f / (1.0f + __expf(-gate[h]));
    float inv0 = gmul / l0, inv1 = gmul / l1;

    const int rq0 = q0 + wid * 16 + g;
#pragma unroll
    for (int fo = 0; fo < 8; fo++) {
        int col = h * HD_ + fo * 8 + 2 * t;
        size_t p0 = ((size_t)(b * SEQ_ + rq0) * DIM_ + col) >> 1;
        size_t p1 = ((size_t)(b * SEQ_ + rq0 + 8) * DIM_ + col) >> 1;
        uint32_t hh, ll;
        split2(oacc[fo][0] * inv0, oacc[fo][1] * inv0, hh, ll);
        Ohi[p0] = hh; Olo[p0] = ll;
        split2(oacc[fo][2] * inv1, oacc[fo][3] * inv1, hh, ll);
        Ohi[p1] = hh; Olo[p1] = ll;
    }
}

// ------------------------------ elementwise ------------------------------
__global__ void pack_split_kernel(const float* __restrict__ in,
                                  uint32_t* __restrict__ hi, uint32_t* __restrict__ lo,
                                  int n4)
{
    int i = blockIdx.x * blockDim.x + threadIdx.x;
    if (i >= n4) return;
    float4 v = ((const float4*)in)[i];
    uint32_t h0, l0, h1, l1;
    split2(v.x, v.y, h0, l0);
    split2(v.z, v.w, h1, l1);
    hi[2 * i] = h0; hi[2 * i + 1] = h1;
    lo[2 * i] = l0; lo[2 * i + 1] = l1;
}

__global__ void embed_pack_kernel(const int* __restrict__ x, const float* __restrict__ emb,
                                  uint32_t* __restrict__ hi, uint32_t* __restrict__ lo)
{
    int i = blockIdx.x * blockDim.x + threadIdx.x;
    if (i >= (int)(ACT_ELEMS / 4)) return;
    int row = i >> 8, c4 = i & 255;
    int tok = x[row];
    float4 v = ((const float4*)(emb + (size_t)tok * DIM_))[c4];
    uint32_t h0, l0, h1, l1;
    split2(v.x, v.y, h0, l0);
    split2(v.z, v.w, h1, l1);
    hi[2 * i] = h0; hi[2 * i + 1] = h1;
    lo[2 * i] = l0; lo[2 * i + 1] = l1;
}

__global__ void bcast_init_kernel(const float* __restrict__ i0, const float* __restrict__ i1,
                                  float* __restrict__ S0, float* __restrict__ S1)
{
    int i = blockIdx.x * blockDim.x + threadIdx.x;
    if (i >= (int)(ACT_ELEMS / 4)) return;
    int src = i & (int)(SEQ_ * DIM_ / 4 - 1);
    ((float4*)S0)[i] = ((const float4*)i0)[src];
    ((float4*)S1)[i] = ((const float4*)i1)[src];
}

__global__ void add3_pack_kernel(const float* __restrict__ a, const float* __restrict__ b,
                                 const float* __restrict__ c, float* __restrict__ o,
                                 uint32_t* __restrict__ hi, uint32_t* __restrict__ lo)
{
    int i = blockIdx.x * blockDim.x + threadIdx.x;
    if (i >= (int)(ACT_ELEMS / 4)) return;
    float4 va = ((const float4*)a)[i];
    float4 vb = ((const float4*)b)[i];
    float4 vc = ((const float4*)c)[i];
    float4 s = make_float4(va.x + vb.x + vc.x, va.y + vb.y + vc.y,
                           va.z + vb.z + vc.z, va.w + vb.w + vc.w);
    ((float4*)o)[i] = s;
    uint32_t h0, l0, h1, l1;
    split2(s.x, s.y, h0, l0);
    split2(s.z, s.w, h1, l1);
    hi[2 * i] = h0; hi[2 * i + 1] = h1;
    lo[2 * i] = l0; lo[2 * i + 1] = l1;
}

template<int PACK>
__global__ __launch_bounds__(256)
void rmsnorm_add_kernel(const float* __restrict__ a, const float* __restrict__ b,
                        float* __restrict__ o,
                        uint32_t* __restrict__ hi, uint32_t* __restrict__ lo)
{
    int row = blockIdx.x;
    int tid = threadIdx.x;
    const float4* a4 = (const float4*)(a + (size_t)row * DIM_);
    const float4* b4 = (const float4*)(b + (size_t)row * DIM_);
    float4 va = a4[tid], vb = b4[tid];
    float4 s = make_float4(va.x + vb.x, va.y + vb.y, va.z + vb.z, va.w + vb.w);
    float ss = s.x * s.x + s.y * s.y + s.z * s.z + s.w * s.w;
#pragma unroll
    for (int off = 16; off > 0; off >>= 1) ss += __shfl_xor_sync(0xffffffffu, ss, off);
    __shared__ float red[8];
    __shared__ float scale_s;
    if ((tid & 31) == 0) red[tid >> 5] = ss;
    __syncthreads();
    if (tid == 0) {
        float tacc = 0.0f;
#pragma unroll
        for (int w = 0; w < 8; w++) tacc += red[w];
        scale_s = rsqrtf(tacc * (1.0f / DIM_) + 1e-6f);
    }
    __syncthreads();
    float sc = scale_s;
    float4 r = make_float4(s.x * sc, s.y * sc, s.z * sc, s.w * sc);
    ((float4*)(o + (size_t)row * DIM_))[tid] = r;
    if (PACK) {
        uint32_t h0, l0, h1, l1;
        split2(r.x, r.y, h0, l0);
        split2(r.z, r.w, h1, l1);
        size_t pidx = (size_t)row * (DIM_ / 2) + tid * 2;
        hi[pidx] = h0; hi[pidx + 1] = h1;
        lo[pidx] = l0; lo[pidx + 1] = l1;
    }
}

__global__ void mean_kernel(const float* __restrict__ S, float* __restrict__ M)
{
    int idx = blockIdx.x * blockDim.x + threadIdx.x;
    if (idx >= B_ * DIM_) return;
    int b = idx >> 10, d = idx & (DIM_ - 1);
    const float* p = S + (size_t)b * SEQ_ * DIM_ + d;
    float s = 0.0f;
    for (int t = 0; t < SEQ_; t++) s += p[(size_t)t * DIM_];
    M[idx] = s * (1.0f / SEQ_);
}

__global__ void qhead_kernel(const float* __restrict__ M, const float* __restrict__ W,
                             float* __restrict__ out)
{
    int w = threadIdx.x >> 5, lane = threadIdx.x & 31;
    int b = w >> 1, o = w & 1;
    const float* m  = M + (size_t)b * DIM_;
    const float* ww = W + (size_t)o * DIM_;
    float s = 0.0f;
    for (int k = lane; k < DIM_; k += 32) s += m[k] * ww[k];
#pragma unroll
    for (int off = 16; off > 0; off >>= 1) s += __shfl_xor_sync(0xffffffffu, s, off);
    if (lane == 0) out[b * 2 + o] = 1.0f / (1.0f + __expf(-s));
}

// ------------------------------ host orchestration ------------------------------
static void launch_gemm(const uint32_t* Ahi, const uint32_t* Alo,
                        const uint32_t* Bhi, const uint32_t* Blo,
                        float* C, uint32_t* Chi, uint32_t* Clo,
                        int M, int N, int K, int mode)
{
    dim3 grid(N / 128, M / 128);
    if (mode == 1)      gemm_cp<1><<<grid, 256, GEMM_SMEM>>>(Ahi, Alo, Bhi, Blo, C, Chi, Clo, M, N, K);
    else if (mode == 2) gemm_cp<2><<<grid, 256, GEMM_SMEM>>>(Ahi, Alo, Bhi, Blo, C, Chi, Clo, M, N, K);
    else                gemm_cp<0><<<grid, 256, GEMM_SMEM>>>(Ahi, Alo, Bhi, Blo, C, Chi, Clo, M, N, K);
}

struct WOffs { size_t wq, wo, w1, w2; };   // wq = start of contiguous q,k,v slots

extern "C" void kernel_launch(void* const* d_in, const int* in_sizes, int n_in,
                              void* d_out, int out_size)
{
    (void)in_sizes; (void)n_in; (void)out_size;
    const int*   x     = (const int*)  d_in[0];
    const float* emb   = (const float*)d_in[1];
    const float* gate  = (const float*)d_in[6];
    const float* init0 = (const float*)d_in[7];
    const float* init1 = (const float*)d_in[8];
    const float* w_out   = (const float*)d_in[21];
    const float* w_qhead = (const float*)d_in[22];
    float* out = (float*)d_out;

    float *XENR, *S0, *S1, *H0, *H1, *T, *G, *MEAN;
    cudaGetSymbolAddress((void**)&XENR, g_XENR);
    cudaGetSymbolAddress((void**)&S0,   g_S0);
    cudaGetSymbolAddress((void**)&S1,   g_S1);
    cudaGetSymbolAddress((void**)&H0,   g_H0);
    cudaGetSymbolAddress((void**)&H1,   g_H1);
    cudaGetSymbolAddress((void**)&T,    g_T);
    cudaGetSymbolAddress((void**)&G,    g_G);
    cudaGetSymbolAddress((void**)&MEAN, g_MEAN);

    uint32_t *cXhi, *cXlo, *cH0hi, *cH0lo, *cH1hi, *cH1lo, *cAThi, *cATlo;
    uint32_t *cGhi, *cGlo, *cFFhi, *cFFlo, *cS1hi, *cS1lo, *WHI, *WLO;
    uint32_t *cQKVhi, *cQKVlo;
    cudaGetSymbolAddress((void**)&cXhi,  g_cXhi);  cudaGetSymbolAddress((void**)&cXlo,  g_cXlo);
    cudaGetSymbolAddress((void**)&cH0hi, g_cH0hi); cudaGetSymbolAddress((void**)&cH0lo, g_cH0lo);
    cudaGetSymbolAddress((void**)&cH1hi, g_cH1hi); cudaGetSymbolAddress((void**)&cH1lo, g_cH1lo);
    cudaGetSymbolAddress((void**)&cAThi, g_cAThi); cudaGetSymbolAddress((void**)&cATlo, g_cATlo);
    cudaGetSymbolAddress((void**)&cGhi,  g_cGhi);  cudaGetSymbolAddress((void**)&cGlo,  g_cGlo);
    cudaGetSymbolAddress((void**)&cFFhi, g_cFFhi); cudaGetSymbolAddress((void**)&cFFlo, g_cFFlo);
    cudaGetSymbolAddress((void**)&cS1hi, g_cS1hi); cudaGetSymbolAddress((void**)&cS1lo, g_cS1lo);
    cudaGetSymbolAddress((void**)&cQKVhi, g_cQKVhi); cudaGetSymbolAddress((void**)&cQKVlo, g_cQKVlo);
    cudaGetSymbolAddress((void**)&WHI,   g_WHI);   cudaGetSymbolAddress((void**)&WLO,   g_WLO);

    cudaFuncSetAttribute(attn_mma, cudaFuncAttributeMaxDynamicSharedMemorySize, ATTN_SMEM_B);
    cudaFuncSetAttribute(gemm_cp<0>, cudaFuncAttributeMaxDynamicSharedMemorySize, GEMM_SMEM);
    cudaFuncSetAttribute(gemm_cp<1>, cudaFuncAttributeMaxDynamicSharedMemorySize, GEMM_SMEM);
    cudaFuncSetAttribute(gemm_cp<2>, cudaFuncAttributeMaxDynamicSharedMemorySize, GEMM_SMEM);

    // ---- weight pre-split (once per launch) ----
    const int widx[14]  = {2, 3, 4, 5,   9, 10, 11, 12, 13, 14,   15, 16, 17, 18};
    const size_t woff[14] = {0, 1*WSZ, 2*WSZ, 3*WSZ,
                             4*WSZ, 5*WSZ, 6*WSZ, 7*WSZ, 8*WSZ, 12*WSZ,
                             16*WSZ, 17*WSZ, 18*WSZ, 19*WSZ};
    const size_t wel[14]  = {1u<<20, 1u<<20, 1u<<20, 1u<<20,
                             1u<<20, 1u<<20, 1u<<20, 1u<<20, 1u<<22, 1u<<22,
                             1u<<20, 1u<<20, 1u<<20, 1u<<20};
    for (int i = 0; i < 14; i++) {
        size_t off = woff[i];
        size_t elems = wel[i];
        if (i >= 10) {
            off = (size_t)(16 + (i - 10)) * WSZ;
            elems = 1u << 20;
        }
        int n4 = (int)(elems / 4);
        pack_split_kernel<<<(n4 + 255) / 256, 256>>>((const float*)d_in[widx[i]],
                                                     WHI + off, WLO + off, n4);
    }
    {
        int n4 = (1 << 22) / 4;
        pack_split_kernel<<<(n4 + 255) / 256, 256>>>((const float*)d_in[19], WHI + 20*WSZ, WLO + 20*WSZ, n4);
        pack_split_kernel<<<(n4 + 255) / 256, 256>>>((const float*)d_in[20], WHI + 24*WSZ, WLO + 24*WSZ, n4);
        int n4v = VOCAB_ * DIM_ / 4;
        pack_split_kernel<<<(n4v + 255) / 256, 256>>>(w_out, WHI + 28*WSZ, WLO + 28*WSZ, n4v);
    }

    WOffs lw[2];
    lw[0] = { 4*WSZ, 7*WSZ, 8*WSZ, 12*WSZ };
    lw[1] = { 16*WSZ, 19*WSZ, 20*WSZ, 24*WSZ };

    const int v4blocks = (int)(ACT_ELEMS / 4 + 255) / 256;
    const dim3 agrid(SEQ_ / 64, B_ * HEADS_);

    // ---- embedding ----
    embed_pack_kernel<<<v4blocks, 256>>>(x, emb, cXhi, cXlo);

    // ---- infini attention (memory==0 => combined = (1-sigmoid(gate))*local) ----
    launch_gemm(cXhi, cXlo, WHI + 0*WSZ, WLO + 0*WSZ, 0, cQKVhi, cQKVlo, ROWS_, 3*DIM_, DIM_, 2);
    attn_mma<<<agrid, 128, ATTN_SMEM_B>>>(cQKVhi, cQKVlo,
                                          cQKVhi + ACT_PAIRS, cQKVlo + ACT_PAIRS,
                                          cQKVhi + 2*ACT_PAIRS, cQKVlo + 2*ACT_PAIRS,
                                          cAThi, cATlo, gate, 1);
    launch_gemm(cAThi, cATlo, WHI + 3*WSZ, WLO + 3*WSZ, XENR, 0, 0, ROWS_, DIM_, DIM_, 0);

    bcast_init_kernel<<<v4blocks, 256>>>(init0, init1, S0, S1);

    // ---- HRM steps ----
    for (int step = 0; step < 8; step++) {
        bool u1 = ((step + 1) % 4 == 0);
        add3_pack_kernel<<<v4blocks, 256>>>(S0, XENR, S1, H0, cH0hi, cH0lo);
        if (u1) add3_pack_kernel<<<v4blocks, 256>>>(S1, XENR, S0, H1, cH1hi, cH1lo);
        for (int li = 0; li < (u1 ? 2 : 1); li++) {
            const WOffs& o = lw[li];
            uint32_t* hHi = li ? cH1hi : cH0hi;
            uint32_t* hLo = li ? cH1lo : cH0lo;
            float* Hres = li ? H1 : H0;
            float* OUT  = li ? S1 : S0;
            launch_gemm(hHi, hLo, WHI + o.wq, WLO + o.wq, 0, cQKVhi, cQKVlo, ROWS_, 3*DIM_, DIM_, 2);
            attn_mma<<<agrid, 128, ATTN_SMEM_B>>>(cQKVhi, cQKVlo,
                                                  cQKVhi + ACT_PAIRS, cQKVlo + ACT_PAIRS,
                                                  cQKVhi + 2*ACT_PAIRS, cQKVlo + 2*ACT_PAIRS,
                                                  cAThi, cATlo, nullptr, 0);
            launch_gemm(cAThi, cATlo, WHI + o.wo, WLO + o.wo, T, 0, 0, ROWS_, DIM_, DIM_, 0);
            rmsnorm_add_kernel<1><<<ROWS_, 256>>>(Hres, T, G, cGhi, cGlo);
            launch_gemm(cGhi, cGlo, WHI + o.w1, WLO + o.w1, 0, cFFhi, cFFlo, ROWS_, FF_, DIM_, 1);
            launch_gemm(cFFhi, cFFlo, WHI + o.w2, WLO + o.w2, T, 0, 0, ROWS_, DIM_, FF_, 0);
            rmsnorm_add_kernel<0><<<ROWS_, 256>>>(G, T, OUT, 0, 0);
        }
    }

    // ---- outputs ----
    pack_split_kernel<<<v4blocks, 256>>>(S1, cS1hi, cS1lo, (int)(ACT_ELEMS / 4));
    launch_gemm(cS1hi, cS1lo, WHI + 28*WSZ, WLO + 28*WSZ, out, 0, 0, ROWS_, VOCAB_, DIM_, 0);
    mean_kernel<<<(B_ * DIM_ + 255) / 256, 256>>>(S1, MEAN);
    qhead_kernel<<<1, 256>>>(MEAN, w_qhead, out + (size_t)ROWS_ * VOCAB_);
}